// round 1
// baseline (speedup 1.0000x reference)
#include <cuda_runtime.h>
#include <cuda_bf16.h>
#include <math.h>

// Problem constants
#define Bn   2
#define Tn   2048
#define Cn   2048
#define NH   16
#define NKV  4
#define HD   128
#define REP  (NH / NKV)          // 4
#define Mrows (Bn * Tn)          // 4096
#define KVC  (NKV * HD)          // 512

// ---------------------------------------------------------------------------
// Scratch (device globals; no runtime allocation allowed)
// ---------------------------------------------------------------------------
__device__ float g_Q[(size_t)Mrows * Cn];   // 32 MB
__device__ float g_K[(size_t)Mrows * KVC];  //  8 MB
__device__ float g_V[(size_t)Mrows * KVC];  //  8 MB
__device__ float g_Y[(size_t)Mrows * Cn];   // 32 MB

// ---------------------------------------------------------------------------
// fp32 SGEMM: C[M,N] = A[M,K] @ B[K,N], all row-major, dims divisible by tiles
// 128x128 tile, BK=16, 256 threads, 8x8 per thread
// ---------------------------------------------------------------------------
#define GBM 128
#define GBN 128
#define GBK 16

__global__ __launch_bounds__(256)
void sgemm_nn(const float* __restrict__ A, const float* __restrict__ B,
              float* __restrict__ C, int M, int N, int K)
{
    __shared__ float As[GBK][GBM];   // stored transposed (k-major)
    __shared__ float Bs[GBK][GBN];

    const int tid = threadIdx.x;
    const int tr  = tid / 16;        // 0..15
    const int tc  = tid % 16;        // 0..15
    const int row0 = blockIdx.y * GBM;
    const int col0 = blockIdx.x * GBN;

    float acc[8][8];
#pragma unroll
    for (int i = 0; i < 8; i++)
#pragma unroll
        for (int j = 0; j < 8; j++) acc[i][j] = 0.f;

    const int a_row = tid / 4;           // 0..63
    const int a_col = (tid % 4) * 4;     // 0,4,8,12
    const int b_row = tid / 32;          // 0..7
    const int b_col = (tid % 32) * 4;    // 0..124

    for (int k0 = 0; k0 < K; k0 += GBK) {
#pragma unroll
        for (int p = 0; p < 2; p++) {
            int r = a_row + p * 64;
            float4 v = *(const float4*)(A + (size_t)(row0 + r) * K + k0 + a_col);
            As[a_col + 0][r] = v.x;
            As[a_col + 1][r] = v.y;
            As[a_col + 2][r] = v.z;
            As[a_col + 3][r] = v.w;
        }
#pragma unroll
        for (int p = 0; p < 2; p++) {
            int r = b_row + p * 8;
            *(float4*)(&Bs[r][b_col]) =
                *(const float4*)(B + (size_t)(k0 + r) * N + col0 + b_col);
        }
        __syncthreads();

#pragma unroll
        for (int kk = 0; kk < GBK; kk++) {
            float ra[8], rb[8];
            *(float4*)&ra[0] = *(float4*)&As[kk][tr * 8];
            *(float4*)&ra[4] = *(float4*)&As[kk][tr * 8 + 4];
            *(float4*)&rb[0] = *(float4*)&Bs[kk][tc * 8];
            *(float4*)&rb[4] = *(float4*)&Bs[kk][tc * 8 + 4];
#pragma unroll
            for (int i = 0; i < 8; i++)
#pragma unroll
                for (int j = 0; j < 8; j++)
                    acc[i][j] += ra[i] * rb[j];
        }
        __syncthreads();
    }

#pragma unroll
    for (int i = 0; i < 8; i++) {
        float* dst = C + (size_t)(row0 + tr * 8 + i) * N + col0 + tc * 8;
        *(float4*)(dst)     = make_float4(acc[i][0], acc[i][1], acc[i][2], acc[i][3]);
        *(float4*)(dst + 4) = make_float4(acc[i][4], acc[i][5], acc[i][6], acc[i][7]);
    }
}

// ---------------------------------------------------------------------------
// RoPE (in place) on X: [Mrows, nheads*HD]; pair i -> cols (2i, 2i+1) per head
// ---------------------------------------------------------------------------
__global__ void rope_kernel(float* __restrict__ X,
                            const float* __restrict__ fcos,
                            const float* __restrict__ fsin,
                            int nheads, int total)
{
    int idx = blockIdx.x * blockDim.x + threadIdx.x;
    if (idx >= total) return;
    int i = idx & 63;                       // HD/2 = 64
    int h = (idx >> 6) % nheads;
    int m = idx / (64 * nheads);
    int t = m % Tn;
    float c = fcos[t * 64 + i];
    float s = fsin[t * 64 + i];
    float* p = X + (size_t)m * (nheads * HD) + h * HD + 2 * i;
    float2 v = *(float2*)p;
    float re = v.x, im = v.y;
    *(float2*)p = make_float2(re * c - im * s, re * s + im * c);
}

// ---------------------------------------------------------------------------
// Flash attention (fp32, causal, GQA): Q[Mrows,Cn], K/V[Mrows,KVC] -> Y[Mrows,Cn]
// CTA: one (b, h, 64-query block); 256 threads; key blocks of 32.
// ---------------------------------------------------------------------------
#define FBM 64
#define FBN 32
#define KPAD 132                 // padded K row (floats)
#define SPAD 33                  // padded S row

// dynamic smem layout (floats):
//   Qs [64][128]      8192
//   Ks [32][132]      4224
//   Vs [32][128]      4096
//   Ss [64][33]       2112
//   m,l,sc [3*64]      192
#define FLASH_SMEM_FLOATS (8192 + 4224 + 4096 + 2112 + 192)

__global__ __launch_bounds__(256)
void flash_attn(const float* __restrict__ Qg, const float* __restrict__ Kg,
                const float* __restrict__ Vg, float* __restrict__ Yg)
{
    extern __shared__ float sm[];
    float* Qs  = sm;
    float* Ks  = Qs + 64 * 128;
    float* Vs  = Ks + 32 * KPAD;
    float* Ss  = Vs + 32 * 128;
    float* m_s = Ss + 64 * SPAD;
    float* l_s = m_s + 64;
    float* sc_s = l_s + 64;

    const int tid = threadIdx.x;
    const int bq = blockIdx.x, h = blockIdx.y, b = blockIdx.z;
    const int q0 = bq * FBM;
    const int kvh = h / REP;

    const float* Qbase = Qg + ((size_t)b * Tn + q0) * Cn + h * HD;
    const float* Kbase = Kg + (size_t)b * Tn * KVC + kvh * HD;
    const float* Vbase = Vg + (size_t)b * Tn * KVC + kvh * HD;

    // load Q tile: 64x128 floats = 2048 float4, 8 per thread
#pragma unroll
    for (int p = 0; p < 8; p++) {
        int idx = tid + p * 256;
        int r = idx >> 5;
        int d4 = (idx & 31) * 4;
        *(float4*)&Qs[r * 128 + d4] = *(const float4*)(Qbase + (size_t)r * Cn + d4);
    }
    if (tid < 64) { m_s[tid] = -1e30f; l_s[tid] = 0.f; }

    const int tr = tid / 16;     // 0..15 -> rows 4*tr..4*tr+3
    const int tc = tid % 16;     // 0..15 -> s-cols 2*tc, O-cols 8*tc..

    float acc[4][8];
#pragma unroll
    for (int i = 0; i < 4; i++)
#pragma unroll
        for (int j = 0; j < 8; j++) acc[i][j] = 0.f;

    const float sscale = 0.08838834764831845f;   // 1/sqrt(128)
    const int nkb = 2 * bq + 2;

    for (int jb = 0; jb < nkb; jb++) {
        const int k0 = jb * FBN;
        __syncthreads();   // protect Ks/Vs/Ss reuse
        // load K (padded) and V: 32x128 each = 1024 float4 -> 4 per thread each
#pragma unroll
        for (int p = 0; p < 4; p++) {
            int idx = tid + p * 256;
            int r = idx >> 5;
            int d4 = (idx & 31) * 4;
            *(float4*)&Ks[r * KPAD + d4] =
                *(const float4*)(Kbase + (size_t)(k0 + r) * KVC + d4);
            *(float4*)&Vs[r * 128 + d4] =
                *(const float4*)(Vbase + (size_t)(k0 + r) * KVC + d4);
        }
        __syncthreads();

        // S = Q @ K^T
        float s[4][2];
#pragma unroll
        for (int i = 0; i < 4; i++) { s[i][0] = 0.f; s[i][1] = 0.f; }
        for (int d = 0; d < 128; d += 4) {
            float4 k0v = *(float4*)&Ks[(2 * tc + 0) * KPAD + d];
            float4 k1v = *(float4*)&Ks[(2 * tc + 1) * KPAD + d];
#pragma unroll
            for (int i = 0; i < 4; i++) {
                float4 qv = *(float4*)&Qs[(4 * tr + i) * 128 + d];
                s[i][0] += qv.x * k0v.x + qv.y * k0v.y + qv.z * k0v.z + qv.w * k0v.w;
                s[i][1] += qv.x * k1v.x + qv.y * k1v.y + qv.z * k1v.z + qv.w * k1v.w;
            }
        }
        // write masked+scaled scores
#pragma unroll
        for (int i = 0; i < 4; i++) {
#pragma unroll
            for (int jj = 0; jj < 2; jj++) {
                int r = 4 * tr + i;
                int c = 2 * tc + jj;
                bool valid = (k0 + c) <= (q0 + r);
                Ss[r * SPAD + c] = valid ? s[i][jj] * sscale : -1e30f;
            }
        }
        __syncthreads();

        // online softmax per row (one thread per row)
        if (tid < 64) {
            int r = tid;
            float mo = m_s[r];
            float mn = mo;
#pragma unroll
            for (int c = 0; c < FBN; c++) mn = fmaxf(mn, Ss[r * SPAD + c]);
            float sc = __expf(mo - mn);
            float l = l_s[r] * sc;
#pragma unroll
            for (int c = 0; c < FBN; c++) {
                float e = __expf(Ss[r * SPAD + c] - mn);
                Ss[r * SPAD + c] = e;
                l += e;
            }
            m_s[r] = mn; l_s[r] = l; sc_s[r] = sc;
        }
        __syncthreads();

        // rescale accumulator, then O += P @ V
#pragma unroll
        for (int i = 0; i < 4; i++) {
            float sc = sc_s[4 * tr + i];
#pragma unroll
            for (int j = 0; j < 8; j++) acc[i][j] *= sc;
        }
#pragma unroll 4
        for (int k = 0; k < FBN; k++) {
            float4 v0 = *(float4*)&Vs[k * 128 + 8 * tc];
            float4 v1 = *(float4*)&Vs[k * 128 + 8 * tc + 4];
#pragma unroll
            for (int i = 0; i < 4; i++) {
                float p = Ss[(4 * tr + i) * SPAD + k];
                acc[i][0] += p * v0.x; acc[i][1] += p * v0.y;
                acc[i][2] += p * v0.z; acc[i][3] += p * v0.w;
                acc[i][4] += p * v1.x; acc[i][5] += p * v1.y;
                acc[i][6] += p * v1.z; acc[i][7] += p * v1.w;
            }
        }
    }

    // write O / l
#pragma unroll
    for (int i = 0; i < 4; i++) {
        int r = 4 * tr + i;
        float inv = 1.f / l_s[r];
        float* dst = Yg + ((size_t)b * Tn + q0 + r) * Cn + h * HD + 8 * tc;
        *(float4*)(dst)     = make_float4(acc[i][0] * inv, acc[i][1] * inv,
                                          acc[i][2] * inv, acc[i][3] * inv);
        *(float4*)(dst + 4) = make_float4(acc[i][4] * inv, acc[i][5] * inv,
                                          acc[i][6] * inv, acc[i][7] * inv);
    }
}

// ---------------------------------------------------------------------------
// launch
// ---------------------------------------------------------------------------
extern "C" void kernel_launch(void* const* d_in, const int* in_sizes, int n_in,
                              void* d_out, int out_size)
{
    const float* x   = (const float*)d_in[0];
    const float* Wq  = (const float*)d_in[1];
    const float* Wk  = (const float*)d_in[2];
    const float* Wv  = (const float*)d_in[3];
    const float* Wo  = (const float*)d_in[4];
    const float* fc  = (const float*)d_in[5];
    const float* fs  = (const float*)d_in[6];
    float* out = (float*)d_out;

    float *Q, *K, *V, *Y;
    cudaGetSymbolAddress((void**)&Q, g_Q);
    cudaGetSymbolAddress((void**)&K, g_K);
    cudaGetSymbolAddress((void**)&V, g_V);
    cudaGetSymbolAddress((void**)&Y, g_Y);

    // projections
    {
        dim3 gq(Cn / GBN, Mrows / GBM);   // 16 x 32
        sgemm_nn<<<gq, 256>>>(x, Wq, Q, Mrows, Cn, Cn);
        dim3 gk(KVC / GBN, Mrows / GBM);  // 4 x 32
        sgemm_nn<<<gk, 256>>>(x, Wk, K, Mrows, KVC, Cn);
        sgemm_nn<<<gk, 256>>>(x, Wv, V, Mrows, KVC, Cn);
    }

    // RoPE
    {
        int totq = Mrows * NH * (HD / 2);
        rope_kernel<<<(totq + 255) / 256, 256>>>(Q, fc, fs, NH, totq);
        int totk = Mrows * NKV * (HD / 2);
        rope_kernel<<<(totk + 255) / 256, 256>>>(K, fc, fs, NKV, totk);
    }

    // attention
    {
        int smem = FLASH_SMEM_FLOATS * sizeof(float);
        cudaFuncSetAttribute(flash_attn,
                             cudaFuncAttributeMaxDynamicSharedMemorySize, smem);
        dim3 g(Tn / FBM, NH, Bn);  // 32 x 16 x 2
        flash_attn<<<g, 256, smem>>>(Q, K, V, Y);
    }

    // output projection
    {
        dim3 go(Cn / GBN, Mrows / GBM);
        sgemm_nn<<<go, 256>>>(Y, Wo, out, Mrows, Cn, Cn);
    }
}

// round 3
// speedup vs baseline: 1.4485x; 1.4485x over previous
#include <cuda_runtime.h>
#include <cuda_bf16.h>
#include <cstdint>
#include <math.h>

// Problem constants
#define Bn   2
#define Tn   2048
#define Cn   2048
#define NH   16
#define NKV  4
#define HD   128
#define REP  (NH / NKV)          // 4
#define Mrows (Bn * Tn)          // 4096
#define KVC  (NKV * HD)          // 512

// ===========================================================================
// Scratch (device globals; no runtime allocation allowed)
// ===========================================================================
__device__ float g_Q[(size_t)Mrows * Cn];   // 32 MB
__device__ float g_K[(size_t)Mrows * KVC];  //  8 MB
__device__ float g_V[(size_t)Mrows * KVC];  //  8 MB
__device__ float g_Y[(size_t)Mrows * Cn];   // 32 MB

__device__ __nv_bfloat16 g_Xhi[(size_t)Mrows * Cn];
__device__ __nv_bfloat16 g_Xlo[(size_t)Mrows * Cn];
__device__ __nv_bfloat16 g_Yhi[(size_t)Mrows * Cn];
__device__ __nv_bfloat16 g_Ylo[(size_t)Mrows * Cn];

// transposed weights [N][K] (K-major) split hi/lo
__device__ __nv_bfloat16 g_WqT_hi[(size_t)Cn * Cn];
__device__ __nv_bfloat16 g_WqT_lo[(size_t)Cn * Cn];
__device__ __nv_bfloat16 g_WkT_hi[(size_t)KVC * Cn];
__device__ __nv_bfloat16 g_WkT_lo[(size_t)KVC * Cn];
__device__ __nv_bfloat16 g_WvT_hi[(size_t)KVC * Cn];
__device__ __nv_bfloat16 g_WvT_lo[(size_t)KVC * Cn];
__device__ __nv_bfloat16 g_WoT_hi[(size_t)Cn * Cn];
__device__ __nv_bfloat16 g_WoT_lo[(size_t)Cn * Cn];

// ===========================================================================
// PTX helpers (baseline-PTX-safe: mma.sync + ldmatrix + cp.async only)
// ===========================================================================
__device__ __forceinline__ uint32_t smem_u32(const void* p) {
    uint32_t a;
    asm("{ .reg .u64 t; cvta.to.shared.u64 t, %1; cvt.u32.u64 %0, t; }"
        : "=r"(a) : "l"(p));
    return a;
}
__device__ __forceinline__ void cp_async16(uint32_t dst, const void* src) {
    asm volatile("cp.async.cg.shared.global [%0], [%1], 16;"
                 :: "r"(dst), "l"(src) : "memory");
}
__device__ __forceinline__ void cp_commit() {
    asm volatile("cp.async.commit_group;" ::: "memory");
}
template <int N> __device__ __forceinline__ void cp_wait_group() {
    asm volatile("cp.async.wait_group %0;" :: "n"(N) : "memory");
}
__device__ __forceinline__ void ldsm_x4(uint32_t* r, uint32_t addr) {
    asm volatile("ldmatrix.sync.aligned.m8n8.x4.shared.b16 {%0,%1,%2,%3}, [%4];"
                 : "=r"(r[0]), "=r"(r[1]), "=r"(r[2]), "=r"(r[3]) : "r"(addr));
}
__device__ __forceinline__ void ldsm_x2(uint32_t* r, uint32_t addr) {
    asm volatile("ldmatrix.sync.aligned.m8n8.x2.shared.b16 {%0,%1}, [%2];"
                 : "=r"(r[0]), "=r"(r[1]) : "r"(addr));
}
__device__ __forceinline__ void mma16816(float* c, const uint32_t* a, const uint32_t* b) {
    asm volatile(
        "mma.sync.aligned.m16n8k16.row.col.f32.bf16.bf16.f32 "
        "{%0,%1,%2,%3}, {%4,%5,%6,%7}, {%8,%9}, {%0,%1,%2,%3};"
        : "+f"(c[0]), "+f"(c[1]), "+f"(c[2]), "+f"(c[3])
        : "r"(a[0]), "r"(a[1]), "r"(a[2]), "r"(a[3]), "r"(b[0]), "r"(b[1]));
}

// ===========================================================================
// split: fp32 -> bf16 hi + bf16 lo (same layout)
// ===========================================================================
__global__ void split_kernel(const float* __restrict__ X,
                             __nv_bfloat16* __restrict__ Xhi,
                             __nv_bfloat16* __restrict__ Xlo, int total)
{
    int i = blockIdx.x * blockDim.x + threadIdx.x;
    if (i >= total) return;
    float v = X[i];
    __nv_bfloat16 h = __float2bfloat16(v);
    Xhi[i] = h;
    Xlo[i] = __float2bfloat16(v - __bfloat162float(h));
}

// ===========================================================================
// transpose + split: W[K][N] fp32 -> WT[N][K] bf16 hi/lo
// ===========================================================================
__global__ __launch_bounds__(256)
void transpose_split(const float* __restrict__ W,
                     __nv_bfloat16* __restrict__ Thi,
                     __nv_bfloat16* __restrict__ Tlo, int K, int N)
{
    __shared__ float tile[32][33];
    int tx = threadIdx.x & 31, ty = threadIdx.x >> 5;   // 32 x 8
    int n0 = blockIdx.x * 32, k0 = blockIdx.y * 32;
#pragma unroll
    for (int i = 0; i < 32; i += 8)
        tile[ty + i][tx] = W[(size_t)(k0 + ty + i) * N + n0 + tx];
    __syncthreads();
#pragma unroll
    for (int i = 0; i < 32; i += 8) {
        int n = n0 + ty + i;
        int k = k0 + tx;
        float v = tile[tx][ty + i];
        __nv_bfloat16 h = __float2bfloat16(v);
        Thi[(size_t)n * K + k] = h;
        Tlo[(size_t)n * K + k] = __float2bfloat16(v - __bfloat162float(h));
    }
}

// ===========================================================================
// HMMA GEMM: C[M,N] = Ahi@BhiT + Ahi@BloT + Alo@BhiT  (fp32 accumulate)
// A: [M,K] bf16 row-major (hi/lo).  Bt: [N,K] bf16 row-major (hi/lo).
// CTA tile 128x128, BK=32, 8 warps (2x4), warp tile 64x32, double-buffered.
// ===========================================================================
#define TBM 128
#define TBN 128
#define TBK 32
#define RS  40                                   // smem row stride (bf16)
#define MAT_BYTES (128 * RS * 2)                 // 10240 B per matrix tile
#define STAGE_BYTES (4 * MAT_BYTES)              // Ahi,Alo,Bhi,Blo
#define GEMM_SMEM (2 * STAGE_BYTES)              // 81920 B

__device__ __forceinline__ void load_chunk(
    uint32_t sb, int s, int c,
    const __nv_bfloat16* __restrict__ Ahi, const __nv_bfloat16* __restrict__ Alo,
    const __nv_bfloat16* __restrict__ Bhi, const __nv_bfloat16* __restrict__ Blo,
    int row0, int col0, int K, int tid)
{
    const uint32_t st = sb + s * STAGE_BYTES;
    const size_t aoff = (size_t)row0 * K + c * TBK;
    const size_t boff = (size_t)col0 * K + c * TBK;
#pragma unroll
    for (int j = 0; j < 2; j++) {
        int idx = tid + j * 256;         // 0..511
        int r = idx >> 2, seg = idx & 3;
        uint32_t so = (uint32_t)(r * (RS * 2) + seg * 16);
        size_t goA = aoff + (size_t)r * K + seg * 8;
        size_t goB = boff + (size_t)r * K + seg * 8;
        cp_async16(st + so,                 Ahi + goA);
        cp_async16(st + MAT_BYTES + so,     Alo + goA);
        cp_async16(st + 2 * MAT_BYTES + so, Bhi + goB);
        cp_async16(st + 3 * MAT_BYTES + so, Blo + goB);
    }
    cp_commit();
}

__global__ __launch_bounds__(256)
void gemm_bf16x3(const __nv_bfloat16* __restrict__ Ahi,
                 const __nv_bfloat16* __restrict__ Alo,
                 const __nv_bfloat16* __restrict__ Bhi,
                 const __nv_bfloat16* __restrict__ Blo,
                 float* __restrict__ C, int M, int N, int K)
{
    extern __shared__ char smem[];
    const uint32_t sb = smem_u32(smem);
    const int tid = threadIdx.x;
    const int lane = tid & 31;
    const int wid = tid >> 5;            // 0..7
    const int wm = wid & 1;              // warp row (2)
    const int wn = wid >> 1;             // warp col (4)
    const int row0 = blockIdx.y * TBM;
    const int col0 = blockIdx.x * TBN;

    float acc[4][4][4];
#pragma unroll
    for (int i = 0; i < 4; i++)
#pragma unroll
        for (int j = 0; j < 4; j++)
#pragma unroll
            for (int q = 0; q < 4; q++) acc[i][j][q] = 0.f;

    // ldmatrix source addresses (fixed per thread, per stage added later)
    // A (x4): lanes 0-7 rows 0-7 k0; 8-15 rows 8-15 k0; 16-23 rows 0-7 k8; 24-31 rows 8-15 k8
    const int a_row_in = (lane & 15);
    const int a_koff   = (lane >> 4) * 8;
    // B (x2): lanes 0-15 used: n = lane&7, k-half = (lane>>3)&1
    const int b_row_in = (lane & 7);
    const int b_koff   = ((lane >> 3) & 1) * 8;

    const int NC = K / TBK;
    load_chunk(sb, 0, 0, Ahi, Alo, Bhi, Blo, row0, col0, K, tid);

    for (int c = 0; c < NC; c++) {
        const int s = c & 1;
        if (c + 1 < NC) {
            load_chunk(sb, s ^ 1, c + 1, Ahi, Alo, Bhi, Blo, row0, col0, K, tid);
            cp_wait_group<1>();
        } else {
            cp_wait_group<0>();
        }
        __syncthreads();

        const uint32_t st = sb + s * STAGE_BYTES;
#pragma unroll
        for (int kk = 0; kk < 2; kk++) {
            const int k0 = kk * 16;
            uint32_t ah[4][4], al[4][4];
#pragma unroll
            for (int mt = 0; mt < 4; mt++) {
                int row = wm * 64 + mt * 16 + a_row_in;
                uint32_t off = (uint32_t)(row * (RS * 2) + (k0 + a_koff) * 2);
                ldsm_x4(ah[mt], st + off);
                ldsm_x4(al[mt], st + MAT_BYTES + off);
            }
            uint32_t bh[4][2], bl[4][2];
#pragma unroll
            for (int nt = 0; nt < 4; nt++) {
                int rowb = wn * 32 + nt * 8 + b_row_in;
                uint32_t off = (uint32_t)(rowb * (RS * 2) + (k0 + b_koff) * 2);
                ldsm_x2(bh[nt], st + 2 * MAT_BYTES + off);
                ldsm_x2(bl[nt], st + 3 * MAT_BYTES + off);
            }
#pragma unroll
            for (int mt = 0; mt < 4; mt++)
#pragma unroll
                for (int nt = 0; nt < 4; nt++) {
                    mma16816(acc[mt][nt], ah[mt], bh[nt]);
                    mma16816(acc[mt][nt], ah[mt], bl[nt]);
                    mma16816(acc[mt][nt], al[mt], bh[nt]);
                }
        }
        __syncthreads();
    }

    // epilogue: fragment layout c0,c1 -> (t/4, (t%4)*2), c2,c3 -> (t/4+8, ...)
#pragma unroll
    for (int mt = 0; mt < 4; mt++) {
#pragma unroll
        for (int nt = 0; nt < 4; nt++) {
            int row = row0 + wm * 64 + mt * 16 + (lane >> 2);
            int col = col0 + wn * 32 + nt * 8 + (lane & 3) * 2;
            *(float2*)(C + (size_t)row * N + col) =
                make_float2(acc[mt][nt][0], acc[mt][nt][1]);
            *(float2*)(C + (size_t)(row + 8) * N + col) =
                make_float2(acc[mt][nt][2], acc[mt][nt][3]);
        }
    }
}

// ===========================================================================
// RoPE (in place) on X: [Mrows, nheads*HD]
// ===========================================================================
__global__ void rope_kernel(float* __restrict__ X,
                            const float* __restrict__ fcos,
                            const float* __restrict__ fsin,
                            int nheads, int total)
{
    int idx = blockIdx.x * blockDim.x + threadIdx.x;
    if (idx >= total) return;
    int i = idx & 63;                       // HD/2 = 64
    int h = (idx >> 6) % nheads;
    int m = idx / (64 * nheads);
    int t = m % Tn;
    float c = fcos[t * 64 + i];
    float s = fsin[t * 64 + i];
    float* p = X + (size_t)m * (nheads * HD) + h * HD + 2 * i;
    float2 v = *(float2*)p;
    float re = v.x, im = v.y;
    *(float2*)p = make_float2(re * c - im * s, re * s + im * c);
}

// ===========================================================================
// Flash attention (fp32, causal, GQA) — unchanged from round 1
// ===========================================================================
#define FBM 64
#define FBN 32
#define KPAD 132
#define SPAD 33
#define FLASH_SMEM_FLOATS (8192 + 4224 + 4096 + 2112 + 192)

__global__ __launch_bounds__(256)
void flash_attn(const float* __restrict__ Qg, const float* __restrict__ Kg,
                const float* __restrict__ Vg, float* __restrict__ Yg)
{
    extern __shared__ float sm[];
    float* Qs  = sm;
    float* Ks  = Qs + 64 * 128;
    float* Vs  = Ks + 32 * KPAD;
    float* Ss  = Vs + 32 * 128;
    float* m_s = Ss + 64 * SPAD;
    float* l_s = m_s + 64;
    float* sc_s = l_s + 64;

    const int tid = threadIdx.x;
    const int bq = blockIdx.x, h = blockIdx.y, b = blockIdx.z;
    const int q0 = bq * FBM;
    const int kvh = h / REP;

    const float* Qbase = Qg + ((size_t)b * Tn + q0) * Cn + h * HD;
    const float* Kbase = Kg + (size_t)b * Tn * KVC + kvh * HD;
    const float* Vbase = Vg + (size_t)b * Tn * KVC + kvh * HD;

#pragma unroll
    for (int p = 0; p < 8; p++) {
        int idx = tid + p * 256;
        int r = idx >> 5;
        int d4 = (idx & 31) * 4;
        *(float4*)&Qs[r * 128 + d4] = *(const float4*)(Qbase + (size_t)r * Cn + d4);
    }
    if (tid < 64) { m_s[tid] = -1e30f; l_s[tid] = 0.f; }

    const int tr = tid / 16;
    const int tc = tid % 16;

    float acc[4][8];
#pragma unroll
    for (int i = 0; i < 4; i++)
#pragma unroll
        for (int j = 0; j < 8; j++) acc[i][j] = 0.f;

    const float sscale = 0.08838834764831845f;
    const int nkb = 2 * bq + 2;

    for (int jb = 0; jb < nkb; jb++) {
        const int k0 = jb * FBN;
        __syncthreads();
#pragma unroll
        for (int p = 0; p < 4; p++) {
            int idx = tid + p * 256;
            int r = idx >> 5;
            int d4 = (idx & 31) * 4;
            *(float4*)&Ks[r * KPAD + d4] =
                *(const float4*)(Kbase + (size_t)(k0 + r) * KVC + d4);
            *(float4*)&Vs[r * 128 + d4] =
                *(const float4*)(Vbase + (size_t)(k0 + r) * KVC + d4);
        }
        __syncthreads();

        float s[4][2];
#pragma unroll
        for (int i = 0; i < 4; i++) { s[i][0] = 0.f; s[i][1] = 0.f; }
        for (int d = 0; d < 128; d += 4) {
            float4 k0v = *(float4*)&Ks[(2 * tc + 0) * KPAD + d];
            float4 k1v = *(float4*)&Ks[(2 * tc + 1) * KPAD + d];
#pragma unroll
            for (int i = 0; i < 4; i++) {
                float4 qv = *(float4*)&Qs[(4 * tr + i) * 128 + d];
                s[i][0] += qv.x * k0v.x + qv.y * k0v.y + qv.z * k0v.z + qv.w * k0v.w;
                s[i][1] += qv.x * k1v.x + qv.y * k1v.y + qv.z * k1v.z + qv.w * k1v.w;
            }
        }
#pragma unroll
        for (int i = 0; i < 4; i++) {
#pragma unroll
            for (int jj = 0; jj < 2; jj++) {
                int r = 4 * tr + i;
                int c = 2 * tc + jj;
                bool valid = (k0 + c) <= (q0 + r);
                Ss[r * SPAD + c] = valid ? s[i][jj] * sscale : -1e30f;
            }
        }
        __syncthreads();

        if (tid < 64) {
            int r = tid;
            float mo = m_s[r];
            float mn = mo;
#pragma unroll
            for (int c = 0; c < FBN; c++) mn = fmaxf(mn, Ss[r * SPAD + c]);
            float sc = __expf(mo - mn);
            float l = l_s[r] * sc;
#pragma unroll
            for (int c = 0; c < FBN; c++) {
                float e = __expf(Ss[r * SPAD + c] - mn);
                Ss[r * SPAD + c] = e;
                l += e;
            }
            m_s[r] = mn; l_s[r] = l; sc_s[r] = sc;
        }
        __syncthreads();

#pragma unroll
        for (int i = 0; i < 4; i++) {
            float sc = sc_s[4 * tr + i];
#pragma unroll
            for (int j = 0; j < 8; j++) acc[i][j] *= sc;
        }
#pragma unroll 4
        for (int k = 0; k < FBN; k++) {
            float4 v0 = *(float4*)&Vs[k * 128 + 8 * tc];
            float4 v1 = *(float4*)&Vs[k * 128 + 8 * tc + 4];
#pragma unroll
            for (int i = 0; i < 4; i++) {
                float p = Ss[(4 * tr + i) * SPAD + k];
                acc[i][0] += p * v0.x; acc[i][1] += p * v0.y;
                acc[i][2] += p * v0.z; acc[i][3] += p * v0.w;
                acc[i][4] += p * v1.x; acc[i][5] += p * v1.y;
                acc[i][6] += p * v1.z; acc[i][7] += p * v1.w;
            }
        }
    }

#pragma unroll
    for (int i = 0; i < 4; i++) {
        int r = 4 * tr + i;
        float inv = 1.f / l_s[r];
        float* dst = Yg + ((size_t)b * Tn + q0 + r) * Cn + h * HD + 8 * tc;
        *(float4*)(dst)     = make_float4(acc[i][0] * inv, acc[i][1] * inv,
                                          acc[i][2] * inv, acc[i][3] * inv);
        *(float4*)(dst + 4) = make_float4(acc[i][4] * inv, acc[i][5] * inv,
                                          acc[i][6] * inv, acc[i][7] * inv);
    }
}

// ===========================================================================
// launch
// ===========================================================================
extern "C" void kernel_launch(void* const* d_in, const int* in_sizes, int n_in,
                              void* d_out, int out_size)
{
    const float* x   = (const float*)d_in[0];
    const float* Wq  = (const float*)d_in[1];
    const float* Wk  = (const float*)d_in[2];
    const float* Wv  = (const float*)d_in[3];
    const float* Wo  = (const float*)d_in[4];
    const float* fc  = (const float*)d_in[5];
    const float* fs  = (const float*)d_in[6];
    float* out = (float*)d_out;

    float *Q, *K, *V, *Y;
    cudaGetSymbolAddress((void**)&Q, g_Q);
    cudaGetSymbolAddress((void**)&K, g_K);
    cudaGetSymbolAddress((void**)&V, g_V);
    cudaGetSymbolAddress((void**)&Y, g_Y);
    __nv_bfloat16 *Xhi, *Xlo, *Yhi, *Ylo;
    cudaGetSymbolAddress((void**)&Xhi, g_Xhi);
    cudaGetSymbolAddress((void**)&Xlo, g_Xlo);
    cudaGetSymbolAddress((void**)&Yhi, g_Yhi);
    cudaGetSymbolAddress((void**)&Ylo, g_Ylo);
    __nv_bfloat16 *WqTh, *WqTl, *WkTh, *WkTl, *WvTh, *WvTl, *WoTh, *WoTl;
    cudaGetSymbolAddress((void**)&WqTh, g_WqT_hi);
    cudaGetSymbolAddress((void**)&WqTl, g_WqT_lo);
    cudaGetSymbolAddress((void**)&WkTh, g_WkT_hi);
    cudaGetSymbolAddress((void**)&WkTl, g_WkT_lo);
    cudaGetSymbolAddress((void**)&WvTh, g_WvT_hi);
    cudaGetSymbolAddress((void**)&WvTl, g_WvT_lo);
    cudaGetSymbolAddress((void**)&WoTh, g_WoT_hi);
    cudaGetSymbolAddress((void**)&WoTl, g_WoT_lo);

    cudaFuncSetAttribute(gemm_bf16x3,
                         cudaFuncAttributeMaxDynamicSharedMemorySize, GEMM_SMEM);

    // split x; transpose+split weights
    {
        int tot = Mrows * Cn;
        split_kernel<<<(tot + 255) / 256, 256>>>(x, Xhi, Xlo, tot);
        transpose_split<<<dim3(Cn / 32, Cn / 32), 256>>>(Wq, WqTh, WqTl, Cn, Cn);
        transpose_split<<<dim3(KVC / 32, Cn / 32), 256>>>(Wk, WkTh, WkTl, Cn, KVC);
        transpose_split<<<dim3(KVC / 32, Cn / 32), 256>>>(Wv, WvTh, WvTl, Cn, KVC);
        transpose_split<<<dim3(Cn / 32, Cn / 32), 256>>>(Wo, WoTh, WoTl, Cn, Cn);
    }

    // projections on tensor cores (HMMA)
    {
        dim3 gq(Cn / TBN, Mrows / TBM);    // 16 x 32
        gemm_bf16x3<<<gq, 256, GEMM_SMEM>>>(Xhi, Xlo, WqTh, WqTl, Q, Mrows, Cn, Cn);
        dim3 gk(KVC / TBN, Mrows / TBM);   // 4 x 32
        gemm_bf16x3<<<gk, 256, GEMM_SMEM>>>(Xhi, Xlo, WkTh, WkTl, K, Mrows, KVC, Cn);
        gemm_bf16x3<<<gk, 256, GEMM_SMEM>>>(Xhi, Xlo, WvTh, WvTl, V, Mrows, KVC, Cn);
    }

    // RoPE
    {
        int totq = Mrows * NH * (HD / 2);
        rope_kernel<<<(totq + 255) / 256, 256>>>(Q, fc, fs, NH, totq);
        int totk = Mrows * NKV * (HD / 2);
        rope_kernel<<<(totk + 255) / 256, 256>>>(K, fc, fs, NKV, totk);
    }

    // attention (fp32 flash)
    {
        int smem = FLASH_SMEM_FLOATS * sizeof(float);
        cudaFuncSetAttribute(flash_attn,
                             cudaFuncAttributeMaxDynamicSharedMemorySize, smem);
        dim3 g(Tn / FBM, NH, Bn);
        flash_attn<<<g, 256, smem>>>(Q, K, V, Y);
    }

    // output projection
    {
        int tot = Mrows * Cn;
        split_kernel<<<(tot + 255) / 256, 256>>>(Y, Yhi, Ylo, tot);
        dim3 go(Cn / TBN, Mrows / TBM);
        gemm_bf16x3<<<go, 256, GEMM_SMEM>>>(Yhi, Ylo, WoTh, WoTl, out, Mrows, Cn, Cn);
    }
}

// round 4
// speedup vs baseline: 2.7566x; 1.9031x over previous
#include <cuda_runtime.h>
#include <cuda_bf16.h>
#include <cstdint>
#include <math.h>

// Problem constants
#define Bn   2
#define Tn   2048
#define Cn   2048
#define NH   16
#define NKV  4
#define HD   128
#define REP  (NH / NKV)          // 4
#define Mrows (Bn * Tn)          // 4096
#define KVC  (NKV * HD)          // 512

// ===========================================================================
// Scratch (device globals; no runtime allocation allowed)
// ===========================================================================
__device__ float g_Q[(size_t)Mrows * Cn];   // 32 MB
__device__ float g_K[(size_t)Mrows * KVC];  //  8 MB
__device__ float g_V[(size_t)Mrows * KVC];  //  8 MB
__device__ float g_Y[(size_t)Mrows * Cn];   // 32 MB

__device__ __nv_bfloat16 g_Xhi[(size_t)Mrows * Cn];
__device__ __nv_bfloat16 g_Xlo[(size_t)Mrows * Cn];
__device__ __nv_bfloat16 g_Yhi[(size_t)Mrows * Cn];
__device__ __nv_bfloat16 g_Ylo[(size_t)Mrows * Cn];

// transposed weights [N][K] (K-major) split hi/lo
__device__ __nv_bfloat16 g_WqT_hi[(size_t)Cn * Cn];
__device__ __nv_bfloat16 g_WqT_lo[(size_t)Cn * Cn];
__device__ __nv_bfloat16 g_WkT_hi[(size_t)KVC * Cn];
__device__ __nv_bfloat16 g_WkT_lo[(size_t)KVC * Cn];
__device__ __nv_bfloat16 g_WvT_hi[(size_t)KVC * Cn];
__device__ __nv_bfloat16 g_WvT_lo[(size_t)KVC * Cn];
__device__ __nv_bfloat16 g_WoT_hi[(size_t)Cn * Cn];
__device__ __nv_bfloat16 g_WoT_lo[(size_t)Cn * Cn];

// ===========================================================================
// PTX helpers (baseline-PTX-safe: mma.sync + ldmatrix + cp.async only)
// ===========================================================================
__device__ __forceinline__ uint32_t smem_u32(const void* p) {
    uint32_t a;
    asm("{ .reg .u64 t; cvta.to.shared.u64 t, %1; cvt.u32.u64 %0, t; }"
        : "=r"(a) : "l"(p));
    return a;
}
__device__ __forceinline__ void cp_async16(uint32_t dst, const void* src) {
    asm volatile("cp.async.cg.shared.global [%0], [%1], 16;"
                 :: "r"(dst), "l"(src) : "memory");
}
__device__ __forceinline__ void cp_commit() {
    asm volatile("cp.async.commit_group;" ::: "memory");
}
template <int N> __device__ __forceinline__ void cp_wait_group() {
    asm volatile("cp.async.wait_group %0;" :: "n"(N) : "memory");
}
__device__ __forceinline__ void ldsm_x4(uint32_t* r, uint32_t addr) {
    asm volatile("ldmatrix.sync.aligned.m8n8.x4.shared.b16 {%0,%1,%2,%3}, [%4];"
                 : "=r"(r[0]), "=r"(r[1]), "=r"(r[2]), "=r"(r[3]) : "r"(addr));
}
__device__ __forceinline__ void ldsm_x4_t(uint32_t* r, uint32_t addr) {
    asm volatile("ldmatrix.sync.aligned.m8n8.x4.trans.shared.b16 {%0,%1,%2,%3}, [%4];"
                 : "=r"(r[0]), "=r"(r[1]), "=r"(r[2]), "=r"(r[3]) : "r"(addr));
}
__device__ __forceinline__ void ldsm_x2(uint32_t* r, uint32_t addr) {
    asm volatile("ldmatrix.sync.aligned.m8n8.x2.shared.b16 {%0,%1}, [%2];"
                 : "=r"(r[0]), "=r"(r[1]) : "r"(addr));
}
__device__ __forceinline__ void mma16816(float* c, const uint32_t* a, const uint32_t* b) {
    asm volatile(
        "mma.sync.aligned.m16n8k16.row.col.f32.bf16.bf16.f32 "
        "{%0,%1,%2,%3}, {%4,%5,%6,%7}, {%8,%9}, {%0,%1,%2,%3};"
        : "+f"(c[0]), "+f"(c[1]), "+f"(c[2]), "+f"(c[3])
        : "r"(a[0]), "r"(a[1]), "r"(a[2]), "r"(a[3]), "r"(b[0]), "r"(b[1]));
}
__device__ __forceinline__ uint32_t pack_bf2(float a, float b) {
    __nv_bfloat162 t = __floats2bfloat162_rn(a, b);
    return *(uint32_t*)&t;
}

// ===========================================================================
// split: fp32 -> bf16 hi + bf16 lo (same layout)
// ===========================================================================
__global__ void split_kernel(const float* __restrict__ X,
                             __nv_bfloat16* __restrict__ Xhi,
                             __nv_bfloat16* __restrict__ Xlo, int total)
{
    int i = blockIdx.x * blockDim.x + threadIdx.x;
    if (i >= total) return;
    float v = X[i];
    __nv_bfloat16 h = __float2bfloat16(v);
    Xhi[i] = h;
    Xlo[i] = __float2bfloat16(v - __bfloat162float(h));
}

// ===========================================================================
// transpose + split: W[K][N] fp32 -> WT[N][K] bf16 hi/lo
// ===========================================================================
__global__ __launch_bounds__(256)
void transpose_split(const float* __restrict__ W,
                     __nv_bfloat16* __restrict__ Thi,
                     __nv_bfloat16* __restrict__ Tlo, int K, int N)
{
    __shared__ float tile[32][33];
    int tx = threadIdx.x & 31, ty = threadIdx.x >> 5;   // 32 x 8
    int n0 = blockIdx.x * 32, k0 = blockIdx.y * 32;
#pragma unroll
    for (int i = 0; i < 32; i += 8)
        tile[ty + i][tx] = W[(size_t)(k0 + ty + i) * N + n0 + tx];
    __syncthreads();
#pragma unroll
    for (int i = 0; i < 32; i += 8) {
        int n = n0 + ty + i;
        int k = k0 + tx;
        float v = tile[tx][ty + i];
        __nv_bfloat16 h = __float2bfloat16(v);
        Thi[(size_t)n * K + k] = h;
        Tlo[(size_t)n * K + k] = __float2bfloat16(v - __bfloat162float(h));
    }
}

// ===========================================================================
// HMMA GEMM: C[M,N] = Ahi@BhiT + Ahi@BloT + Alo@BhiT  (fp32 accumulate)
// ===========================================================================
#define TBM 128
#define TBN 128
#define TBK 32
#define RS  40
#define MAT_BYTES (128 * RS * 2)
#define STAGE_BYTES (4 * MAT_BYTES)
#define GEMM_SMEM (2 * STAGE_BYTES)

__device__ __forceinline__ void load_chunk(
    uint32_t sb, int s, int c,
    const __nv_bfloat16* __restrict__ Ahi, const __nv_bfloat16* __restrict__ Alo,
    const __nv_bfloat16* __restrict__ Bhi, const __nv_bfloat16* __restrict__ Blo,
    int row0, int col0, int K, int tid)
{
    const uint32_t st = sb + s * STAGE_BYTES;
    const size_t aoff = (size_t)row0 * K + c * TBK;
    const size_t boff = (size_t)col0 * K + c * TBK;
#pragma unroll
    for (int j = 0; j < 2; j++) {
        int idx = tid + j * 256;
        int r = idx >> 2, seg = idx & 3;
        uint32_t so = (uint32_t)(r * (RS * 2) + seg * 16);
        size_t goA = aoff + (size_t)r * K + seg * 8;
        size_t goB = boff + (size_t)r * K + seg * 8;
        cp_async16(st + so,                 Ahi + goA);
        cp_async16(st + MAT_BYTES + so,     Alo + goA);
        cp_async16(st + 2 * MAT_BYTES + so, Bhi + goB);
        cp_async16(st + 3 * MAT_BYTES + so, Blo + goB);
    }
    cp_commit();
}

__global__ __launch_bounds__(256)
void gemm_bf16x3(const __nv_bfloat16* __restrict__ Ahi,
                 const __nv_bfloat16* __restrict__ Alo,
                 const __nv_bfloat16* __restrict__ Bhi,
                 const __nv_bfloat16* __restrict__ Blo,
                 float* __restrict__ C, int M, int N, int K)
{
    extern __shared__ char smem[];
    const uint32_t sb = smem_u32(smem);
    const int tid = threadIdx.x;
    const int lane = tid & 31;
    const int wid = tid >> 5;
    const int wm = wid & 1;
    const int wn = wid >> 1;
    const int row0 = blockIdx.y * TBM;
    const int col0 = blockIdx.x * TBN;

    float acc[4][4][4];
#pragma unroll
    for (int i = 0; i < 4; i++)
#pragma unroll
        for (int j = 0; j < 4; j++)
#pragma unroll
            for (int q = 0; q < 4; q++) acc[i][j][q] = 0.f;

    const int a_row_in = (lane & 15);
    const int a_koff   = (lane >> 4) * 8;
    const int b_row_in = (lane & 7);
    const int b_koff   = ((lane >> 3) & 1) * 8;

    const int NC = K / TBK;
    load_chunk(sb, 0, 0, Ahi, Alo, Bhi, Blo, row0, col0, K, tid);

    for (int c = 0; c < NC; c++) {
        const int s = c & 1;
        if (c + 1 < NC) {
            load_chunk(sb, s ^ 1, c + 1, Ahi, Alo, Bhi, Blo, row0, col0, K, tid);
            cp_wait_group<1>();
        } else {
            cp_wait_group<0>();
        }
        __syncthreads();

        const uint32_t st = sb + s * STAGE_BYTES;
#pragma unroll
        for (int kk = 0; kk < 2; kk++) {
            const int k0 = kk * 16;
            uint32_t ah[4][4], al[4][4];
#pragma unroll
            for (int mt = 0; mt < 4; mt++) {
                int row = wm * 64 + mt * 16 + a_row_in;
                uint32_t off = (uint32_t)(row * (RS * 2) + (k0 + a_koff) * 2);
                ldsm_x4(ah[mt], st + off);
                ldsm_x4(al[mt], st + MAT_BYTES + off);
            }
            uint32_t bh[4][2], bl[4][2];
#pragma unroll
            for (int nt = 0; nt < 4; nt++) {
                int rowb = wn * 32 + nt * 8 + b_row_in;
                uint32_t off = (uint32_t)(rowb * (RS * 2) + (k0 + b_koff) * 2);
                ldsm_x2(bh[nt], st + 2 * MAT_BYTES + off);
                ldsm_x2(bl[nt], st + 3 * MAT_BYTES + off);
            }
#pragma unroll
            for (int mt = 0; mt < 4; mt++)
#pragma unroll
                for (int nt = 0; nt < 4; nt++) {
                    mma16816(acc[mt][nt], ah[mt], bh[nt]);
                    mma16816(acc[mt][nt], ah[mt], bl[nt]);
                    mma16816(acc[mt][nt], al[mt], bh[nt]);
                }
        }
        __syncthreads();
    }

#pragma unroll
    for (int mt = 0; mt < 4; mt++) {
#pragma unroll
        for (int nt = 0; nt < 4; nt++) {
            int row = row0 + wm * 64 + mt * 16 + (lane >> 2);
            int col = col0 + wn * 32 + nt * 8 + (lane & 3) * 2;
            *(float2*)(C + (size_t)row * N + col) =
                make_float2(acc[mt][nt][0], acc[mt][nt][1]);
            *(float2*)(C + (size_t)(row + 8) * N + col) =
                make_float2(acc[mt][nt][2], acc[mt][nt][3]);
        }
    }
}

// ===========================================================================
// RoPE (in place)
// ===========================================================================
__global__ void rope_kernel(float* __restrict__ X,
                            const float* __restrict__ fcos,
                            const float* __restrict__ fsin,
                            int nheads, int total)
{
    int idx = blockIdx.x * blockDim.x + threadIdx.x;
    if (idx >= total) return;
    int i = idx & 63;
    int h = (idx >> 6) % nheads;
    int m = idx / (64 * nheads);
    int t = m % Tn;
    float c = fcos[t * 64 + i];
    float s = fsin[t * 64 + i];
    float* p = X + (size_t)m * (nheads * HD) + h * HD + 2 * i;
    float2 v = *(float2*)p;
    float re = v.x, im = v.y;
    *(float2*)p = make_float2(re * c - im * s, re * s + im * c);
}

// ===========================================================================
// Flash attention on HMMA (bf16 3-term split, causal, GQA)
// CTA: (64-query block, head, batch). 128 threads / 4 warps, 16 q-rows per warp.
// SMEM: Qhi/Qlo, Khi/Klo, Vhi/Vlo each [64][136] bf16 (272B rows).
// ===========================================================================
#define FST 136
#define FROWB (FST * 2)          // 272 bytes per row
#define FTILE_B (64 * FROWB)     // 17408 bytes per tile
#define FLASH_SMEM (6 * FTILE_B) // 104448 bytes

__global__ __launch_bounds__(128)
void flash_attn_mma(const float* __restrict__ Qg, const float* __restrict__ Kg,
                    const float* __restrict__ Vg, float* __restrict__ Yg)
{
    extern __shared__ char smc[];
    const uint32_t sb  = smem_u32(smc);
    const uint32_t sQh = sb;
    const uint32_t sQl = sb + FTILE_B;
    const uint32_t sKh = sb + 2 * FTILE_B;
    const uint32_t sKl = sb + 3 * FTILE_B;
    const uint32_t sVh = sb + 4 * FTILE_B;
    const uint32_t sVl = sb + 5 * FTILE_B;

    const int tid = threadIdx.x;
    const int lane = tid & 31;
    const int w = tid >> 5;
    const int bq = blockIdx.x, h = blockIdx.y, b = blockIdx.z;
    const int q0 = bq * 64;
    const int kvh = h / REP;

    const float* Qbase = Qg + ((size_t)b * Tn + q0) * Cn + h * HD;
    const float* Kbase = Kg + (size_t)b * Tn * KVC + kvh * HD;
    const float* Vbase = Vg + (size_t)b * Tn * KVC + kvh * HD;

    // --- load + split Q tile (64 x 128 fp32 -> bf16 hi/lo) ---
#pragma unroll
    for (int i = 0; i < 16; i++) {
        int idx = tid + i * 128;
        int r = idx >> 5;
        int d4 = (idx & 31) * 4;
        float4 v = *(const float4*)(Qbase + (size_t)r * Cn + d4);
        __nv_bfloat16 hx = __float2bfloat16(v.x), hy = __float2bfloat16(v.y);
        __nv_bfloat16 hz = __float2bfloat16(v.z), hw = __float2bfloat16(v.w);
        uint32_t hi0 = pack_bf2(__bfloat162float(hx), __bfloat162float(hy));
        uint32_t hi1 = pack_bf2(__bfloat162float(hz), __bfloat162float(hw));
        uint32_t lo0 = pack_bf2(v.x - __bfloat162float(hx), v.y - __bfloat162float(hy));
        uint32_t lo1 = pack_bf2(v.z - __bfloat162float(hz), v.w - __bfloat162float(hw));
        uint32_t off = (uint32_t)(r * FROWB + d4 * 2);
        asm volatile("st.shared.v2.b32 [%0], {%1,%2};" :: "r"(sQh + off), "r"(hi0), "r"(hi1));
        asm volatile("st.shared.v2.b32 [%0], {%1,%2};" :: "r"(sQl + off), "r"(lo0), "r"(lo1));
    }

    // fragment addressing
    const int arow = lane & 15;
    const int akoff = (lane >> 4) * 8;
    const int brow = (lane & 7) + ((lane >> 4) * 8);
    const int bkoff = ((lane >> 3) & 1) * 8;
    const int vrow = lane & 15;
    const int vnoff = (lane >> 4) * 8;

    float Oa[16][4];
#pragma unroll
    for (int i = 0; i < 16; i++)
#pragma unroll
        for (int q = 0; q < 4; q++) Oa[i][q] = 0.f;

    float m1 = -1e30f, m2 = -1e30f, l1 = 0.f, l2 = 0.f;
    const float sscale = 0.08838834764831845f;
    const int rg1 = q0 + w * 16 + (lane >> 2);
    const int rg2 = rg1 + 8;

    for (int j = 0; j <= bq; j++) {
        const int k0g = j * 64;
        __syncthreads();
        // --- load + split K, V tiles ---
#pragma unroll
        for (int i = 0; i < 16; i++) {
            int idx = tid + i * 128;
            int r = idx >> 5;
            int d4 = (idx & 31) * 4;
            uint32_t off = (uint32_t)(r * FROWB + d4 * 2);
            {
                float4 v = *(const float4*)(Kbase + (size_t)(k0g + r) * KVC + d4);
                __nv_bfloat16 hx = __float2bfloat16(v.x), hy = __float2bfloat16(v.y);
                __nv_bfloat16 hz = __float2bfloat16(v.z), hw = __float2bfloat16(v.w);
                uint32_t hi0 = pack_bf2(__bfloat162float(hx), __bfloat162float(hy));
                uint32_t hi1 = pack_bf2(__bfloat162float(hz), __bfloat162float(hw));
                uint32_t lo0 = pack_bf2(v.x - __bfloat162float(hx), v.y - __bfloat162float(hy));
                uint32_t lo1 = pack_bf2(v.z - __bfloat162float(hz), v.w - __bfloat162float(hw));
                asm volatile("st.shared.v2.b32 [%0], {%1,%2};" :: "r"(sKh + off), "r"(hi0), "r"(hi1));
                asm volatile("st.shared.v2.b32 [%0], {%1,%2};" :: "r"(sKl + off), "r"(lo0), "r"(lo1));
            }
            {
                float4 v = *(const float4*)(Vbase + (size_t)(k0g + r) * KVC + d4);
                __nv_bfloat16 hx = __float2bfloat16(v.x), hy = __float2bfloat16(v.y);
                __nv_bfloat16 hz = __float2bfloat16(v.z), hw = __float2bfloat16(v.w);
                uint32_t hi0 = pack_bf2(__bfloat162float(hx), __bfloat162float(hy));
                uint32_t hi1 = pack_bf2(__bfloat162float(hz), __bfloat162float(hw));
                uint32_t lo0 = pack_bf2(v.x - __bfloat162float(hx), v.y - __bfloat162float(hy));
                uint32_t lo1 = pack_bf2(v.z - __bfloat162float(hz), v.w - __bfloat162float(hw));
                asm volatile("st.shared.v2.b32 [%0], {%1,%2};" :: "r"(sVh + off), "r"(hi0), "r"(hi1));
                asm volatile("st.shared.v2.b32 [%0], {%1,%2};" :: "r"(sVl + off), "r"(lo0), "r"(lo1));
            }
        }
        __syncthreads();

        // --- S = Q K^T (3-term split) ---
        float S[8][4];
#pragma unroll
        for (int t = 0; t < 8; t++)
#pragma unroll
            for (int q = 0; q < 4; q++) S[t][q] = 0.f;

#pragma unroll
        for (int kc = 0; kc < 8; kc++) {
            uint32_t ah[4], al[4];
            uint32_t aoff = (uint32_t)((w * 16 + arow) * FROWB + (kc * 16 + akoff) * 2);
            ldsm_x4(ah, sQh + aoff);
            ldsm_x4(al, sQl + aoff);
#pragma unroll
            for (int np = 0; np < 4; np++) {
                uint32_t bh[4], bl[4];
                uint32_t boff = (uint32_t)((np * 16 + brow) * FROWB + (kc * 16 + bkoff) * 2);
                ldsm_x4(bh, sKh + boff);
                ldsm_x4(bl, sKl + boff);
                mma16816(S[2 * np],     ah, bh);
                mma16816(S[2 * np],     ah, bl);
                mma16816(S[2 * np],     al, bh);
                mma16816(S[2 * np + 1], ah, bh + 2);
                mma16816(S[2 * np + 1], ah, bl + 2);
                mma16816(S[2 * np + 1], al, bh + 2);
            }
        }

        // --- mask + scale + online softmax (register, quad shuffles) ---
        const bool diag = (j == bq);
        float mx1 = -1e30f, mx2 = -1e30f;
#pragma unroll
        for (int t = 0; t < 8; t++) {
            int cg = k0g + t * 8 + (lane & 3) * 2;
#pragma unroll
            for (int e = 0; e < 2; e++) {
                float s0 = S[t][e] * sscale;
                float s1 = S[t][2 + e] * sscale;
                if (diag) {
                    if (cg + e > rg1) s0 = -1e30f;
                    if (cg + e > rg2) s1 = -1e30f;
                }
                S[t][e] = s0;
                S[t][2 + e] = s1;
                mx1 = fmaxf(mx1, s0);
                mx2 = fmaxf(mx2, s1);
            }
        }
        mx1 = fmaxf(mx1, __shfl_xor_sync(0xffffffff, mx1, 1));
        mx1 = fmaxf(mx1, __shfl_xor_sync(0xffffffff, mx1, 2));
        mx2 = fmaxf(mx2, __shfl_xor_sync(0xffffffff, mx2, 1));
        mx2 = fmaxf(mx2, __shfl_xor_sync(0xffffffff, mx2, 2));

        float mn1 = fmaxf(m1, mx1), mn2 = fmaxf(m2, mx2);
        float f1 = __expf(m1 - mn1), f2 = __expf(m2 - mn2);
        float rs1 = 0.f, rs2 = 0.f;
#pragma unroll
        for (int t = 0; t < 8; t++) {
#pragma unroll
            for (int e = 0; e < 2; e++) {
                float p0 = __expf(S[t][e] - mn1);
                float p1 = __expf(S[t][2 + e] - mn2);
                S[t][e] = p0;
                S[t][2 + e] = p1;
                rs1 += p0;
                rs2 += p1;
            }
        }
        rs1 += __shfl_xor_sync(0xffffffff, rs1, 1);
        rs1 += __shfl_xor_sync(0xffffffff, rs1, 2);
        rs2 += __shfl_xor_sync(0xffffffff, rs2, 1);
        rs2 += __shfl_xor_sync(0xffffffff, rs2, 2);
        l1 = l1 * f1 + rs1;
        l2 = l2 * f2 + rs2;
        m1 = mn1; m2 = mn2;
#pragma unroll
        for (int t = 0; t < 16; t++) {
            Oa[t][0] *= f1; Oa[t][1] *= f1;
            Oa[t][2] *= f2; Oa[t][3] *= f2;
        }

        // --- O += P V (3-term split; P frags from registers, V via ldmatrix.trans) ---
#pragma unroll
        for (int kc = 0; kc < 4; kc++) {
            uint32_t ph[4], pl[4];
            {
                const float* s0 = S[2 * kc];
                const float* s1 = S[2 * kc + 1];
                float h00 = __bfloat162float(__float2bfloat16(s0[0]));
                float h01 = __bfloat162float(__float2bfloat16(s0[1]));
                float h02 = __bfloat162float(__float2bfloat16(s0[2]));
                float h03 = __bfloat162float(__float2bfloat16(s0[3]));
                float h10 = __bfloat162float(__float2bfloat16(s1[0]));
                float h11 = __bfloat162float(__float2bfloat16(s1[1]));
                float h12 = __bfloat162float(__float2bfloat16(s1[2]));
                float h13 = __bfloat162float(__float2bfloat16(s1[3]));
                ph[0] = pack_bf2(h00, h01);
                ph[1] = pack_bf2(h02, h03);
                ph[2] = pack_bf2(h10, h11);
                ph[3] = pack_bf2(h12, h13);
                pl[0] = pack_bf2(s0[0] - h00, s0[1] - h01);
                pl[1] = pack_bf2(s0[2] - h02, s0[3] - h03);
                pl[2] = pack_bf2(s1[0] - h10, s1[1] - h11);
                pl[3] = pack_bf2(s1[2] - h12, s1[3] - h13);
            }
#pragma unroll
            for (int np = 0; np < 8; np++) {
                uint32_t vh[4], vl[4];
                uint32_t voff = (uint32_t)((kc * 16 + vrow) * FROWB + (np * 16 + vnoff) * 2);
                ldsm_x4_t(vh, sVh + voff);
                ldsm_x4_t(vl, sVl + voff);
                mma16816(Oa[2 * np],     ph, vh);
                mma16816(Oa[2 * np],     ph, vl);
                mma16816(Oa[2 * np],     pl, vh);
                mma16816(Oa[2 * np + 1], ph, vh + 2);
                mma16816(Oa[2 * np + 1], ph, vl + 2);
                mma16816(Oa[2 * np + 1], pl, vh + 2);
            }
        }
    }

    // --- epilogue ---
    const float il1 = 1.f / l1, il2 = 1.f / l2;
    float* Y1 = Yg + ((size_t)b * Tn + q0 + w * 16 + (lane >> 2)) * Cn + h * HD;
    float* Y2 = Y1 + 8 * Cn;
#pragma unroll
    for (int nt = 0; nt < 16; nt++) {
        int col = nt * 8 + (lane & 3) * 2;
        *(float2*)(Y1 + col) = make_float2(Oa[nt][0] * il1, Oa[nt][1] * il1);
        *(float2*)(Y2 + col) = make_float2(Oa[nt][2] * il2, Oa[nt][3] * il2);
    }
}

// ===========================================================================
// launch
// ===========================================================================
extern "C" void kernel_launch(void* const* d_in, const int* in_sizes, int n_in,
                              void* d_out, int out_size)
{
    const float* x   = (const float*)d_in[0];
    const float* Wq  = (const float*)d_in[1];
    const float* Wk  = (const float*)d_in[2];
    const float* Wv  = (const float*)d_in[3];
    const float* Wo  = (const float*)d_in[4];
    const float* fc  = (const float*)d_in[5];
    const float* fs  = (const float*)d_in[6];
    float* out = (float*)d_out;

    float *Q, *K, *V, *Y;
    cudaGetSymbolAddress((void**)&Q, g_Q);
    cudaGetSymbolAddress((void**)&K, g_K);
    cudaGetSymbolAddress((void**)&V, g_V);
    cudaGetSymbolAddress((void**)&Y, g_Y);
    __nv_bfloat16 *Xhi, *Xlo, *Yhi, *Ylo;
    cudaGetSymbolAddress((void**)&Xhi, g_Xhi);
    cudaGetSymbolAddress((void**)&Xlo, g_Xlo);
    cudaGetSymbolAddress((void**)&Yhi, g_Yhi);
    cudaGetSymbolAddress((void**)&Ylo, g_Ylo);
    __nv_bfloat16 *WqTh, *WqTl, *WkTh, *WkTl, *WvTh, *WvTl, *WoTh, *WoTl;
    cudaGetSymbolAddress((void**)&WqTh, g_WqT_hi);
    cudaGetSymbolAddress((void**)&WqTl, g_WqT_lo);
    cudaGetSymbolAddress((void**)&WkTh, g_WkT_hi);
    cudaGetSymbolAddress((void**)&WkTl, g_WkT_lo);
    cudaGetSymbolAddress((void**)&WvTh, g_WvT_hi);
    cudaGetSymbolAddress((void**)&WvTl, g_WvT_lo);
    cudaGetSymbolAddress((void**)&WoTh, g_WoT_hi);
    cudaGetSymbolAddress((void**)&WoTl, g_WoT_lo);

    cudaFuncSetAttribute(gemm_bf16x3,
                         cudaFuncAttributeMaxDynamicSharedMemorySize, GEMM_SMEM);
    cudaFuncSetAttribute(flash_attn_mma,
                         cudaFuncAttributeMaxDynamicSharedMemorySize, FLASH_SMEM);

    // split x; transpose+split weights
    {
        int tot = Mrows * Cn;
        split_kernel<<<(tot + 255) / 256, 256>>>(x, Xhi, Xlo, tot);
        transpose_split<<<dim3(Cn / 32, Cn / 32), 256>>>(Wq, WqTh, WqTl, Cn, Cn);
        transpose_split<<<dim3(KVC / 32, Cn / 32), 256>>>(Wk, WkTh, WkTl, Cn, KVC);
        transpose_split<<<dim3(KVC / 32, Cn / 32), 256>>>(Wv, WvTh, WvTl, Cn, KVC);
        transpose_split<<<dim3(Cn / 32, Cn / 32), 256>>>(Wo, WoTh, WoTl, Cn, Cn);
    }

    // projections on tensor cores (HMMA)
    {
        dim3 gq(Cn / TBN, Mrows / TBM);    // 16 x 32
        gemm_bf16x3<<<gq, 256, GEMM_SMEM>>>(Xhi, Xlo, WqTh, WqTl, Q, Mrows, Cn, Cn);
        dim3 gk(KVC / TBN, Mrows / TBM);   // 4 x 32
        gemm_bf16x3<<<gk, 256, GEMM_SMEM>>>(Xhi, Xlo, WkTh, WkTl, K, Mrows, KVC, Cn);
        gemm_bf16x3<<<gk, 256, GEMM_SMEM>>>(Xhi, Xlo, WvTh, WvTl, V, Mrows, KVC, Cn);
    }

    // RoPE
    {
        int totq = Mrows * NH * (HD / 2);
        rope_kernel<<<(totq + 255) / 256, 256>>>(Q, fc, fs, NH, totq);
        int totk = Mrows * NKV * (HD / 2);
        rope_kernel<<<(totk + 255) / 256, 256>>>(K, fc, fs, NKV, totk);
    }

    // attention (HMMA flash)
    {
        dim3 g(Tn / 64, NH, Bn);           // 32 x 16 x 2
        flash_attn_mma<<<g, 128, FLASH_SMEM>>>(Q, K, V, Y);
    }

    // output projection
    {
        int tot = Mrows * Cn;
        split_kernel<<<(tot + 255) / 256, 256>>>(Y, Yhi, Ylo, tot);
        dim3 go(Cn / TBN, Mrows / TBM);
        gemm_bf16x3<<<go, 256, GEMM_SMEM>>>(Yhi, Ylo, WoTh, WoTl, out, Mrows, Cn, Cn);
    }
}

// round 5
// speedup vs baseline: 2.8160x; 1.0215x over previous
#include <cuda_runtime.h>
#include <cuda_bf16.h>
#include <cstdint>
#include <math.h>

// Problem constants
#define Bn   2
#define Tn   2048
#define Cn   2048
#define NH   16
#define NKV  4
#define HD   128
#define REP  (NH / NKV)          // 4
#define Mrows (Bn * Tn)          // 4096
#define KVC  (NKV * HD)          // 512

// ===========================================================================
// Scratch (device globals; no runtime allocation allowed)
// ===========================================================================
__device__ float g_Q[(size_t)Mrows * Cn];   // 32 MB
__device__ float g_K[(size_t)Mrows * KVC];  //  8 MB
__device__ float g_V[(size_t)Mrows * KVC];  //  8 MB

__device__ __nv_bfloat16 g_Xhi[(size_t)Mrows * Cn];
__device__ __nv_bfloat16 g_Xlo[(size_t)Mrows * Cn];
__device__ __nv_bfloat16 g_Yhi[(size_t)Mrows * Cn];
__device__ __nv_bfloat16 g_Ylo[(size_t)Mrows * Cn];

// transposed weights [N][K] (K-major) split hi/lo
__device__ __nv_bfloat16 g_WqT_hi[(size_t)Cn * Cn];
__device__ __nv_bfloat16 g_WqT_lo[(size_t)Cn * Cn];
__device__ __nv_bfloat16 g_WkT_hi[(size_t)KVC * Cn];
__device__ __nv_bfloat16 g_WkT_lo[(size_t)KVC * Cn];
__device__ __nv_bfloat16 g_WvT_hi[(size_t)KVC * Cn];
__device__ __nv_bfloat16 g_WvT_lo[(size_t)KVC * Cn];
__device__ __nv_bfloat16 g_WoT_hi[(size_t)Cn * Cn];
__device__ __nv_bfloat16 g_WoT_lo[(size_t)Cn * Cn];

// ===========================================================================
// PTX helpers (baseline-PTX-safe: mma.sync + ldmatrix + cp.async only)
// ===========================================================================
__device__ __forceinline__ uint32_t smem_u32(const void* p) {
    uint32_t a;
    asm("{ .reg .u64 t; cvta.to.shared.u64 t, %1; cvt.u32.u64 %0, t; }"
        : "=r"(a) : "l"(p));
    return a;
}
__device__ __forceinline__ void cp_async16(uint32_t dst, const void* src) {
    asm volatile("cp.async.cg.shared.global [%0], [%1], 16;"
                 :: "r"(dst), "l"(src) : "memory");
}
__device__ __forceinline__ void cp_commit() {
    asm volatile("cp.async.commit_group;" ::: "memory");
}
template <int N> __device__ __forceinline__ void cp_wait_group() {
    asm volatile("cp.async.wait_group %0;" :: "n"(N) : "memory");
}
__device__ __forceinline__ void ldsm_x4(uint32_t* r, uint32_t addr) {
    asm volatile("ldmatrix.sync.aligned.m8n8.x4.shared.b16 {%0,%1,%2,%3}, [%4];"
                 : "=r"(r[0]), "=r"(r[1]), "=r"(r[2]), "=r"(r[3]) : "r"(addr));
}
__device__ __forceinline__ void ldsm_x4_t(uint32_t* r, uint32_t addr) {
    asm volatile("ldmatrix.sync.aligned.m8n8.x4.trans.shared.b16 {%0,%1,%2,%3}, [%4];"
                 : "=r"(r[0]), "=r"(r[1]), "=r"(r[2]), "=r"(r[3]) : "r"(addr));
}
__device__ __forceinline__ void ldsm_x2(uint32_t* r, uint32_t addr) {
    asm volatile("ldmatrix.sync.aligned.m8n8.x2.shared.b16 {%0,%1}, [%2];"
                 : "=r"(r[0]), "=r"(r[1]) : "r"(addr));
}
__device__ __forceinline__ void mma16816(float* c, const uint32_t* a, const uint32_t* b) {
    asm volatile(
        "mma.sync.aligned.m16n8k16.row.col.f32.bf16.bf16.f32 "
        "{%0,%1,%2,%3}, {%4,%5,%6,%7}, {%8,%9}, {%0,%1,%2,%3};"
        : "+f"(c[0]), "+f"(c[1]), "+f"(c[2]), "+f"(c[3])
        : "r"(a[0]), "r"(a[1]), "r"(a[2]), "r"(a[3]), "r"(b[0]), "r"(b[1]));
}
__device__ __forceinline__ uint32_t pack_bf2(float a, float b) {
    __nv_bfloat162 t = __floats2bfloat162_rn(a, b);
    return *(uint32_t*)&t;
}

// ===========================================================================
// split: fp32 -> bf16 hi + bf16 lo (same layout)
// ===========================================================================
__global__ void split_kernel(const float* __restrict__ X,
                             __nv_bfloat16* __restrict__ Xhi,
                             __nv_bfloat16* __restrict__ Xlo, int total)
{
    int i = blockIdx.x * blockDim.x + threadIdx.x;
    if (i >= total) return;
    float v = X[i];
    __nv_bfloat16 h = __float2bfloat16(v);
    Xhi[i] = h;
    Xlo[i] = __float2bfloat16(v - __bfloat162float(h));
}

// ===========================================================================
// transpose + split: W[K][N] fp32 -> WT[N][K] bf16 hi/lo
// ===========================================================================
__global__ __launch_bounds__(256)
void transpose_split(const float* __restrict__ W,
                     __nv_bfloat16* __restrict__ Thi,
                     __nv_bfloat16* __restrict__ Tlo, int K, int N)
{
    __shared__ float tile[32][33];
    int tx = threadIdx.x & 31, ty = threadIdx.x >> 5;   // 32 x 8
    int n0 = blockIdx.x * 32, k0 = blockIdx.y * 32;
#pragma unroll
    for (int i = 0; i < 32; i += 8)
        tile[ty + i][tx] = W[(size_t)(k0 + ty + i) * N + n0 + tx];
    __syncthreads();
#pragma unroll
    for (int i = 0; i < 32; i += 8) {
        int n = n0 + ty + i;
        int k = k0 + tx;
        float v = tile[tx][ty + i];
        __nv_bfloat16 h = __float2bfloat16(v);
        Thi[(size_t)n * K + k] = h;
        Tlo[(size_t)n * K + k] = __float2bfloat16(v - __bfloat162float(h));
    }
}

// ===========================================================================
// HMMA GEMM core: C = Ahi@BhT + Ahi@BlT + Alo@BhT (fp32 acc)
// 128x128 tile, BK=32, 256 threads, 3-stage cp.async pipeline.
// Pointers pre-offset: A* to row0, B* to col0 row, Cc to (row0, col0).
// ===========================================================================
#define TBK 32
#define RS  40
#define MAT_BYTES (128 * RS * 2)          // 10240
#define STG_BYTES (4 * MAT_BYTES)         // 40960
#define GEMM_SMEM (3 * STG_BYTES)         // 122880

__device__ __forceinline__ void gemm3_load(
    uint32_t st,
    const __nv_bfloat16* __restrict__ Ah, const __nv_bfloat16* __restrict__ Al,
    const __nv_bfloat16* __restrict__ Bh, const __nv_bfloat16* __restrict__ Bl,
    int K, int c, int tid)
{
#pragma unroll
    for (int j = 0; j < 2; j++) {
        int idx = tid + j * 256;
        int r = idx >> 2, seg = idx & 3;
        uint32_t so = (uint32_t)(r * (RS * 2) + seg * 16);
        size_t go = (size_t)r * K + (size_t)c * TBK + seg * 8;
        cp_async16(st + so,                 Ah + go);
        cp_async16(st + MAT_BYTES + so,     Al + go);
        cp_async16(st + 2 * MAT_BYTES + so, Bh + go);
        cp_async16(st + 3 * MAT_BYTES + so, Bl + go);
    }
    cp_commit();
}

__device__ __forceinline__ void gemm3_core(
    const __nv_bfloat16* __restrict__ Ah, const __nv_bfloat16* __restrict__ Al,
    const __nv_bfloat16* __restrict__ Bh, const __nv_bfloat16* __restrict__ Bl,
    float* __restrict__ Cc, int ldc, int K)
{
    extern __shared__ char smem[];
    const uint32_t sb = smem_u32(smem);
    const int tid = threadIdx.x;
    const int lane = tid & 31;
    const int wid = tid >> 5;
    const int wm = wid & 1;
    const int wn = wid >> 1;

    float acc[4][4][4];
#pragma unroll
    for (int i = 0; i < 4; i++)
#pragma unroll
        for (int j = 0; j < 4; j++)
#pragma unroll
            for (int q = 0; q < 4; q++) acc[i][j][q] = 0.f;

    const int a_row_in = (lane & 15);
    const int a_koff   = (lane >> 4) * 8;
    const int b_row_in = (lane & 7);
    const int b_koff   = ((lane >> 3) & 1) * 8;

    const int NC = K / TBK;
    gemm3_load(sb,              Ah, Al, Bh, Bl, K, 0, tid);
    gemm3_load(sb + STG_BYTES,  Ah, Al, Bh, Bl, K, 1, tid);

    int snext = 2;     // stage index for c+2
    for (int c = 0; c < NC; c++) {
        const int s = (c < NC - (NC % 3 == 0 ? 3 : NC % 3)) ? 0 : 0; // placeholder (unused)
        (void)s;
        const int scur = c % 3;
        if (c + 2 < NC) { cp_wait_group<1>(); } else { cp_wait_group<0>(); }
        __syncthreads();
        if (c + 2 < NC) {
            gemm3_load(sb + snext * STG_BYTES, Ah, Al, Bh, Bl, K, c + 2, tid);
            snext = (snext + 1) % 3;
        }

        const uint32_t st = sb + scur * STG_BYTES;
#pragma unroll
        for (int kk = 0; kk < 2; kk++) {
            const int k0 = kk * 16;
            uint32_t ah[4][4], al[4][4];
#pragma unroll
            for (int mt = 0; mt < 4; mt++) {
                int row = wm * 64 + mt * 16 + a_row_in;
                uint32_t off = (uint32_t)(row * (RS * 2) + (k0 + a_koff) * 2);
                ldsm_x4(ah[mt], st + off);
                ldsm_x4(al[mt], st + MAT_BYTES + off);
            }
            uint32_t bh[4][2], bl[4][2];
#pragma unroll
            for (int nt = 0; nt < 4; nt++) {
                int rowb = wn * 32 + nt * 8 + b_row_in;
                uint32_t off = (uint32_t)(rowb * (RS * 2) + (k0 + b_koff) * 2);
                ldsm_x2(bh[nt], st + 2 * MAT_BYTES + off);
                ldsm_x2(bl[nt], st + 3 * MAT_BYTES + off);
            }
#pragma unroll
            for (int mt = 0; mt < 4; mt++)
#pragma unroll
                for (int nt = 0; nt < 4; nt++) {
                    mma16816(acc[mt][nt], ah[mt], bh[nt]);
                    mma16816(acc[mt][nt], ah[mt], bl[nt]);
                    mma16816(acc[mt][nt], al[mt], bh[nt]);
                }
        }
    }

#pragma unroll
    for (int mt = 0; mt < 4; mt++) {
#pragma unroll
        for (int nt = 0; nt < 4; nt++) {
            int row = wm * 64 + mt * 16 + (lane >> 2);
            int col = wn * 32 + nt * 8 + (lane & 3) * 2;
            *(float2*)(Cc + (size_t)row * ldc + col) =
                make_float2(acc[mt][nt][0], acc[mt][nt][1]);
            *(float2*)(Cc + (size_t)(row + 8) * ldc + col) =
                make_float2(acc[mt][nt][2], acc[mt][nt][3]);
        }
    }
}

// Fused QKV projection: grid (24, 32). Col tiles 0-15 -> Q, 16-19 -> K, 20-23 -> V
__global__ __launch_bounds__(256)
void gemm3_qkv(const __nv_bfloat16* __restrict__ Xh, const __nv_bfloat16* __restrict__ Xl,
               const __nv_bfloat16* __restrict__ Wqh, const __nv_bfloat16* __restrict__ Wql,
               const __nv_bfloat16* __restrict__ Wkh, const __nv_bfloat16* __restrict__ Wkl,
               const __nv_bfloat16* __restrict__ Wvh, const __nv_bfloat16* __restrict__ Wvl,
               float* __restrict__ Q, float* __restrict__ Ko, float* __restrict__ Vo)
{
    const int ct = blockIdx.x;
    const int row0 = blockIdx.y * 128;
    const __nv_bfloat16 *Bh, *Bl;
    float* C;
    int ldc, c0;
    if (ct < 16)       { Bh = Wqh; Bl = Wql; C = Q;  ldc = Cn;  c0 = ct * 128; }
    else if (ct < 20)  { Bh = Wkh; Bl = Wkl; C = Ko; ldc = KVC; c0 = (ct - 16) * 128; }
    else               { Bh = Wvh; Bl = Wvl; C = Vo; ldc = KVC; c0 = (ct - 20) * 128; }
    gemm3_core(Xh + (size_t)row0 * Cn, Xl + (size_t)row0 * Cn,
               Bh + (size_t)c0 * Cn,  Bl + (size_t)c0 * Cn,
               C + (size_t)row0 * ldc + c0, ldc, Cn);
}

// Generic NN GEMM (used for output projection)
__global__ __launch_bounds__(256)
void gemm3_nn(const __nv_bfloat16* __restrict__ Ah, const __nv_bfloat16* __restrict__ Al,
              const __nv_bfloat16* __restrict__ Bh, const __nv_bfloat16* __restrict__ Bl,
              float* __restrict__ C, int N, int K)
{
    const int row0 = blockIdx.y * 128;
    const int col0 = blockIdx.x * 128;
    gemm3_core(Ah + (size_t)row0 * K, Al + (size_t)row0 * K,
               Bh + (size_t)col0 * K, Bl + (size_t)col0 * K,
               C + (size_t)row0 * N + col0, N, K);
}

// ===========================================================================
// RoPE (in place)
// ===========================================================================
__global__ void rope_kernel(float* __restrict__ X,
                            const float* __restrict__ fcos,
                            const float* __restrict__ fsin,
                            int nheads, int total)
{
    int idx = blockIdx.x * blockDim.x + threadIdx.x;
    if (idx >= total) return;
    int i = idx & 63;
    int h = (idx >> 6) % nheads;
    int m = idx / (64 * nheads);
    int t = m % Tn;
    float c = fcos[t * 64 + i];
    float s = fsin[t * 64 + i];
    float* p = X + (size_t)m * (nheads * HD) + h * HD + 2 * i;
    float2 v = *(float2*)p;
    float re = v.x, im = v.y;
    *(float2*)p = make_float2(re * c - im * s, re * s + im * c);
}

// ===========================================================================
// Flash attention on HMMA (bf16 3-term split, causal, GQA)
// CTA: (128-query block, head, batch). 256 threads / 8 warps.
// Writes bf16 hi/lo split output directly (consumed by O-projection GEMM).
// ===========================================================================
#define FST 136
#define FROWB (FST * 2)              // 272 bytes per row
#define QTILE_B (128 * FROWB)        // 34816
#define KTILE_B (64 * FROWB)         // 17408
#define FLASH_SMEM (2 * QTILE_B + 4 * KTILE_B)   // 139264

__global__ __launch_bounds__(256)
void flash_attn_mma(const float* __restrict__ Qg, const float* __restrict__ Kg,
                    const float* __restrict__ Vg,
                    __nv_bfloat16* __restrict__ Yhi, __nv_bfloat16* __restrict__ Ylo)
{
    extern __shared__ char smc[];
    const uint32_t sb  = smem_u32(smc);
    const uint32_t sQh = sb;
    const uint32_t sQl = sb + QTILE_B;
    const uint32_t sKh = sb + 2 * QTILE_B;
    const uint32_t sKl = sKh + KTILE_B;
    const uint32_t sVh = sKh + 2 * KTILE_B;
    const uint32_t sVl = sKh + 3 * KTILE_B;

    const int tid = threadIdx.x;
    const int lane = tid & 31;
    const int w = tid >> 5;                          // 0..7
    const int bq = gridDim.x - 1 - blockIdx.x;       // heavy blocks first
    const int h = blockIdx.y, b = blockIdx.z;
    const int q0 = bq * 128;
    const int kvh = h / REP;

    const float* Qbase = Qg + ((size_t)b * Tn + q0) * Cn + h * HD;
    const float* Kbase = Kg + (size_t)b * Tn * KVC + kvh * HD;
    const float* Vbase = Vg + (size_t)b * Tn * KVC + kvh * HD;

    // --- load + split Q tile (128 x 128 fp32 -> bf16 hi/lo) ---
#pragma unroll
    for (int i = 0; i < 16; i++) {
        int idx = tid + i * 256;
        int r = idx >> 5;                  // 0..127
        int d4 = (idx & 31) * 4;
        float4 v = *(const float4*)(Qbase + (size_t)r * Cn + d4);
        __nv_bfloat16 hx = __float2bfloat16(v.x), hy = __float2bfloat16(v.y);
        __nv_bfloat16 hz = __float2bfloat16(v.z), hw = __float2bfloat16(v.w);
        uint32_t hi0 = pack_bf2(__bfloat162float(hx), __bfloat162float(hy));
        uint32_t hi1 = pack_bf2(__bfloat162float(hz), __bfloat162float(hw));
        uint32_t lo0 = pack_bf2(v.x - __bfloat162float(hx), v.y - __bfloat162float(hy));
        uint32_t lo1 = pack_bf2(v.z - __bfloat162float(hz), v.w - __bfloat162float(hw));
        uint32_t off = (uint32_t)(r * FROWB + d4 * 2);
        asm volatile("st.shared.v2.b32 [%0], {%1,%2};" :: "r"(sQh + off), "r"(hi0), "r"(hi1));
        asm volatile("st.shared.v2.b32 [%0], {%1,%2};" :: "r"(sQl + off), "r"(lo0), "r"(lo1));
    }

    // fragment addressing
    const int arow = lane & 15;
    const int akoff = (lane >> 4) * 8;
    const int brow = (lane & 7) + ((lane >> 4) * 8);
    const int bkoff = ((lane >> 3) & 1) * 8;
    const int vrow = lane & 15;
    const int vnoff = (lane >> 4) * 8;

    float Oa[16][4];
#pragma unroll
    for (int i = 0; i < 16; i++)
#pragma unroll
        for (int q = 0; q < 4; q++) Oa[i][q] = 0.f;

    float m1 = -1e30f, m2 = -1e30f, l1 = 0.f, l2 = 0.f;
    const float sscale = 0.08838834764831845f;
    const int rg1 = q0 + w * 16 + (lane >> 2);
    const int rg2 = rg1 + 8;

    const int nkb = 2 * bq + 2;
    for (int j = 0; j < nkb; j++) {
        const int k0g = j * 64;
        __syncthreads();
        // --- load + split K, V tiles (64 x 128 each) ---
#pragma unroll
        for (int i = 0; i < 8; i++) {
            int idx = tid + i * 256;
            int r = idx >> 5;              // 0..63
            int d4 = (idx & 31) * 4;
            uint32_t off = (uint32_t)(r * FROWB + d4 * 2);
            {
                float4 v = *(const float4*)(Kbase + (size_t)(k0g + r) * KVC + d4);
                __nv_bfloat16 hx = __float2bfloat16(v.x), hy = __float2bfloat16(v.y);
                __nv_bfloat16 hz = __float2bfloat16(v.z), hw = __float2bfloat16(v.w);
                uint32_t hi0 = pack_bf2(__bfloat162float(hx), __bfloat162float(hy));
                uint32_t hi1 = pack_bf2(__bfloat162float(hz), __bfloat162float(hw));
                uint32_t lo0 = pack_bf2(v.x - __bfloat162float(hx), v.y - __bfloat162float(hy));
                uint32_t lo1 = pack_bf2(v.z - __bfloat162float(hz), v.w - __bfloat162float(hw));
                asm volatile("st.shared.v2.b32 [%0], {%1,%2};" :: "r"(sKh + off), "r"(hi0), "r"(hi1));
                asm volatile("st.shared.v2.b32 [%0], {%1,%2};" :: "r"(sKl + off), "r"(lo0), "r"(lo1));
            }
            {
                float4 v = *(const float4*)(Vbase + (size_t)(k0g + r) * KVC + d4);
                __nv_bfloat16 hx = __float2bfloat16(v.x), hy = __float2bfloat16(v.y);
                __nv_bfloat16 hz = __float2bfloat16(v.z), hw = __float2bfloat16(v.w);
                uint32_t hi0 = pack_bf2(__bfloat162float(hx), __bfloat162float(hy));
                uint32_t hi1 = pack_bf2(__bfloat162float(hz), __bfloat162float(hw));
                uint32_t lo0 = pack_bf2(v.x - __bfloat162float(hx), v.y - __bfloat162float(hy));
                uint32_t lo1 = pack_bf2(v.z - __bfloat162float(hz), v.w - __bfloat162float(hw));
                asm volatile("st.shared.v2.b32 [%0], {%1,%2};" :: "r"(sVh + off), "r"(hi0), "r"(hi1));
                asm volatile("st.shared.v2.b32 [%0], {%1,%2};" :: "r"(sVl + off), "r"(lo0), "r"(lo1));
            }
        }
        __syncthreads();

        // --- S = Q K^T (3-term split) ---
        float S[8][4];
#pragma unroll
        for (int t = 0; t < 8; t++)
#pragma unroll
            for (int q = 0; q < 4; q++) S[t][q] = 0.f;

#pragma unroll
        for (int kc = 0; kc < 8; kc++) {
            uint32_t ah[4], al[4];
            uint32_t aoff = (uint32_t)((w * 16 + arow) * FROWB + (kc * 16 + akoff) * 2);
            ldsm_x4(ah, sQh + aoff);
            ldsm_x4(al, sQl + aoff);
#pragma unroll
            for (int np = 0; np < 4; np++) {
                uint32_t bh[4], bl[4];
                uint32_t boff = (uint32_t)((np * 16 + brow) * FROWB + (kc * 16 + bkoff) * 2);
                ldsm_x4(bh, sKh + boff);
                ldsm_x4(bl, sKl + boff);
                mma16816(S[2 * np],     ah, bh);
                mma16816(S[2 * np],     ah, bl);
                mma16816(S[2 * np],     al, bh);
                mma16816(S[2 * np + 1], ah, bh + 2);
                mma16816(S[2 * np + 1], ah, bl + 2);
                mma16816(S[2 * np + 1], al, bh + 2);
            }
        }

        // --- mask + scale + online softmax ---
        const bool diag = (k0g + 63 > q0 + w * 16);
        float mx1 = -1e30f, mx2 = -1e30f;
#pragma unroll
        for (int t = 0; t < 8; t++) {
            int cg = k0g + t * 8 + (lane & 3) * 2;
#pragma unroll
            for (int e = 0; e < 2; e++) {
                float s0 = S[t][e] * sscale;
                float s1 = S[t][2 + e] * sscale;
                if (diag) {
                    if (cg + e > rg1) s0 = -1e30f;
                    if (cg + e > rg2) s1 = -1e30f;
                }
                S[t][e] = s0;
                S[t][2 + e] = s1;
                mx1 = fmaxf(mx1, s0);
                mx2 = fmaxf(mx2, s1);
            }
        }
        mx1 = fmaxf(mx1, __shfl_xor_sync(0xffffffff, mx1, 1));
        mx1 = fmaxf(mx1, __shfl_xor_sync(0xffffffff, mx1, 2));
        mx2 = fmaxf(mx2, __shfl_xor_sync(0xffffffff, mx2, 1));
        mx2 = fmaxf(mx2, __shfl_xor_sync(0xffffffff, mx2, 2));

        float mn1 = fmaxf(m1, mx1), mn2 = fmaxf(m2, mx2);
        float f1 = __expf(m1 - mn1), f2 = __expf(m2 - mn2);
        float rs1 = 0.f, rs2 = 0.f;
#pragma unroll
        for (int t = 0; t < 8; t++) {
#pragma unroll
            for (int e = 0; e < 2; e++) {
                float p0 = __expf(S[t][e] - mn1);
                float p1 = __expf(S[t][2 + e] - mn2);
                S[t][e] = p0;
                S[t][2 + e] = p1;
                rs1 += p0;
                rs2 += p1;
            }
        }
        rs1 += __shfl_xor_sync(0xffffffff, rs1, 1);
        rs1 += __shfl_xor_sync(0xffffffff, rs1, 2);
        rs2 += __shfl_xor_sync(0xffffffff, rs2, 1);
        rs2 += __shfl_xor_sync(0xffffffff, rs2, 2);
        l1 = l1 * f1 + rs1;
        l2 = l2 * f2 + rs2;
        m1 = mn1; m2 = mn2;
#pragma unroll
        for (int t = 0; t < 16; t++) {
            Oa[t][0] *= f1; Oa[t][1] *= f1;
            Oa[t][2] *= f2; Oa[t][3] *= f2;
        }

        // --- O += P V (3-term split) ---
#pragma unroll
        for (int kc = 0; kc < 4; kc++) {
            uint32_t ph[4], pl[4];
            {
                const float* s0 = S[2 * kc];
                const float* s1 = S[2 * kc + 1];
                float h00 = __bfloat162float(__float2bfloat16(s0[0]));
                float h01 = __bfloat162float(__float2bfloat16(s0[1]));
                float h02 = __bfloat162float(__float2bfloat16(s0[2]));
                float h03 = __bfloat162float(__float2bfloat16(s0[3]));
                float h10 = __bfloat162float(__float2bfloat16(s1[0]));
                float h11 = __bfloat162float(__float2bfloat16(s1[1]));
                float h12 = __bfloat162float(__float2bfloat16(s1[2]));
                float h13 = __bfloat162float(__float2bfloat16(s1[3]));
                ph[0] = pack_bf2(h00, h01);
                ph[1] = pack_bf2(h02, h03);
                ph[2] = pack_bf2(h10, h11);
                ph[3] = pack_bf2(h12, h13);
                pl[0] = pack_bf2(s0[0] - h00, s0[1] - h01);
                pl[1] = pack_bf2(s0[2] - h02, s0[3] - h03);
                pl[2] = pack_bf2(s1[0] - h10, s1[1] - h11);
                pl[3] = pack_bf2(s1[2] - h12, s1[3] - h13);
            }
#pragma unroll
            for (int np = 0; np < 8; np++) {
                uint32_t vh[4], vl[4];
                uint32_t voff = (uint32_t)((kc * 16 + vrow) * FROWB + (np * 16 + vnoff) * 2);
                ldsm_x4_t(vh, sVh + voff);
                ldsm_x4_t(vl, sVl + voff);
                mma16816(Oa[2 * np],     ph, vh);
                mma16816(Oa[2 * np],     ph, vl);
                mma16816(Oa[2 * np],     pl, vh);
                mma16816(Oa[2 * np + 1], ph, vh + 2);
                mma16816(Oa[2 * np + 1], ph, vl + 2);
                mma16816(Oa[2 * np + 1], pl, vh + 2);
            }
        }
    }

    // --- epilogue: write bf16 hi/lo split directly ---
    const float il1 = 1.f / l1, il2 = 1.f / l2;
    const size_t base1 = ((size_t)b * Tn + q0 + w * 16 + (lane >> 2)) * Cn + h * HD;
    const size_t base2 = base1 + 8 * (size_t)Cn;
#pragma unroll
    for (int nt = 0; nt < 16; nt++) {
        int col = nt * 8 + (lane & 3) * 2;
        {
            float y0 = Oa[nt][0] * il1, y1 = Oa[nt][1] * il1;
            __nv_bfloat16 h0 = __float2bfloat16(y0), h1 = __float2bfloat16(y1);
            __nv_bfloat162 hv; hv.x = h0; hv.y = h1;
            __nv_bfloat162 lv = __floats2bfloat162_rn(y0 - __bfloat162float(h0),
                                                      y1 - __bfloat162float(h1));
            *(__nv_bfloat162*)(Yhi + base1 + col) = hv;
            *(__nv_bfloat162*)(Ylo + base1 + col) = lv;
        }
        {
            float y0 = Oa[nt][2] * il2, y1 = Oa[nt][3] * il2;
            __nv_bfloat16 h0 = __float2bfloat16(y0), h1 = __float2bfloat16(y1);
            __nv_bfloat162 hv; hv.x = h0; hv.y = h1;
            __nv_bfloat162 lv = __floats2bfloat162_rn(y0 - __bfloat162float(h0),
                                                      y1 - __bfloat162float(h1));
            *(__nv_bfloat162*)(Yhi + base2 + col) = hv;
            *(__nv_bfloat162*)(Ylo + base2 + col) = lv;
        }
    }
}

// ===========================================================================
// launch
// ===========================================================================
extern "C" void kernel_launch(void* const* d_in, const int* in_sizes, int n_in,
                              void* d_out, int out_size)
{
    const float* x   = (const float*)d_in[0];
    const float* Wq  = (const float*)d_in[1];
    const float* Wk  = (const float*)d_in[2];
    const float* Wv  = (const float*)d_in[3];
    const float* Wo  = (const float*)d_in[4];
    const float* fc  = (const float*)d_in[5];
    const float* fs  = (const float*)d_in[6];
    float* out = (float*)d_out;

    float *Q, *K, *V;
    cudaGetSymbolAddress((void**)&Q, g_Q);
    cudaGetSymbolAddress((void**)&K, g_K);
    cudaGetSymbolAddress((void**)&V, g_V);
    __nv_bfloat16 *Xhi, *Xlo, *Yhi, *Ylo;
    cudaGetSymbolAddress((void**)&Xhi, g_Xhi);
    cudaGetSymbolAddress((void**)&Xlo, g_Xlo);
    cudaGetSymbolAddress((void**)&Yhi, g_Yhi);
    cudaGetSymbolAddress((void**)&Ylo, g_Ylo);
    __nv_bfloat16 *WqTh, *WqTl, *WkTh, *WkTl, *WvTh, *WvTl, *WoTh, *WoTl;
    cudaGetSymbolAddress((void**)&WqTh, g_WqT_hi);
    cudaGetSymbolAddress((void**)&WqTl, g_WqT_lo);
    cudaGetSymbolAddress((void**)&WkTh, g_WkT_hi);
    cudaGetSymbolAddress((void**)&WkTl, g_WkT_lo);
    cudaGetSymbolAddress((void**)&WvTh, g_WvT_hi);
    cudaGetSymbolAddress((void**)&WvTl, g_WvT_lo);
    cudaGetSymbolAddress((void**)&WoTh, g_WoT_hi);
    cudaGetSymbolAddress((void**)&WoTl, g_WoT_lo);

    cudaFuncSetAttribute(gemm3_qkv,
                         cudaFuncAttributeMaxDynamicSharedMemorySize, GEMM_SMEM);
    cudaFuncSetAttribute(gemm3_nn,
                         cudaFuncAttributeMaxDynamicSharedMemorySize, GEMM_SMEM);
    cudaFuncSetAttribute(flash_attn_mma,
                         cudaFuncAttributeMaxDynamicSharedMemorySize, FLASH_SMEM);

    // split x; transpose+split weights
    {
        int tot = Mrows * Cn;
        split_kernel<<<(tot + 255) / 256, 256>>>(x, Xhi, Xlo, tot);
        transpose_split<<<dim3(Cn / 32, Cn / 32), 256>>>(Wq, WqTh, WqTl, Cn, Cn);
        transpose_split<<<dim3(KVC / 32, Cn / 32), 256>>>(Wk, WkTh, WkTl, Cn, KVC);
        transpose_split<<<dim3(KVC / 32, Cn / 32), 256>>>(Wv, WvTh, WvTl, Cn, KVC);
        transpose_split<<<dim3(Cn / 32, Cn / 32), 256>>>(Wo, WoTh, WoTl, Cn, Cn);
    }

    // fused QKV projection on tensor cores
    {
        dim3 g(24, Mrows / 128);      // 24 x 32 = 768 CTAs
        gemm3_qkv<<<g, 256, GEMM_SMEM>>>(Xhi, Xlo, WqTh, WqTl, WkTh, WkTl,
                                         WvTh, WvTl, Q, K, V);
    }

    // RoPE
    {
        int totq = Mrows * NH * (HD / 2);
        rope_kernel<<<(totq + 255) / 256, 256>>>(Q, fc, fs, NH, totq);
        int totk = Mrows * NKV * (HD / 2);
        rope_kernel<<<(totk + 255) / 256, 256>>>(K, fc, fs, NKV, totk);
    }

    // attention (HMMA flash, writes bf16 hi/lo split)
    {
        dim3 g(Tn / 128, NH, Bn);     // 16 x 16 x 2
        flash_attn_mma<<<g, 256, FLASH_SMEM>>>(Q, K, V, Yhi, Ylo);
    }

    // output projection
    {
        dim3 go(Cn / 128, Mrows / 128);   // 16 x 32
        gemm3_nn<<<go, 256, GEMM_SMEM>>>(Yhi, Ylo, WoTh, WoTl, out, Cn, Cn);
    }
}

// round 6
// speedup vs baseline: 2.8764x; 1.0215x over previous
#include <cuda_runtime.h>
#include <cuda_bf16.h>
#include <cstdint>
#include <math.h>

// Problem constants
#define Bn   2
#define Tn   2048
#define Cn   2048
#define NH   16
#define NKV  4
#define HD   128
#define REP  (NH / NKV)          // 4
#define Mrows (Bn * Tn)          // 4096
#define KVC  (NKV * HD)          // 512

// ===========================================================================
// Scratch (device globals; no runtime allocation allowed)
// ===========================================================================
__device__ __nv_bfloat16 g_Xhi[(size_t)Mrows * Cn];
__device__ __nv_bfloat16 g_Xlo[(size_t)Mrows * Cn];
__device__ __nv_bfloat16 g_Qhi[(size_t)Mrows * Cn];
__device__ __nv_bfloat16 g_Qlo[(size_t)Mrows * Cn];
__device__ __nv_bfloat16 g_Khi[(size_t)Mrows * KVC];
__device__ __nv_bfloat16 g_Klo[(size_t)Mrows * KVC];
__device__ __nv_bfloat16 g_Vhi[(size_t)Mrows * KVC];
__device__ __nv_bfloat16 g_Vlo[(size_t)Mrows * KVC];
__device__ __nv_bfloat16 g_Yhi[(size_t)Mrows * Cn];
__device__ __nv_bfloat16 g_Ylo[(size_t)Mrows * Cn];

// transposed weights [N][K] (K-major) split hi/lo
__device__ __nv_bfloat16 g_WqT_hi[(size_t)Cn * Cn];
__device__ __nv_bfloat16 g_WqT_lo[(size_t)Cn * Cn];
__device__ __nv_bfloat16 g_WkT_hi[(size_t)KVC * Cn];
__device__ __nv_bfloat16 g_WkT_lo[(size_t)KVC * Cn];
__device__ __nv_bfloat16 g_WvT_hi[(size_t)KVC * Cn];
__device__ __nv_bfloat16 g_WvT_lo[(size_t)KVC * Cn];
__device__ __nv_bfloat16 g_WoT_hi[(size_t)Cn * Cn];
__device__ __nv_bfloat16 g_WoT_lo[(size_t)Cn * Cn];

// ===========================================================================
// PTX helpers (baseline-PTX-safe: mma.sync + ldmatrix + cp.async only)
// ===========================================================================
__device__ __forceinline__ uint32_t smem_u32(const void* p) {
    uint32_t a;
    asm("{ .reg .u64 t; cvta.to.shared.u64 t, %1; cvt.u32.u64 %0, t; }"
        : "=r"(a) : "l"(p));
    return a;
}
__device__ __forceinline__ void cp_async16(uint32_t dst, const void* src) {
    asm volatile("cp.async.cg.shared.global [%0], [%1], 16;"
                 :: "r"(dst), "l"(src) : "memory");
}
__device__ __forceinline__ void cp_commit() {
    asm volatile("cp.async.commit_group;" ::: "memory");
}
template <int N> __device__ __forceinline__ void cp_wait_group() {
    asm volatile("cp.async.wait_group %0;" :: "n"(N) : "memory");
}
__device__ __forceinline__ void ldsm_x4(uint32_t* r, uint32_t addr) {
    asm volatile("ldmatrix.sync.aligned.m8n8.x4.shared.b16 {%0,%1,%2,%3}, [%4];"
                 : "=r"(r[0]), "=r"(r[1]), "=r"(r[2]), "=r"(r[3]) : "r"(addr));
}
__device__ __forceinline__ void ldsm_x4_t(uint32_t* r, uint32_t addr) {
    asm volatile("ldmatrix.sync.aligned.m8n8.x4.trans.shared.b16 {%0,%1,%2,%3}, [%4];"
                 : "=r"(r[0]), "=r"(r[1]), "=r"(r[2]), "=r"(r[3]) : "r"(addr));
}
__device__ __forceinline__ void ldsm_x2(uint32_t* r, uint32_t addr) {
    asm volatile("ldmatrix.sync.aligned.m8n8.x2.shared.b16 {%0,%1}, [%2];"
                 : "=r"(r[0]), "=r"(r[1]) : "r"(addr));
}
__device__ __forceinline__ void mma16816(float* c, const uint32_t* a, const uint32_t* b) {
    asm volatile(
        "mma.sync.aligned.m16n8k16.row.col.f32.bf16.bf16.f32 "
        "{%0,%1,%2,%3}, {%4,%5,%6,%7}, {%8,%9}, {%0,%1,%2,%3};"
        : "+f"(c[0]), "+f"(c[1]), "+f"(c[2]), "+f"(c[3])
        : "r"(a[0]), "r"(a[1]), "r"(a[2]), "r"(a[3]), "r"(b[0]), "r"(b[1]));
}
__device__ __forceinline__ uint32_t pack_bf2(float a, float b) {
    __nv_bfloat162 t = __floats2bfloat162_rn(a, b);
    return *(uint32_t*)&t;
}

// ===========================================================================
// split: fp32 -> bf16 hi + bf16 lo (same layout)
// ===========================================================================
__global__ void split_kernel(const float* __restrict__ X,
                             __nv_bfloat16* __restrict__ Xhi,
                             __nv_bfloat16* __restrict__ Xlo, int total)
{
    int i = blockIdx.x * blockDim.x + threadIdx.x;
    if (i >= total) return;
    float v = X[i];
    __nv_bfloat16 h = __float2bfloat16(v);
    Xhi[i] = h;
    Xlo[i] = __float2bfloat16(v - __bfloat162float(h));
}

// ===========================================================================
// transpose + split: W[K][N] fp32 -> WT[N][K] bf16 hi/lo
// ===========================================================================
__global__ __launch_bounds__(256)
void transpose_split(const float* __restrict__ W,
                     __nv_bfloat16* __restrict__ Thi,
                     __nv_bfloat16* __restrict__ Tlo, int K, int N)
{
    __shared__ float tile[32][33];
    int tx = threadIdx.x & 31, ty = threadIdx.x >> 5;   // 32 x 8
    int n0 = blockIdx.x * 32, k0 = blockIdx.y * 32;
#pragma unroll
    for (int i = 0; i < 32; i += 8)
        tile[ty + i][tx] = W[(size_t)(k0 + ty + i) * N + n0 + tx];
    __syncthreads();
#pragma unroll
    for (int i = 0; i < 32; i += 8) {
        int n = n0 + ty + i;
        int k = k0 + tx;
        float v = tile[tx][ty + i];
        __nv_bfloat16 h = __float2bfloat16(v);
        Thi[(size_t)n * K + k] = h;
        Tlo[(size_t)n * K + k] = __float2bfloat16(v - __bfloat162float(h));
    }
}

// ===========================================================================
// HMMA GEMM core: C = Ahi@BhT + Ahi@BlT + Alo@BhT (fp32 acc)
// 128x128 tile, BK=32, 256 threads, 3-stage cp.async pipeline.
// MODE 0: store fp32 C. MODE 1: store bf16 hi/lo split. MODE 2: rope + split.
// ===========================================================================
#define TBK 32
#define RS  40
#define MAT_BYTES (128 * RS * 2)          // 10240
#define STG_BYTES (4 * MAT_BYTES)         // 40960
#define GEMM_SMEM (3 * STG_BYTES)         // 122880

__device__ __forceinline__ void gemm3_load(
    uint32_t st,
    const __nv_bfloat16* __restrict__ Ah, const __nv_bfloat16* __restrict__ Al,
    const __nv_bfloat16* __restrict__ Bh, const __nv_bfloat16* __restrict__ Bl,
    int K, int c, int tid)
{
#pragma unroll
    for (int j = 0; j < 2; j++) {
        int idx = tid + j * 256;
        int r = idx >> 2, seg = idx & 3;
        uint32_t so = (uint32_t)(r * (RS * 2) + seg * 16);
        size_t go = (size_t)r * K + (size_t)c * TBK + seg * 8;
        cp_async16(st + so,                 Ah + go);
        cp_async16(st + MAT_BYTES + so,     Al + go);
        cp_async16(st + 2 * MAT_BYTES + so, Bh + go);
        cp_async16(st + 3 * MAT_BYTES + so, Bl + go);
    }
    cp_commit();
}

template <int MODE>
__device__ __forceinline__ void gemm3_core(
    const __nv_bfloat16* __restrict__ Ah, const __nv_bfloat16* __restrict__ Al,
    const __nv_bfloat16* __restrict__ Bh, const __nv_bfloat16* __restrict__ Bl,
    float* __restrict__ Cf,
    __nv_bfloat16* __restrict__ Chi, __nv_bfloat16* __restrict__ Clo,
    int ldc, int K,
    const float* __restrict__ fcos, const float* __restrict__ fsin, int rowg0)
{
    extern __shared__ char smem[];
    const uint32_t sb = smem_u32(smem);
    const int tid = threadIdx.x;
    const int lane = tid & 31;
    const int wid = tid >> 5;
    const int wm = wid & 1;
    const int wn = wid >> 1;

    float acc[4][4][4];
#pragma unroll
    for (int i = 0; i < 4; i++)
#pragma unroll
        for (int j = 0; j < 4; j++)
#pragma unroll
            for (int q = 0; q < 4; q++) acc[i][j][q] = 0.f;

    const int a_row_in = (lane & 15);
    const int a_koff   = (lane >> 4) * 8;
    const int b_row_in = (lane & 7);
    const int b_koff   = ((lane >> 3) & 1) * 8;

    const int NC = K / TBK;
    gemm3_load(sb,             Ah, Al, Bh, Bl, K, 0, tid);
    gemm3_load(sb + STG_BYTES, Ah, Al, Bh, Bl, K, 1, tid);

    int snext = 2;
    for (int c = 0; c < NC; c++) {
        const int scur = c % 3;
        if (c + 2 < NC) { cp_wait_group<1>(); } else { cp_wait_group<0>(); }
        __syncthreads();
        if (c + 2 < NC) {
            gemm3_load(sb + snext * STG_BYTES, Ah, Al, Bh, Bl, K, c + 2, tid);
            snext = (snext + 1) % 3;
        }

        const uint32_t st = sb + scur * STG_BYTES;
#pragma unroll
        for (int kk = 0; kk < 2; kk++) {
            const int k0 = kk * 16;
            uint32_t ah[4][4], al[4][4];
#pragma unroll
            for (int mt = 0; mt < 4; mt++) {
                int row = wm * 64 + mt * 16 + a_row_in;
                uint32_t off = (uint32_t)(row * (RS * 2) + (k0 + a_koff) * 2);
                ldsm_x4(ah[mt], st + off);
                ldsm_x4(al[mt], st + MAT_BYTES + off);
            }
            uint32_t bh[4][2], bl[4][2];
#pragma unroll
            for (int nt = 0; nt < 4; nt++) {
                int rowb = wn * 32 + nt * 8 + b_row_in;
                uint32_t off = (uint32_t)(rowb * (RS * 2) + (k0 + b_koff) * 2);
                ldsm_x2(bh[nt], st + 2 * MAT_BYTES + off);
                ldsm_x2(bl[nt], st + 3 * MAT_BYTES + off);
            }
#pragma unroll
            for (int mt = 0; mt < 4; mt++)
#pragma unroll
                for (int nt = 0; nt < 4; nt++) {
                    mma16816(acc[mt][nt], ah[mt], bh[nt]);
                    mma16816(acc[mt][nt], ah[mt], bl[nt]);
                    mma16816(acc[mt][nt], al[mt], bh[nt]);
                }
        }
    }

#pragma unroll
    for (int mt = 0; mt < 4; mt++) {
#pragma unroll
        for (int nt = 0; nt < 4; nt++) {
            int row = wm * 64 + mt * 16 + (lane >> 2);
            int col = wn * 32 + nt * 8 + (lane & 3) * 2;
            float v0 = acc[mt][nt][0], v1 = acc[mt][nt][1];
            float v2 = acc[mt][nt][2], v3 = acc[mt][nt][3];
            if (MODE == 0) {
                *(float2*)(Cf + (size_t)row * ldc + col) = make_float2(v0, v1);
                *(float2*)(Cf + (size_t)(row + 8) * ldc + col) = make_float2(v2, v3);
            } else {
                if (MODE == 2) {
                    int i = (col & 127) >> 1;
                    int t1 = (rowg0 + row) & (Tn - 1);
                    int t2 = (rowg0 + row + 8) & (Tn - 1);
                    float c1 = fcos[t1 * 64 + i], s1 = fsin[t1 * 64 + i];
                    float c2 = fcos[t2 * 64 + i], s2 = fsin[t2 * 64 + i];
                    float re = v0, im = v1;
                    v0 = re * c1 - im * s1; v1 = re * s1 + im * c1;
                    re = v2; im = v3;
                    v2 = re * c2 - im * s2; v3 = re * s2 + im * c2;
                }
                __nv_bfloat16 h0 = __float2bfloat16(v0), h1 = __float2bfloat16(v1);
                __nv_bfloat16 h2 = __float2bfloat16(v2), h3 = __float2bfloat16(v3);
                __nv_bfloat162 hA; hA.x = h0; hA.y = h1;
                __nv_bfloat162 hB; hB.x = h2; hB.y = h3;
                __nv_bfloat162 lA = __floats2bfloat162_rn(v0 - __bfloat162float(h0),
                                                          v1 - __bfloat162float(h1));
                __nv_bfloat162 lB = __floats2bfloat162_rn(v2 - __bfloat162float(h2),
                                                          v3 - __bfloat162float(h3));
                *(__nv_bfloat162*)(Chi + (size_t)row * ldc + col) = hA;
                *(__nv_bfloat162*)(Clo + (size_t)row * ldc + col) = lA;
                *(__nv_bfloat162*)(Chi + (size_t)(row + 8) * ldc + col) = hB;
                *(__nv_bfloat162*)(Clo + (size_t)(row + 8) * ldc + col) = lB;
            }
        }
    }
}

// Fused QKV projection: grid (24, 32). Col tiles 0-15 -> Q, 16-19 -> K, 20-23 -> V
// Q/K epilogue: rope + bf16 split. V epilogue: bf16 split.
__global__ __launch_bounds__(256)
void gemm3_qkv(const __nv_bfloat16* __restrict__ Xh, const __nv_bfloat16* __restrict__ Xl,
               const __nv_bfloat16* __restrict__ Wqh, const __nv_bfloat16* __restrict__ Wql,
               const __nv_bfloat16* __restrict__ Wkh, const __nv_bfloat16* __restrict__ Wkl,
               const __nv_bfloat16* __restrict__ Wvh, const __nv_bfloat16* __restrict__ Wvl,
               __nv_bfloat16* __restrict__ Qhi, __nv_bfloat16* __restrict__ Qlo,
               __nv_bfloat16* __restrict__ Khi, __nv_bfloat16* __restrict__ Klo,
               __nv_bfloat16* __restrict__ Vhi, __nv_bfloat16* __restrict__ Vlo,
               const float* __restrict__ fcos, const float* __restrict__ fsin)
{
    const int ct = blockIdx.x;
    const int row0 = blockIdx.y * 128;
    const __nv_bfloat16* Xhp = Xh + (size_t)row0 * Cn;
    const __nv_bfloat16* Xlp = Xl + (size_t)row0 * Cn;
    if (ct < 16) {
        int c0 = ct * 128;
        gemm3_core<2>(Xhp, Xlp, Wqh + (size_t)c0 * Cn, Wql + (size_t)c0 * Cn,
                      nullptr,
                      Qhi + (size_t)row0 * Cn + c0, Qlo + (size_t)row0 * Cn + c0,
                      Cn, Cn, fcos, fsin, row0);
    } else if (ct < 20) {
        int c0 = (ct - 16) * 128;
        gemm3_core<2>(Xhp, Xlp, Wkh + (size_t)c0 * Cn, Wkl + (size_t)c0 * Cn,
                      nullptr,
                      Khi + (size_t)row0 * KVC + c0, Klo + (size_t)row0 * KVC + c0,
                      KVC, Cn, fcos, fsin, row0);
    } else {
        int c0 = (ct - 20) * 128;
        gemm3_core<1>(Xhp, Xlp, Wvh + (size_t)c0 * Cn, Wvl + (size_t)c0 * Cn,
                      nullptr,
                      Vhi + (size_t)row0 * KVC + c0, Vlo + (size_t)row0 * KVC + c0,
                      KVC, Cn, nullptr, nullptr, row0);
    }
}

// Generic NN GEMM (output projection, fp32 out)
__global__ __launch_bounds__(256)
void gemm3_nn(const __nv_bfloat16* __restrict__ Ah, const __nv_bfloat16* __restrict__ Al,
              const __nv_bfloat16* __restrict__ Bh, const __nv_bfloat16* __restrict__ Bl,
              float* __restrict__ C, int N, int K)
{
    const int row0 = blockIdx.y * 128;
    const int col0 = blockIdx.x * 128;
    gemm3_core<0>(Ah + (size_t)row0 * K, Al + (size_t)row0 * K,
                  Bh + (size_t)col0 * K, Bl + (size_t)col0 * K,
                  C + (size_t)row0 * N + col0, nullptr, nullptr,
                  N, K, nullptr, nullptr, 0);
}

// ===========================================================================
// Flash attention on HMMA (bf16 3-term split, causal, GQA)
// Inputs are pre-split bf16 hi/lo (rope already applied by QKV GEMM epilogue).
// CTA: (128-query block, head, batch). 256 threads / 8 warps.
// K/V double-buffered via cp.async. Writes bf16 hi/lo split output.
// ===========================================================================
#define FST 136
#define FROWB (FST * 2)              // 272 bytes per row
#define QTILE_B (128 * FROWB)        // 34816
#define KTILE_B (64 * FROWB)         // 17408
#define KVSTG_B (4 * KTILE_B)        // 69632 per stage
#define FLASH_SMEM (2 * QTILE_B + 2 * KVSTG_B)   // 208896

__device__ __forceinline__ void f_load_kv(
    uint32_t skv,
    const __nv_bfloat16* __restrict__ Kh, const __nv_bfloat16* __restrict__ Kl,
    const __nv_bfloat16* __restrict__ Vh, const __nv_bfloat16* __restrict__ Vl,
    int k0g, int tid)
{
#pragma unroll
    for (int i = 0; i < 4; i++) {
        int idx = tid + i * 256;
        int r = idx >> 4, seg = idx & 15;
        uint32_t off = (uint32_t)(r * FROWB + seg * 16);
        size_t go = (size_t)(k0g + r) * KVC + seg * 8;
        cp_async16(skv + off,               Kh + go);
        cp_async16(skv + KTILE_B + off,     Kl + go);
        cp_async16(skv + 2 * KTILE_B + off, Vh + go);
        cp_async16(skv + 3 * KTILE_B + off, Vl + go);
    }
    cp_commit();
}

__global__ __launch_bounds__(256)
void flash_attn_mma(const __nv_bfloat16* __restrict__ Qhg, const __nv_bfloat16* __restrict__ Qlg,
                    const __nv_bfloat16* __restrict__ Khg, const __nv_bfloat16* __restrict__ Klg,
                    const __nv_bfloat16* __restrict__ Vhg, const __nv_bfloat16* __restrict__ Vlg,
                    __nv_bfloat16* __restrict__ Yhi, __nv_bfloat16* __restrict__ Ylo)
{
    extern __shared__ char smc[];
    const uint32_t sb  = smem_u32(smc);
    const uint32_t sQh = sb;
    const uint32_t sQl = sb + QTILE_B;
    const uint32_t sKV0 = sb + 2 * QTILE_B;

    const int tid = threadIdx.x;
    const int lane = tid & 31;
    const int w = tid >> 5;                          // 0..7
    const int bq = gridDim.x - 1 - blockIdx.x;       // heavy blocks first
    const int h = blockIdx.y, b = blockIdx.z;
    const int q0 = bq * 128;
    const int kvh = h / REP;

    const __nv_bfloat16* Qh = Qhg + ((size_t)b * Tn + q0) * Cn + h * HD;
    const __nv_bfloat16* Ql = Qlg + ((size_t)b * Tn + q0) * Cn + h * HD;
    const __nv_bfloat16* Kh = Khg + (size_t)b * Tn * KVC + kvh * HD;
    const __nv_bfloat16* Kl = Klg + (size_t)b * Tn * KVC + kvh * HD;
    const __nv_bfloat16* Vh = Vhg + (size_t)b * Tn * KVC + kvh * HD;
    const __nv_bfloat16* Vl = Vlg + (size_t)b * Tn * KVC + kvh * HD;

    // --- Q tile loads (cp.async) ---
#pragma unroll
    for (int i = 0; i < 8; i++) {
        int idx = tid + i * 256;
        int r = idx >> 4, seg = idx & 15;
        uint32_t off = (uint32_t)(r * FROWB + seg * 16);
        size_t go = (size_t)r * Cn + seg * 8;
        cp_async16(sQh + off, Qh + go);
        cp_async16(sQl + off, Ql + go);
    }
    // KV tile 0 into stage 0, same group as Q
    f_load_kv(sKV0, Kh, Kl, Vh, Vl, 0, tid);

    // fragment addressing
    const int arow = lane & 15;
    const int akoff = (lane >> 4) * 8;
    const int brow = (lane & 7) + ((lane >> 4) * 8);
    const int bkoff = ((lane >> 3) & 1) * 8;
    const int vrow = lane & 15;
    const int vnoff = (lane >> 4) * 8;

    float Oa[16][4];
#pragma unroll
    for (int i = 0; i < 16; i++)
#pragma unroll
        for (int q = 0; q < 4; q++) Oa[i][q] = 0.f;

    float m1 = -1e30f, m2 = -1e30f, l1 = 0.f, l2 = 0.f;
    const float sscale = 0.08838834764831845f;
    const int rg1 = q0 + w * 16 + (lane >> 2);
    const int rg2 = rg1 + 8;

    const int nkb = 2 * bq + 2;
    for (int j = 0; j < nkb; j++) {
        const int k0g = j * 64;
        const uint32_t skv = sKV0 + (j & 1) * KVSTG_B;
        if (j + 1 < nkb) {
            f_load_kv(sKV0 + ((j + 1) & 1) * KVSTG_B, Kh, Kl, Vh, Vl,
                      (j + 1) * 64, tid);
            cp_wait_group<1>();
        } else {
            cp_wait_group<0>();
        }
        __syncthreads();

        const uint32_t sKh = skv;
        const uint32_t sKl = skv + KTILE_B;
        const uint32_t sVh = skv + 2 * KTILE_B;
        const uint32_t sVl = skv + 3 * KTILE_B;

        // --- S = Q K^T (3-term split) ---
        float S[8][4];
#pragma unroll
        for (int t = 0; t < 8; t++)
#pragma unroll
            for (int q = 0; q < 4; q++) S[t][q] = 0.f;

#pragma unroll
        for (int kc = 0; kc < 8; kc++) {
            uint32_t ah[4], al[4];
            uint32_t aoff = (uint32_t)((w * 16 + arow) * FROWB + (kc * 16 + akoff) * 2);
            ldsm_x4(ah, sQh + aoff);
            ldsm_x4(al, sQl + aoff);
#pragma unroll
            for (int np = 0; np < 4; np++) {
                uint32_t bh[4], bl[4];
                uint32_t boff = (uint32_t)((np * 16 + brow) * FROWB + (kc * 16 + bkoff) * 2);
                ldsm_x4(bh, sKh + boff);
                ldsm_x4(bl, sKl + boff);
                mma16816(S[2 * np],     ah, bh);
                mma16816(S[2 * np],     ah, bl);
                mma16816(S[2 * np],     al, bh);
                mma16816(S[2 * np + 1], ah, bh + 2);
                mma16816(S[2 * np + 1], ah, bl + 2);
                mma16816(S[2 * np + 1], al, bh + 2);
            }
        }

        // --- mask + scale + online softmax ---
        const bool diag = (k0g + 63 > q0 + w * 16);
        float mx1 = -1e30f, mx2 = -1e30f;
#pragma unroll
        for (int t = 0; t < 8; t++) {
            int cg = k0g + t * 8 + (lane & 3) * 2;
#pragma unroll
            for (int e = 0; e < 2; e++) {
                float s0 = S[t][e] * sscale;
                float s1 = S[t][2 + e] * sscale;
                if (diag) {
                    if (cg + e > rg1) s0 = -1e30f;
                    if (cg + e > rg2) s1 = -1e30f;
                }
                S[t][e] = s0;
                S[t][2 + e] = s1;
                mx1 = fmaxf(mx1, s0);
                mx2 = fmaxf(mx2, s1);
            }
        }
        mx1 = fmaxf(mx1, __shfl_xor_sync(0xffffffff, mx1, 1));
        mx1 = fmaxf(mx1, __shfl_xor_sync(0xffffffff, mx1, 2));
        mx2 = fmaxf(mx2, __shfl_xor_sync(0xffffffff, mx2, 1));
        mx2 = fmaxf(mx2, __shfl_xor_sync(0xffffffff, mx2, 2));

        float mn1 = fmaxf(m1, mx1), mn2 = fmaxf(m2, mx2);
        float f1 = __expf(m1 - mn1), f2 = __expf(m2 - mn2);
        float rs1 = 0.f, rs2 = 0.f;
#pragma unroll
        for (int t = 0; t < 8; t++) {
#pragma unroll
            for (int e = 0; e < 2; e++) {
                float p0 = __expf(S[t][e] - mn1);
                float p1 = __expf(S[t][2 + e] - mn2);
                S[t][e] = p0;
                S[t][2 + e] = p1;
                rs1 += p0;
                rs2 += p1;
            }
        }
        rs1 += __shfl_xor_sync(0xffffffff, rs1, 1);
        rs1 += __shfl_xor_sync(0xffffffff, rs1, 2);
        rs2 += __shfl_xor_sync(0xffffffff, rs2, 1);
        rs2 += __shfl_xor_sync(0xffffffff, rs2, 2);
        l1 = l1 * f1 + rs1;
        l2 = l2 * f2 + rs2;
        m1 = mn1; m2 = mn2;
#pragma unroll
        for (int t = 0; t < 16; t++) {
            Oa[t][0] *= f1; Oa[t][1] *= f1;
            Oa[t][2] *= f2; Oa[t][3] *= f2;
        }

        // --- O += P V (3-term split) ---
#pragma unroll
        for (int kc = 0; kc < 4; kc++) {
            uint32_t ph[4], pl[4];
            {
                const float* s0 = S[2 * kc];
                const float* s1 = S[2 * kc + 1];
                float h00 = __bfloat162float(__float2bfloat16(s0[0]));
                float h01 = __bfloat162float(__float2bfloat16(s0[1]));
                float h02 = __bfloat162float(__float2bfloat16(s0[2]));
                float h03 = __bfloat162float(__float2bfloat16(s0[3]));
                float h10 = __bfloat162float(__float2bfloat16(s1[0]));
                float h11 = __bfloat162float(__float2bfloat16(s1[1]));
                float h12 = __bfloat162float(__float2bfloat16(s1[2]));
                float h13 = __bfloat162float(__float2bfloat16(s1[3]));
                ph[0] = pack_bf2(h00, h01);
                ph[1] = pack_bf2(h02, h03);
                ph[2] = pack_bf2(h10, h11);
                ph[3] = pack_bf2(h12, h13);
                pl[0] = pack_bf2(s0[0] - h00, s0[1] - h01);
                pl[1] = pack_bf2(s0[2] - h02, s0[3] - h03);
                pl[2] = pack_bf2(s1[0] - h10, s1[1] - h11);
                pl[3] = pack_bf2(s1[2] - h12, s1[3] - h13);
            }
#pragma unroll
            for (int np = 0; np < 8; np++) {
                uint32_t vh[4], vl[4];
                uint32_t voff = (uint32_t)((kc * 16 + vrow) * FROWB + (np * 16 + vnoff) * 2);
                ldsm_x4_t(vh, sVh + voff);
                ldsm_x4_t(vl, sVl + voff);
                mma16816(Oa[2 * np],     ph, vh);
                mma16816(Oa[2 * np],     ph, vl);
                mma16816(Oa[2 * np],     pl, vh);
                mma16816(Oa[2 * np + 1], ph, vh + 2);
                mma16816(Oa[2 * np + 1], ph, vl + 2);
                mma16816(Oa[2 * np + 1], pl, vh + 2);
            }
        }
        __syncthreads();
    }

    // --- epilogue: write bf16 hi/lo split directly ---
    const float il1 = 1.f / l1, il2 = 1.f / l2;
    const size_t base1 = ((size_t)b * Tn + q0 + w * 16 + (lane >> 2)) * Cn + h * HD;
    const size_t base2 = base1 + 8 * (size_t)Cn;
#pragma unroll
    for (int nt = 0; nt < 16; nt++) {
        int col = nt * 8 + (lane & 3) * 2;
        {
            float y0 = Oa[nt][0] * il1, y1 = Oa[nt][1] * il1;
            __nv_bfloat16 h0 = __float2bfloat16(y0), h1 = __float2bfloat16(y1);
            __nv_bfloat162 hv; hv.x = h0; hv.y = h1;
            __nv_bfloat162 lv = __floats2bfloat162_rn(y0 - __bfloat162float(h0),
                                                      y1 - __bfloat162float(h1));
            *(__nv_bfloat162*)(Yhi + base1 + col) = hv;
            *(__nv_bfloat162*)(Ylo + base1 + col) = lv;
        }
        {
            float y0 = Oa[nt][2] * il2, y1 = Oa[nt][3] * il2;
            __nv_bfloat16 h0 = __float2bfloat16(y0), h1 = __float2bfloat16(y1);
            __nv_bfloat162 hv; hv.x = h0; hv.y = h1;
            __nv_bfloat162 lv = __floats2bfloat162_rn(y0 - __bfloat162float(h0),
                                                      y1 - __bfloat162float(h1));
            *(__nv_bfloat162*)(Yhi + base2 + col) = hv;
            *(__nv_bfloat162*)(Ylo + base2 + col) = lv;
        }
    }
}

// ===========================================================================
// launch
// ===========================================================================
extern "C" void kernel_launch(void* const* d_in, const int* in_sizes, int n_in,
                              void* d_out, int out_size)
{
    const float* x   = (const float*)d_in[0];
    const float* Wq  = (const float*)d_in[1];
    const float* Wk  = (const float*)d_in[2];
    const float* Wv  = (const float*)d_in[3];
    const float* Wo  = (const float*)d_in[4];
    const float* fc  = (const float*)d_in[5];
    const float* fs  = (const float*)d_in[6];
    float* out = (float*)d_out;

    __nv_bfloat16 *Xhi, *Xlo, *Qhi, *Qlo, *Khi, *Klo, *Vhi, *Vlo, *Yhi, *Ylo;
    cudaGetSymbolAddress((void**)&Xhi, g_Xhi);
    cudaGetSymbolAddress((void**)&Xlo, g_Xlo);
    cudaGetSymbolAddress((void**)&Qhi, g_Qhi);
    cudaGetSymbolAddress((void**)&Qlo, g_Qlo);
    cudaGetSymbolAddress((void**)&Khi, g_Khi);
    cudaGetSymbolAddress((void**)&Klo, g_Klo);
    cudaGetSymbolAddress((void**)&Vhi, g_Vhi);
    cudaGetSymbolAddress((void**)&Vlo, g_Vlo);
    cudaGetSymbolAddress((void**)&Yhi, g_Yhi);
    cudaGetSymbolAddress((void**)&Ylo, g_Ylo);
    __nv_bfloat16 *WqTh, *WqTl, *WkTh, *WkTl, *WvTh, *WvTl, *WoTh, *WoTl;
    cudaGetSymbolAddress((void**)&WqTh, g_WqT_hi);
    cudaGetSymbolAddress((void**)&WqTl, g_WqT_lo);
    cudaGetSymbolAddress((void**)&WkTh, g_WkT_hi);
    cudaGetSymbolAddress((void**)&WkTl, g_WkT_lo);
    cudaGetSymbolAddress((void**)&WvTh, g_WvT_hi);
    cudaGetSymbolAddress((void**)&WvTl, g_WvT_lo);
    cudaGetSymbolAddress((void**)&WoTh, g_WoT_hi);
    cudaGetSymbolAddress((void**)&WoTl, g_WoT_lo);

    cudaFuncSetAttribute(gemm3_qkv,
                         cudaFuncAttributeMaxDynamicSharedMemorySize, GEMM_SMEM);
    cudaFuncSetAttribute(gemm3_nn,
                         cudaFuncAttributeMaxDynamicSharedMemorySize, GEMM_SMEM);
    cudaFuncSetAttribute(flash_attn_mma,
                         cudaFuncAttributeMaxDynamicSharedMemorySize, FLASH_SMEM);

    // split x; transpose+split weights
    {
        int tot = Mrows * Cn;
        split_kernel<<<(tot + 255) / 256, 256>>>(x, Xhi, Xlo, tot);
        transpose_split<<<dim3(Cn / 32, Cn / 32), 256>>>(Wq, WqTh, WqTl, Cn, Cn);
        transpose_split<<<dim3(KVC / 32, Cn / 32), 256>>>(Wk, WkTh, WkTl, Cn, KVC);
        transpose_split<<<dim3(KVC / 32, Cn / 32), 256>>>(Wv, WvTh, WvTl, Cn, KVC);
        transpose_split<<<dim3(Cn / 32, Cn / 32), 256>>>(Wo, WoTh, WoTl, Cn, Cn);
    }

    // fused QKV projection (rope + bf16 split fused into epilogue)
    {
        dim3 g(24, Mrows / 128);      // 24 x 32 = 768 CTAs
        gemm3_qkv<<<g, 256, GEMM_SMEM>>>(Xhi, Xlo, WqTh, WqTl, WkTh, WkTl,
                                         WvTh, WvTl, Qhi, Qlo, Khi, Klo,
                                         Vhi, Vlo, fc, fs);
    }

    // attention (HMMA flash, bf16 split in/out, K/V double-buffered)
    {
        dim3 g(Tn / 128, NH, Bn);     // 16 x 16 x 2
        flash_attn_mma<<<g, 256, FLASH_SMEM>>>(Qhi, Qlo, Khi, Klo, Vhi, Vlo,
                                               Yhi, Ylo);
    }

    // output projection
    {
        dim3 go(Cn / 128, Mrows / 128);   // 16 x 32
        gemm3_nn<<<go, 256, GEMM_SMEM>>>(Yhi, Ylo, WoTh, WoTl, out, Cn, Cn);
    }
}

// round 7
// speedup vs baseline: 6.4514x; 2.2429x over previous
#include <cuda_runtime.h>
#include <cuda_fp16.h>
#include <cstdint>
#include <math.h>

// Problem constants
#define Bn   2
#define Tn   2048
#define Cn   2048
#define NH   16
#define NKV  4
#define HD   128
#define REP  (NH / NKV)          // 4
#define Mrows (Bn * Tn)          // 4096
#define KVC  (NKV * HD)          // 512

// ===========================================================================
// Scratch (device globals; no runtime allocation allowed)
// ===========================================================================
__device__ __half g_X16[(size_t)Mrows * Cn];
__device__ __half g_Q16[(size_t)Mrows * Cn];
__device__ __half g_K16[(size_t)Mrows * KVC];
__device__ __half g_V16[(size_t)Mrows * KVC];
__device__ __half g_Y16[(size_t)Mrows * Cn];

// transposed weights [N][K] (K-major) fp16
__device__ __half g_WqT[(size_t)Cn * Cn];
__device__ __half g_WkT[(size_t)KVC * Cn];
__device__ __half g_WvT[(size_t)KVC * Cn];
__device__ __half g_WoT[(size_t)Cn * Cn];

// ===========================================================================
// PTX helpers (baseline-PTX-safe: mma.sync + ldmatrix + cp.async only)
// ===========================================================================
__device__ __forceinline__ uint32_t smem_u32(const void* p) {
    uint32_t a;
    asm("{ .reg .u64 t; cvta.to.shared.u64 t, %1; cvt.u32.u64 %0, t; }"
        : "=r"(a) : "l"(p));
    return a;
}
__device__ __forceinline__ void cp_async16(uint32_t dst, const void* src) {
    asm volatile("cp.async.cg.shared.global [%0], [%1], 16;"
                 :: "r"(dst), "l"(src) : "memory");
}
__device__ __forceinline__ void cp_commit() {
    asm volatile("cp.async.commit_group;" ::: "memory");
}
template <int N> __device__ __forceinline__ void cp_wait_group() {
    asm volatile("cp.async.wait_group %0;" :: "n"(N) : "memory");
}
__device__ __forceinline__ void ldsm_x4(uint32_t* r, uint32_t addr) {
    asm volatile("ldmatrix.sync.aligned.m8n8.x4.shared.b16 {%0,%1,%2,%3}, [%4];"
                 : "=r"(r[0]), "=r"(r[1]), "=r"(r[2]), "=r"(r[3]) : "r"(addr));
}
__device__ __forceinline__ void ldsm_x4_t(uint32_t* r, uint32_t addr) {
    asm volatile("ldmatrix.sync.aligned.m8n8.x4.trans.shared.b16 {%0,%1,%2,%3}, [%4];"
                 : "=r"(r[0]), "=r"(r[1]), "=r"(r[2]), "=r"(r[3]) : "r"(addr));
}
__device__ __forceinline__ void ldsm_x2(uint32_t* r, uint32_t addr) {
    asm volatile("ldmatrix.sync.aligned.m8n8.x2.shared.b16 {%0,%1}, [%2];"
                 : "=r"(r[0]), "=r"(r[1]) : "r"(addr));
}
// fp16 in, fp32 accumulate
__device__ __forceinline__ void mma16816(float* c, const uint32_t* a, const uint32_t* b) {
    asm volatile(
        "mma.sync.aligned.m16n8k16.row.col.f32.f16.f16.f32 "
        "{%0,%1,%2,%3}, {%4,%5,%6,%7}, {%8,%9}, {%0,%1,%2,%3};"
        : "+f"(c[0]), "+f"(c[1]), "+f"(c[2]), "+f"(c[3])
        : "r"(a[0]), "r"(a[1]), "r"(a[2]), "r"(a[3]), "r"(b[0]), "r"(b[1]));
}
__device__ __forceinline__ uint32_t pack_h2(float a, float b) {
    __half2 t = __floats2half2_rn(a, b);
    return *(uint32_t*)&t;
}

// ===========================================================================
// convert: fp32 -> fp16
// ===========================================================================
__global__ void convert_kernel(const float* __restrict__ X,
                               __half* __restrict__ X16, int total4)
{
    int i = blockIdx.x * blockDim.x + threadIdx.x;
    if (i >= total4) return;
    float4 v = ((const float4*)X)[i];
    __half2 a = __floats2half2_rn(v.x, v.y);
    __half2 b = __floats2half2_rn(v.z, v.w);
    ((__half2*)X16)[2 * i]     = a;
    ((__half2*)X16)[2 * i + 1] = b;
}

// ===========================================================================
// transpose + convert: W[K][N] fp32 -> WT[N][K] fp16
// ===========================================================================
__global__ __launch_bounds__(256)
void transpose_convert(const float* __restrict__ W,
                       __half* __restrict__ T, int K, int N)
{
    __shared__ float tile[32][33];
    int tx = threadIdx.x & 31, ty = threadIdx.x >> 5;   // 32 x 8
    int n0 = blockIdx.x * 32, k0 = blockIdx.y * 32;
#pragma unroll
    for (int i = 0; i < 32; i += 8)
        tile[ty + i][tx] = W[(size_t)(k0 + ty + i) * N + n0 + tx];
    __syncthreads();
#pragma unroll
    for (int i = 0; i < 32; i += 8) {
        int n = n0 + ty + i;
        int k = k0 + tx;
        T[(size_t)n * K + k] = __float2half(tile[tx][ty + i]);
    }
}

// ===========================================================================
// fp16 HMMA GEMM core: C[M,N] = A @ B^T (fp32 acc)
// A: [M,K] fp16 row-major. Bt: [N,K] fp16 row-major.
// 128x128 tile, BK=32, 256 threads, 3-stage cp.async pipeline.
// MODE 0: fp32 C out. MODE 1: fp16 out. MODE 2: rope + fp16 out.
// ===========================================================================
#define TBK 32
#define RS  40
#define MAT_BYTES (128 * RS * 2)          // 10240
#define STG_BYTES (2 * MAT_BYTES)         // 20480
#define GEMM_SMEM (3 * STG_BYTES)         // 61440  -> 2 CTAs/SM

__device__ __forceinline__ void gemm_load(
    uint32_t st,
    const __half* __restrict__ A, const __half* __restrict__ B,
    int K, int c, int tid)
{
#pragma unroll
    for (int j = 0; j < 2; j++) {
        int idx = tid + j * 256;
        int r = idx >> 2, seg = idx & 3;
        uint32_t so = (uint32_t)(r * (RS * 2) + seg * 16);
        size_t go = (size_t)r * K + (size_t)c * TBK + seg * 8;
        cp_async16(st + so,             A + go);
        cp_async16(st + MAT_BYTES + so, B + go);
    }
    cp_commit();
}

template <int MODE>
__device__ __forceinline__ void gemm_core(
    const __half* __restrict__ A, const __half* __restrict__ B,
    float* __restrict__ Cf, __half* __restrict__ Ch,
    int ldc, int K,
    const float* __restrict__ fcos, const float* __restrict__ fsin, int rowg0)
{
    extern __shared__ char smem[];
    const uint32_t sb = smem_u32(smem);
    const int tid = threadIdx.x;
    const int lane = tid & 31;
    const int wid = tid >> 5;
    const int wm = wid & 1;
    const int wn = wid >> 1;

    float acc[4][4][4];
#pragma unroll
    for (int i = 0; i < 4; i++)
#pragma unroll
        for (int j = 0; j < 4; j++)
#pragma unroll
            for (int q = 0; q < 4; q++) acc[i][j][q] = 0.f;

    const int a_row_in = (lane & 15);
    const int a_koff   = (lane >> 4) * 8;
    const int b_row_in = (lane & 7);
    const int b_koff   = ((lane >> 3) & 1) * 8;

    const int NC = K / TBK;
    gemm_load(sb,             A, B, K, 0, tid);
    gemm_load(sb + STG_BYTES, A, B, K, 1, tid);

    int snext = 2;
    for (int c = 0; c < NC; c++) {
        const int scur = c % 3;
        if (c + 2 < NC) { cp_wait_group<1>(); } else { cp_wait_group<0>(); }
        __syncthreads();
        if (c + 2 < NC) {
            gemm_load(sb + snext * STG_BYTES, A, B, K, c + 2, tid);
            snext = (snext + 1) % 3;
        }

        const uint32_t st = sb + scur * STG_BYTES;
#pragma unroll
        for (int kk = 0; kk < 2; kk++) {
            const int k0 = kk * 16;
            uint32_t af[4][4];
#pragma unroll
            for (int mt = 0; mt < 4; mt++) {
                int row = wm * 64 + mt * 16 + a_row_in;
                ldsm_x4(af[mt], st + (uint32_t)(row * (RS * 2) + (k0 + a_koff) * 2));
            }
            uint32_t bf[4][2];
#pragma unroll
            for (int nt = 0; nt < 4; nt++) {
                int rowb = wn * 32 + nt * 8 + b_row_in;
                ldsm_x2(bf[nt], st + MAT_BYTES
                        + (uint32_t)(rowb * (RS * 2) + (k0 + b_koff) * 2));
            }
#pragma unroll
            for (int mt = 0; mt < 4; mt++)
#pragma unroll
                for (int nt = 0; nt < 4; nt++)
                    mma16816(acc[mt][nt], af[mt], bf[nt]);
        }
    }

#pragma unroll
    for (int mt = 0; mt < 4; mt++) {
#pragma unroll
        for (int nt = 0; nt < 4; nt++) {
            int row = wm * 64 + mt * 16 + (lane >> 2);
            int col = wn * 32 + nt * 8 + (lane & 3) * 2;
            float v0 = acc[mt][nt][0], v1 = acc[mt][nt][1];
            float v2 = acc[mt][nt][2], v3 = acc[mt][nt][3];
            if (MODE == 0) {
                *(float2*)(Cf + (size_t)row * ldc + col) = make_float2(v0, v1);
                *(float2*)(Cf + (size_t)(row + 8) * ldc + col) = make_float2(v2, v3);
            } else {
                if (MODE == 2) {
                    int i = (col & 127) >> 1;
                    int t1 = (rowg0 + row) & (Tn - 1);
                    int t2 = (rowg0 + row + 8) & (Tn - 1);
                    float c1 = fcos[t1 * 64 + i], s1 = fsin[t1 * 64 + i];
                    float c2 = fcos[t2 * 64 + i], s2 = fsin[t2 * 64 + i];
                    float re = v0, im = v1;
                    v0 = re * c1 - im * s1; v1 = re * s1 + im * c1;
                    re = v2; im = v3;
                    v2 = re * c2 - im * s2; v3 = re * s2 + im * c2;
                }
                *(__half2*)(Ch + (size_t)row * ldc + col) = __floats2half2_rn(v0, v1);
                *(__half2*)(Ch + (size_t)(row + 8) * ldc + col) = __floats2half2_rn(v2, v3);
            }
        }
    }
}

// Fused QKV projection: grid (24, 32). Col tiles 0-15 -> Q, 16-19 -> K, 20-23 -> V
__global__ __launch_bounds__(256)
void gemm_qkv(const __half* __restrict__ X16,
              const __half* __restrict__ WqT, const __half* __restrict__ WkT,
              const __half* __restrict__ WvT,
              __half* __restrict__ Q, __half* __restrict__ Ko, __half* __restrict__ Vo,
              const float* __restrict__ fcos, const float* __restrict__ fsin)
{
    const int ct = blockIdx.x;
    const int row0 = blockIdx.y * 128;
    const __half* Xp = X16 + (size_t)row0 * Cn;
    if (ct < 16) {
        int c0 = ct * 128;
        gemm_core<2>(Xp, WqT + (size_t)c0 * Cn, nullptr,
                     Q + (size_t)row0 * Cn + c0, Cn, Cn, fcos, fsin, row0);
    } else if (ct < 20) {
        int c0 = (ct - 16) * 128;
        gemm_core<2>(Xp, WkT + (size_t)c0 * Cn, nullptr,
                     Ko + (size_t)row0 * KVC + c0, KVC, Cn, fcos, fsin, row0);
    } else {
        int c0 = (ct - 20) * 128;
        gemm_core<1>(Xp, WvT + (size_t)c0 * Cn, nullptr,
                     Vo + (size_t)row0 * KVC + c0, KVC, Cn, nullptr, nullptr, row0);
    }
}

// Output projection GEMM (fp32 out)
__global__ __launch_bounds__(256)
void gemm_out(const __half* __restrict__ A, const __half* __restrict__ B,
              float* __restrict__ C, int N, int K)
{
    const int row0 = blockIdx.y * 128;
    const int col0 = blockIdx.x * 128;
    gemm_core<0>(A + (size_t)row0 * K, B + (size_t)col0 * K,
                 C + (size_t)row0 * N + col0, nullptr,
                 N, K, nullptr, nullptr, 0);
}

// ===========================================================================
// Flash attention on fp16 HMMA (causal, GQA)
// Inputs pre-rope'd fp16. CTA: (128-query block, head, batch). 256 thr / 8 warps.
// K/V double-buffered via cp.async. Writes fp16 output.
// ===========================================================================
#define FST 136
#define FROWB (FST * 2)              // 272 bytes per row
#define QTILE_B (128 * FROWB)        // 34816
#define KTILE_B (64 * FROWB)         // 17408
#define KVSTG_B (2 * KTILE_B)        // 34816 per stage (K+V)
#define FLASH_SMEM (QTILE_B + 2 * KVSTG_B)   // 104448

__device__ __forceinline__ void f_load_kv(
    uint32_t skv,
    const __half* __restrict__ Kp, const __half* __restrict__ Vp,
    int k0g, int tid)
{
#pragma unroll
    for (int i = 0; i < 4; i++) {
        int idx = tid + i * 256;
        int r = idx >> 4, seg = idx & 15;
        uint32_t off = (uint32_t)(r * FROWB + seg * 16);
        size_t go = (size_t)(k0g + r) * KVC + seg * 8;
        cp_async16(skv + off,           Kp + go);
        cp_async16(skv + KTILE_B + off, Vp + go);
    }
    cp_commit();
}

__global__ __launch_bounds__(256)
void flash_attn_mma(const __half* __restrict__ Qg, const __half* __restrict__ Kg,
                    const __half* __restrict__ Vg, __half* __restrict__ Yg)
{
    extern __shared__ char smc[];
    const uint32_t sb  = smem_u32(smc);
    const uint32_t sQ  = sb;
    const uint32_t sKV0 = sb + QTILE_B;

    const int tid = threadIdx.x;
    const int lane = tid & 31;
    const int w = tid >> 5;                          // 0..7
    const int bq = gridDim.x - 1 - blockIdx.x;       // heavy blocks first
    const int h = blockIdx.y, b = blockIdx.z;
    const int q0 = bq * 128;
    const int kvh = h / REP;

    const __half* Qp = Qg + ((size_t)b * Tn + q0) * Cn + h * HD;
    const __half* Kp = Kg + (size_t)b * Tn * KVC + kvh * HD;
    const __half* Vp = Vg + (size_t)b * Tn * KVC + kvh * HD;

    // --- Q tile loads (cp.async, folded into first commit group) ---
#pragma unroll
    for (int i = 0; i < 8; i++) {
        int idx = tid + i * 256;
        int r = idx >> 4, seg = idx & 15;
        uint32_t off = (uint32_t)(r * FROWB + seg * 16);
        cp_async16(sQ + off, Qp + (size_t)r * Cn + seg * 8);
    }
    f_load_kv(sKV0, Kp, Vp, 0, tid);

    // fragment addressing
    const int arow = lane & 15;
    const int akoff = (lane >> 4) * 8;
    const int brow = (lane & 7) + ((lane >> 4) * 8);
    const int bkoff = ((lane >> 3) & 1) * 8;
    const int vrow = lane & 15;
    const int vnoff = (lane >> 4) * 8;

    float Oa[16][4];
#pragma unroll
    for (int i = 0; i < 16; i++)
#pragma unroll
        for (int q = 0; q < 4; q++) Oa[i][q] = 0.f;

    float m1 = -1e30f, m2 = -1e30f, l1 = 0.f, l2 = 0.f;
    const float sscale = 0.08838834764831845f;
    const int rg1 = q0 + w * 16 + (lane >> 2);
    const int rg2 = rg1 + 8;

    const int nkb = 2 * bq + 2;
    for (int j = 0; j < nkb; j++) {
        const int k0g = j * 64;
        const uint32_t skv = sKV0 + (j & 1) * KVSTG_B;
        if (j + 1 < nkb) {
            f_load_kv(sKV0 + ((j + 1) & 1) * KVSTG_B, Kp, Vp, (j + 1) * 64, tid);
            cp_wait_group<1>();
        } else {
            cp_wait_group<0>();
        }
        __syncthreads();

        const uint32_t sK = skv;
        const uint32_t sV = skv + KTILE_B;

        // --- S = Q K^T ---
        float S[8][4];
#pragma unroll
        for (int t = 0; t < 8; t++)
#pragma unroll
            for (int q = 0; q < 4; q++) S[t][q] = 0.f;

#pragma unroll
        for (int kc = 0; kc < 8; kc++) {
            uint32_t af[4];
            ldsm_x4(af, sQ + (uint32_t)((w * 16 + arow) * FROWB + (kc * 16 + akoff) * 2));
#pragma unroll
            for (int np = 0; np < 4; np++) {
                uint32_t bf[4];
                ldsm_x4(bf, sK + (uint32_t)((np * 16 + brow) * FROWB + (kc * 16 + bkoff) * 2));
                mma16816(S[2 * np],     af, bf);
                mma16816(S[2 * np + 1], af, bf + 2);
            }
        }

        // --- mask + scale + online softmax ---
        const bool diag = (k0g + 63 > q0 + w * 16);
        float mx1 = -1e30f, mx2 = -1e30f;
#pragma unroll
        for (int t = 0; t < 8; t++) {
            int cg = k0g + t * 8 + (lane & 3) * 2;
#pragma unroll
            for (int e = 0; e < 2; e++) {
                float s0 = S[t][e] * sscale;
                float s1 = S[t][2 + e] * sscale;
                if (diag) {
                    if (cg + e > rg1) s0 = -1e30f;
                    if (cg + e > rg2) s1 = -1e30f;
                }
                S[t][e] = s0;
                S[t][2 + e] = s1;
                mx1 = fmaxf(mx1, s0);
                mx2 = fmaxf(mx2, s1);
            }
        }
        mx1 = fmaxf(mx1, __shfl_xor_sync(0xffffffff, mx1, 1));
        mx1 = fmaxf(mx1, __shfl_xor_sync(0xffffffff, mx1, 2));
        mx2 = fmaxf(mx2, __shfl_xor_sync(0xffffffff, mx2, 1));
        mx2 = fmaxf(mx2, __shfl_xor_sync(0xffffffff, mx2, 2));

        float mn1 = fmaxf(m1, mx1), mn2 = fmaxf(m2, mx2);
        float f1 = __expf(m1 - mn1), f2 = __expf(m2 - mn2);
        float rs1 = 0.f, rs2 = 0.f;
#pragma unroll
        for (int t = 0; t < 8; t++) {
#pragma unroll
            for (int e = 0; e < 2; e++) {
                float p0 = __expf(S[t][e] - mn1);
                float p1 = __expf(S[t][2 + e] - mn2);
                S[t][e] = p0;
                S[t][2 + e] = p1;
                rs1 += p0;
                rs2 += p1;
            }
        }
        rs1 += __shfl_xor_sync(0xffffffff, rs1, 1);
        rs1 += __shfl_xor_sync(0xffffffff, rs1, 2);
        rs2 += __shfl_xor_sync(0xffffffff, rs2, 1);
        rs2 += __shfl_xor_sync(0xffffffff, rs2, 2);
        l1 = l1 * f1 + rs1;
        l2 = l2 * f2 + rs2;
        m1 = mn1; m2 = mn2;
#pragma unroll
        for (int t = 0; t < 16; t++) {
            Oa[t][0] *= f1; Oa[t][1] *= f1;
            Oa[t][2] *= f2; Oa[t][3] *= f2;
        }

        // --- O += P V ---
#pragma unroll
        for (int kc = 0; kc < 4; kc++) {
            uint32_t pf[4];
            pf[0] = pack_h2(S[2 * kc][0],     S[2 * kc][1]);
            pf[1] = pack_h2(S[2 * kc][2],     S[2 * kc][3]);
            pf[2] = pack_h2(S[2 * kc + 1][0], S[2 * kc + 1][1]);
            pf[3] = pack_h2(S[2 * kc + 1][2], S[2 * kc + 1][3]);
#pragma unroll
            for (int np = 0; np < 8; np++) {
                uint32_t vf[4];
                ldsm_x4_t(vf, sV + (uint32_t)((kc * 16 + vrow) * FROWB
                                              + (np * 16 + vnoff) * 2));
                mma16816(Oa[2 * np],     pf, vf);
                mma16816(Oa[2 * np + 1], pf, vf + 2);
            }
        }
        __syncthreads();
    }

    // --- epilogue: fp16 out ---
    const float il1 = 1.f / l1, il2 = 1.f / l2;
    const size_t base1 = ((size_t)b * Tn + q0 + w * 16 + (lane >> 2)) * Cn + h * HD;
    const size_t base2 = base1 + 8 * (size_t)Cn;
#pragma unroll
    for (int nt = 0; nt < 16; nt++) {
        int col = nt * 8 + (lane & 3) * 2;
        *(__half2*)(Yg + base1 + col) =
            __floats2half2_rn(Oa[nt][0] * il1, Oa[nt][1] * il1);
        *(__half2*)(Yg + base2 + col) =
            __floats2half2_rn(Oa[nt][2] * il2, Oa[nt][3] * il2);
    }
}

// ===========================================================================
// launch
// ===========================================================================
extern "C" void kernel_launch(void* const* d_in, const int* in_sizes, int n_in,
                              void* d_out, int out_size)
{
    const float* x   = (const float*)d_in[0];
    const float* Wq  = (const float*)d_in[1];
    const float* Wk  = (const float*)d_in[2];
    const float* Wv  = (const float*)d_in[3];
    const float* Wo  = (const float*)d_in[4];
    const float* fc  = (const float*)d_in[5];
    const float* fs  = (const float*)d_in[6];
    float* out = (float*)d_out;

    __half *X16, *Q16, *K16, *V16, *Y16, *WqT, *WkT, *WvT, *WoT;
    cudaGetSymbolAddress((void**)&X16, g_X16);
    cudaGetSymbolAddress((void**)&Q16, g_Q16);
    cudaGetSymbolAddress((void**)&K16, g_K16);
    cudaGetSymbolAddress((void**)&V16, g_V16);
    cudaGetSymbolAddress((void**)&Y16, g_Y16);
    cudaGetSymbolAddress((void**)&WqT, g_WqT);
    cudaGetSymbolAddress((void**)&WkT, g_WkT);
    cudaGetSymbolAddress((void**)&WvT, g_WvT);
    cudaGetSymbolAddress((void**)&WoT, g_WoT);

    cudaFuncSetAttribute(gemm_qkv,
                         cudaFuncAttributeMaxDynamicSharedMemorySize, GEMM_SMEM);
    cudaFuncSetAttribute(gemm_out,
                         cudaFuncAttributeMaxDynamicSharedMemorySize, GEMM_SMEM);
    cudaFuncSetAttribute(flash_attn_mma,
                         cudaFuncAttributeMaxDynamicSharedMemorySize, FLASH_SMEM);

    // convert x; transpose+convert weights
    {
        int tot4 = (Mrows * Cn) / 4;
        convert_kernel<<<(tot4 + 255) / 256, 256>>>(x, X16, tot4);
        transpose_convert<<<dim3(Cn / 32, Cn / 32), 256>>>(Wq, WqT, Cn, Cn);
        transpose_convert<<<dim3(KVC / 32, Cn / 32), 256>>>(Wk, WkT, Cn, KVC);
        transpose_convert<<<dim3(KVC / 32, Cn / 32), 256>>>(Wv, WvT, Cn, KVC);
        transpose_convert<<<dim3(Cn / 32, Cn / 32), 256>>>(Wo, WoT, Cn, Cn);
    }

    // fused QKV projection (rope fused into epilogue)
    {
        dim3 g(24, Mrows / 128);      // 24 x 32 = 768 CTAs
        gemm_qkv<<<g, 256, GEMM_SMEM>>>(X16, WqT, WkT, WvT,
                                        Q16, K16, V16, fc, fs);
    }

    // attention (fp16 HMMA flash)
    {
        dim3 g(Tn / 128, NH, Bn);     // 16 x 16 x 2
        flash_attn_mma<<<g, 256, FLASH_SMEM>>>(Q16, K16, V16, Y16);
    }

    // output projection
    {
        dim3 go(Cn / 128, Mrows / 128);   // 16 x 32
        gemm_out<<<go, 256, GEMM_SMEM>>>(Y16, WoT, out, Cn, Cn);
    }
}

// round 9
// speedup vs baseline: 7.6830x; 1.1909x over previous
#include <cuda_runtime.h>
#include <cuda_fp16.h>
#include <cstdint>
#include <math.h>

// Problem constants
#define Bn   2
#define Tn   2048
#define Cn   2048
#define NH   16
#define NKV  4
#define HD   128
#define REP  (NH / NKV)          // 4
#define Mrows (Bn * Tn)          // 4096
#define KVC  (NKV * HD)          // 512

// ===========================================================================
// Scratch (device globals; no runtime allocation allowed)
// ===========================================================================
__device__ __half g_X16[(size_t)Mrows * Cn];
__device__ __half g_Q16[(size_t)Mrows * Cn];
__device__ __half g_K16[(size_t)Mrows * KVC];
__device__ __half g_V16[(size_t)Mrows * KVC];
__device__ __half g_Y16[(size_t)Mrows * Cn];

// transposed weights [N][K] (K-major) fp16
__device__ __half g_WqT[(size_t)Cn * Cn];
__device__ __half g_WkT[(size_t)KVC * Cn];
__device__ __half g_WvT[(size_t)KVC * Cn];
__device__ __half g_WoT[(size_t)Cn * Cn];

// ===========================================================================
// PTX helpers
// ===========================================================================
__device__ __forceinline__ uint32_t smem_u32(const void* p) {
    uint32_t a;
    asm("{ .reg .u64 t; cvta.to.shared.u64 t, %1; cvt.u32.u64 %0, t; }"
        : "=r"(a) : "l"(p));
    return a;
}
__device__ __forceinline__ void cp_async16(uint32_t dst, const void* src) {
    asm volatile("cp.async.cg.shared.global [%0], [%1], 16;"
                 :: "r"(dst), "l"(src) : "memory");
}
__device__ __forceinline__ void cp_commit() {
    asm volatile("cp.async.commit_group;" ::: "memory");
}
template <int N> __device__ __forceinline__ void cp_wait_group() {
    asm volatile("cp.async.wait_group %0;" :: "n"(N) : "memory");
}
__device__ __forceinline__ void ldsm_x4(uint32_t* r, uint32_t addr) {
    asm volatile("ldmatrix.sync.aligned.m8n8.x4.shared.b16 {%0,%1,%2,%3}, [%4];"
                 : "=r"(r[0]), "=r"(r[1]), "=r"(r[2]), "=r"(r[3]) : "r"(addr));
}
__device__ __forceinline__ void ldsm_x4_t(uint32_t* r, uint32_t addr) {
    asm volatile("ldmatrix.sync.aligned.m8n8.x4.trans.shared.b16 {%0,%1,%2,%3}, [%4];"
                 : "=r"(r[0]), "=r"(r[1]), "=r"(r[2]), "=r"(r[3]) : "r"(addr));
}
__device__ __forceinline__ void mma16816(float* c, const uint32_t* a, const uint32_t* b) {
    asm volatile(
        "mma.sync.aligned.m16n8k16.row.col.f32.f16.f16.f32 "
        "{%0,%1,%2,%3}, {%4,%5,%6,%7}, {%8,%9}, {%0,%1,%2,%3};"
        : "+f"(c[0]), "+f"(c[1]), "+f"(c[2]), "+f"(c[3])
        : "r"(a[0]), "r"(a[1]), "r"(a[2]), "r"(a[3]), "r"(b[0]), "r"(b[1]));
}
__device__ __forceinline__ uint32_t pack_h2(float a, float b) {
    __half2 t = __floats2half2_rn(a, b);
    return *(uint32_t*)&t;
}

// ===========================================================================
// Fused prep: z = 0..3 -> transpose+convert Wq/Wk/Wv/Wo;  z = 4 -> convert X
// grid must be (128, 64, 5): z=4 uses 128*64=8192 blocks * 256 thr = 2M float4.
// ===========================================================================
__global__ __launch_bounds__(256)
void prep_kernel(const float* __restrict__ x,
                 const float* __restrict__ Wq, const float* __restrict__ Wk,
                 const float* __restrict__ Wv, const float* __restrict__ Wo,
                 __half* __restrict__ X16,
                 __half* __restrict__ WqT, __half* __restrict__ WkT,
                 __half* __restrict__ WvT, __half* __restrict__ WoT)
{
    const int z = blockIdx.z;
    if (z == 4) {
        int i = (blockIdx.y * gridDim.x + blockIdx.x) * 256 + threadIdx.x;
        int total4 = (Mrows * Cn) / 4;   // 2M
        if (i < total4) {
            float4 v = ((const float4*)x)[i];
            ((__half2*)X16)[2 * i]     = __floats2half2_rn(v.x, v.y);
            ((__half2*)X16)[2 * i + 1] = __floats2half2_rn(v.z, v.w);
        }
        return;
    }
    const float* W;
    __half* T;
    int N;
    if (z == 0)      { W = Wq; T = WqT; N = Cn; }
    else if (z == 1) { W = Wk; T = WkT; N = KVC; }
    else if (z == 2) { W = Wv; T = WvT; N = KVC; }
    else             { W = Wo; T = WoT; N = Cn; }
    const int K = Cn;
    int n0 = blockIdx.x * 32, k0 = blockIdx.y * 32;
    if (n0 >= N) return;

    __shared__ float tile[32][33];
    int tx = threadIdx.x & 31, ty = threadIdx.x >> 5;
#pragma unroll
    for (int i = 0; i < 32; i += 8)
        tile[ty + i][tx] = W[(size_t)(k0 + ty + i) * N + n0 + tx];
    __syncthreads();
#pragma unroll
    for (int i = 0; i < 32; i += 8)
        T[(size_t)(n0 + ty + i) * K + k0 + tx] = __float2half(tile[tx][ty + i]);
}

// ===========================================================================
// fp16 HMMA GEMM: C[M,N] = A @ B^T (fp32 acc)
// 128x128 CTA tile, BK=32, 128 threads / 4 warps (2x2), 64x64 warp tiles,
// 3-stage cp.async pipeline.
// MODE 0: fp32 out. MODE 1: fp16 out. MODE 2: rope + fp16 out.
// ===========================================================================
#define TBK 32
#define RS  40
#define MAT_BYTES (128 * RS * 2)          // 10240
#define STG_BYTES (2 * MAT_BYTES)         // 20480
#define GEMM_SMEM (3 * STG_BYTES)         // 61440

__device__ __forceinline__ void gemm_load(
    uint32_t st,
    const __half* __restrict__ A, const __half* __restrict__ B,
    int K, int c, int tid)
{
#pragma unroll
    for (int j = 0; j < 4; j++) {
        int idx = tid + j * 128;
        int r = idx >> 2, seg = idx & 3;
        uint32_t so = (uint32_t)(r * (RS * 2) + seg * 16);
        size_t go = (size_t)r * K + (size_t)c * TBK + seg * 8;
        cp_async16(st + so,             A + go);
        cp_async16(st + MAT_BYTES + so, B + go);
    }
    cp_commit();
}

template <int MODE>
__device__ __forceinline__ void gemm_core(
    const __half* __restrict__ A, const __half* __restrict__ B,
    float* __restrict__ Cf, __half* __restrict__ Ch,
    int ldc, int K,
    const float* __restrict__ fcos, const float* __restrict__ fsin, int rowg0)
{
    extern __shared__ char smem[];
    const uint32_t sb = smem_u32(smem);
    const int tid = threadIdx.x;
    const int lane = tid & 31;
    const int wid = tid >> 5;        // 0..3
    const int wm = wid & 1;          // warp row
    const int wn = wid >> 1;         // warp col

    float acc[4][8][4];              // mt x (nt,half) x 4
#pragma unroll
    for (int i = 0; i < 4; i++)
#pragma unroll
        for (int j = 0; j < 8; j++)
#pragma unroll
            for (int q = 0; q < 4; q++) acc[i][j][q] = 0.f;

    const int a_row_in = (lane & 15);
    const int a_koff   = (lane >> 4) * 8;
    const int b_row_in = (lane & 7) + ((lane >> 4) * 8);
    const int b_koff   = ((lane >> 3) & 1) * 8;

    const int NC = K / TBK;
    gemm_load(sb,             A, B, K, 0, tid);
    gemm_load(sb + STG_BYTES, A, B, K, 1, tid);

    int snext = 2;
    for (int c = 0; c < NC; c++) {
        const int scur = c % 3;
        if (c + 2 < NC) { cp_wait_group<1>(); } else { cp_wait_group<0>(); }
        __syncthreads();
        if (c + 2 < NC) {
            gemm_load(sb + snext * STG_BYTES, A, B, K, c + 2, tid);
            snext = (snext + 1) % 3;
        }

        const uint32_t st = sb + scur * STG_BYTES;
#pragma unroll
        for (int kk = 0; kk < 2; kk++) {
            const int k0 = kk * 16;
            uint32_t af[4][4];
#pragma unroll
            for (int mt = 0; mt < 4; mt++) {
                int row = wm * 64 + mt * 16 + a_row_in;
                ldsm_x4(af[mt], st + (uint32_t)(row * (RS * 2) + (k0 + a_koff) * 2));
            }
            uint32_t bf[4][4];
#pragma unroll
            for (int nt = 0; nt < 4; nt++) {
                int rowb = wn * 64 + nt * 16 + b_row_in;
                ldsm_x4(bf[nt], st + MAT_BYTES
                        + (uint32_t)(rowb * (RS * 2) + (k0 + b_koff) * 2));
            }
#pragma unroll
            for (int mt = 0; mt < 4; mt++)
#pragma unroll
                for (int nt = 0; nt < 4; nt++) {
                    mma16816(acc[mt][2 * nt],     af[mt], bf[nt]);
                    mma16816(acc[mt][2 * nt + 1], af[mt], bf[nt] + 2);
                }
        }
    }

#pragma unroll
    for (int mt = 0; mt < 4; mt++) {
#pragma unroll
        for (int nt = 0; nt < 8; nt++) {
            int row = wm * 64 + mt * 16 + (lane >> 2);
            int col = wn * 64 + nt * 8 + (lane & 3) * 2;
            float v0 = acc[mt][nt][0], v1 = acc[mt][nt][1];
            float v2 = acc[mt][nt][2], v3 = acc[mt][nt][3];
            if (MODE == 0) {
                *(float2*)(Cf + (size_t)row * ldc + col) = make_float2(v0, v1);
                *(float2*)(Cf + (size_t)(row + 8) * ldc + col) = make_float2(v2, v3);
            } else {
                if (MODE == 2) {
                    int i = (col & 127) >> 1;
                    int t1 = (rowg0 + row) & (Tn - 1);
                    int t2 = (rowg0 + row + 8) & (Tn - 1);
                    float c1 = fcos[t1 * 64 + i], s1 = fsin[t1 * 64 + i];
                    float c2 = fcos[t2 * 64 + i], s2 = fsin[t2 * 64 + i];
                    float re = v0, im = v1;
                    v0 = re * c1 - im * s1; v1 = re * s1 + im * c1;
                    re = v2; im = v3;
                    v2 = re * c2 - im * s2; v3 = re * s2 + im * c2;
                }
                *(__half2*)(Ch + (size_t)row * ldc + col) = __floats2half2_rn(v0, v1);
                *(__half2*)(Ch + (size_t)(row + 8) * ldc + col) = __floats2half2_rn(v2, v3);
            }
        }
    }
}

// Fused QKV projection: grid (24, 32). Col tiles 0-15 -> Q, 16-19 -> K, 20-23 -> V
__global__ __launch_bounds__(128)
void gemm_qkv(const __half* __restrict__ X16,
              const __half* __restrict__ WqT, const __half* __restrict__ WkT,
              const __half* __restrict__ WvT,
              __half* __restrict__ Q, __half* __restrict__ Ko, __half* __restrict__ Vo,
              const float* __restrict__ fcos, const float* __restrict__ fsin)
{
    const int ct = blockIdx.x;
    const int row0 = blockIdx.y * 128;
    const __half* Xp = X16 + (size_t)row0 * Cn;
    if (ct < 16) {
        int c0 = ct * 128;
        gemm_core<2>(Xp, WqT + (size_t)c0 * Cn, nullptr,
                     Q + (size_t)row0 * Cn + c0, Cn, Cn, fcos, fsin, row0);
    } else if (ct < 20) {
        int c0 = (ct - 16) * 128;
        gemm_core<2>(Xp, WkT + (size_t)c0 * Cn, nullptr,
                     Ko + (size_t)row0 * KVC + c0, KVC, Cn, fcos, fsin, row0);
    } else {
        int c0 = (ct - 20) * 128;
        gemm_core<1>(Xp, WvT + (size_t)c0 * Cn, nullptr,
                     Vo + (size_t)row0 * KVC + c0, KVC, Cn, nullptr, nullptr, row0);
    }
}

// Output projection GEMM (fp32 out)
__global__ __launch_bounds__(128)
void gemm_out(const __half* __restrict__ A, const __half* __restrict__ B,
              float* __restrict__ C, int N, int K)
{
    const int row0 = blockIdx.y * 128;
    const int col0 = blockIdx.x * 128;
    gemm_core<0>(A + (size_t)row0 * K, B + (size_t)col0 * K,
                 C + (size_t)row0 * N + col0, nullptr,
                 N, K, nullptr, nullptr, 0);
}

// ===========================================================================
// Flash attention on fp16 HMMA (causal, GQA)
// ===========================================================================
#define FST 136
#define FROWB (FST * 2)              // 272 bytes per row
#define QTILE_B (128 * FROWB)        // 34816
#define KTILE_B (64 * FROWB)         // 17408
#define KVSTG_B (2 * KTILE_B)        // 34816 per stage (K+V)
#define FLASH_SMEM (QTILE_B + 2 * KVSTG_B)   // 104448

__device__ __forceinline__ void f_load_kv(
    uint32_t skv,
    const __half* __restrict__ Kp, const __half* __restrict__ Vp,
    int k0g, int tid)
{
#pragma unroll
    for (int i = 0; i < 4; i++) {
        int idx = tid + i * 256;
        int r = idx >> 4, seg = idx & 15;
        uint32_t off = (uint32_t)(r * FROWB + seg * 16);
        size_t go = (size_t)(k0g + r) * KVC + seg * 8;
        cp_async16(skv + off,           Kp + go);
        cp_async16(skv + KTILE_B + off, Vp + go);
    }
    cp_commit();
}

__global__ __launch_bounds__(256)
void flash_attn_mma(const __half* __restrict__ Qg, const __half* __restrict__ Kg,
                    const __half* __restrict__ Vg, __half* __restrict__ Yg)
{
    extern __shared__ char smc[];
    const uint32_t sb  = smem_u32(smc);
    const uint32_t sQ  = sb;
    const uint32_t sKV0 = sb + QTILE_B;

    const int tid = threadIdx.x;
    const int lane = tid & 31;
    const int w = tid >> 5;
    const int bq = gridDim.x - 1 - blockIdx.x;       // heavy blocks first
    const int h = blockIdx.y, b = blockIdx.z;
    const int q0 = bq * 128;
    const int kvh = h / REP;

    const __half* Qp = Qg + ((size_t)b * Tn + q0) * Cn + h * HD;
    const __half* Kp = Kg + (size_t)b * Tn * KVC + kvh * HD;
    const __half* Vp = Vg + (size_t)b * Tn * KVC + kvh * HD;

#pragma unroll
    for (int i = 0; i < 8; i++) {
        int idx = tid + i * 256;
        int r = idx >> 4, seg = idx & 15;
        uint32_t off = (uint32_t)(r * FROWB + seg * 16);
        cp_async16(sQ + off, Qp + (size_t)r * Cn + seg * 8);
    }
    f_load_kv(sKV0, Kp, Vp, 0, tid);

    const int arow = lane & 15;
    const int akoff = (lane >> 4) * 8;
    const int brow = (lane & 7) + ((lane >> 4) * 8);
    const int bkoff = ((lane >> 3) & 1) * 8;
    const int vrow = lane & 15;
    const int vnoff = (lane >> 4) * 8;

    float Oa[16][4];
#pragma unroll
    for (int i = 0; i < 16; i++)
#pragma unroll
        for (int q = 0; q < 4; q++) Oa[i][q] = 0.f;

    float m1 = -1e30f, m2 = -1e30f, l1 = 0.f, l2 = 0.f;
    const float sscale = 0.08838834764831845f;
    const int rg1 = q0 + w * 16 + (lane >> 2);
    const int rg2 = rg1 + 8;

    const int nkb = 2 * bq + 2;
    for (int j = 0; j < nkb; j++) {
        const int k0g = j * 64;
        const uint32_t skv = sKV0 + (j & 1) * KVSTG_B;
        if (j + 1 < nkb) {
            f_load_kv(sKV0 + ((j + 1) & 1) * KVSTG_B, Kp, Vp, (j + 1) * 64, tid);
            cp_wait_group<1>();
        } else {
            cp_wait_group<0>();
        }
        __syncthreads();

        const uint32_t sK = skv;
        const uint32_t sV = skv + KTILE_B;

        float S[8][4];
#pragma unroll
        for (int t = 0; t < 8; t++)
#pragma unroll
            for (int q = 0; q < 4; q++) S[t][q] = 0.f;

#pragma unroll
        for (int kc = 0; kc < 8; kc++) {
            uint32_t af[4];
            ldsm_x4(af, sQ + (uint32_t)((w * 16 + arow) * FROWB + (kc * 16 + akoff) * 2));
#pragma unroll
            for (int np = 0; np < 4; np++) {
                uint32_t bf[4];
                ldsm_x4(bf, sK + (uint32_t)((np * 16 + brow) * FROWB + (kc * 16 + bkoff) * 2));
                mma16816(S[2 * np],     af, bf);
                mma16816(S[2 * np + 1], af, bf + 2);
            }
        }

        const bool diag = (k0g + 63 > q0 + w * 16);
        float mx1 = -1e30f, mx2 = -1e30f;
#pragma unroll
        for (int t = 0; t < 8; t++) {
            int cg = k0g + t * 8 + (lane & 3) * 2;
#pragma unroll
            for (int e = 0; e < 2; e++) {
                float s0 = S[t][e] * sscale;
                float s1 = S[t][2 + e] * sscale;
                if (diag) {
                    if (cg + e > rg1) s0 = -1e30f;
                    if (cg + e > rg2) s1 = -1e30f;
                }
                S[t][e] = s0;
                S[t][2 + e] = s1;
                mx1 = fmaxf(mx1, s0);
                mx2 = fmaxf(mx2, s1);
            }
        }
        mx1 = fmaxf(mx1, __shfl_xor_sync(0xffffffff, mx1, 1));
        mx1 = fmaxf(mx1, __shfl_xor_sync(0xffffffff, mx1, 2));
        mx2 = fmaxf(mx2, __shfl_xor_sync(0xffffffff, mx2, 1));
        mx2 = fmaxf(mx2, __shfl_xor_sync(0xffffffff, mx2, 2));

        float mn1 = fmaxf(m1, mx1), mn2 = fmaxf(m2, mx2);
        float f1 = __expf(m1 - mn1), f2 = __expf(m2 - mn2);
        float rs1 = 0.f, rs2 = 0.f;
#pragma unroll
        for (int t = 0; t < 8; t++) {
#pragma unroll
            for (int e = 0; e < 2; e++) {
                float p0 = __expf(S[t][e] - mn1);
                float p1 = __expf(S[t][2 + e] - mn2);
                S[t][e] = p0;
                S[t][2 + e] = p1;
                rs1 += p0;
                rs2 += p1;
            }
        }
        rs1 += __shfl_xor_sync(0xffffffff, rs1, 1);
        rs1 += __shfl_xor_sync(0xffffffff, rs1, 2);
        rs2 += __shfl_xor_sync(0xffffffff, rs2, 1);
        rs2 += __shfl_xor_sync(0xffffffff, rs2, 2);
        l1 = l1 * f1 + rs1;
        l2 = l2 * f2 + rs2;
        m1 = mn1; m2 = mn2;
#pragma unroll
        for (int t = 0; t < 16; t++) {
            Oa[t][0] *= f1; Oa[t][1] *= f1;
            Oa[t][2] *= f2; Oa[t][3] *= f2;
        }

#pragma unroll
        for (int kc = 0; kc < 4; kc++) {
            uint32_t pf[4];
            pf[0] = pack_h2(S[2 * kc][0],     S[2 * kc][1]);
            pf[1] = pack_h2(S[2 * kc][2],     S[2 * kc][3]);
            pf[2] = pack_h2(S[2 * kc + 1][0], S[2 * kc + 1][1]);
            pf[3] = pack_h2(S[2 * kc + 1][2], S[2 * kc + 1][3]);
#pragma unroll
            for (int np = 0; np < 8; np++) {
                uint32_t vf[4];
                ldsm_x4_t(vf, sV + (uint32_t)((kc * 16 + vrow) * FROWB
                                              + (np * 16 + vnoff) * 2));
                mma16816(Oa[2 * np],     pf, vf);
                mma16816(Oa[2 * np + 1], pf, vf + 2);
            }
        }
        __syncthreads();
    }

    const float il1 = 1.f / l1, il2 = 1.f / l2;
    const size_t base1 = ((size_t)b * Tn + q0 + w * 16 + (lane >> 2)) * Cn + h * HD;
    const size_t base2 = base1 + 8 * (size_t)Cn;
#pragma unroll
    for (int nt = 0; nt < 16; nt++) {
        int col = nt * 8 + (lane & 3) * 2;
        *(__half2*)(Yg + base1 + col) =
            __floats2half2_rn(Oa[nt][0] * il1, Oa[nt][1] * il1);
        *(__half2*)(Yg + base2 + col) =
            __floats2half2_rn(Oa[nt][2] * il2, Oa[nt][3] * il2);
    }
}

// ===========================================================================
// launch
// ===========================================================================
extern "C" void kernel_launch(void* const* d_in, const int* in_sizes, int n_in,
                              void* d_out, int out_size)
{
    const float* x   = (const float*)d_in[0];
    const float* Wq  = (const float*)d_in[1];
    const float* Wk  = (const float*)d_in[2];
    const float* Wv  = (const float*)d_in[3];
    const float* Wo  = (const float*)d_in[4];
    const float* fc  = (const float*)d_in[5];
    const float* fs  = (const float*)d_in[6];
    float* out = (float*)d_out;

    __half *X16, *Q16, *K16, *V16, *Y16, *WqT, *WkT, *WvT, *WoT;
    cudaGetSymbolAddress((void**)&X16, g_X16);
    cudaGetSymbolAddress((void**)&Q16, g_Q16);
    cudaGetSymbolAddress((void**)&K16, g_K16);
    cudaGetSymbolAddress((void**)&V16, g_V16);
    cudaGetSymbolAddress((void**)&Y16, g_Y16);
    cudaGetSymbolAddress((void**)&WqT, g_WqT);
    cudaGetSymbolAddress((void**)&WkT, g_WkT);
    cudaGetSymbolAddress((void**)&WvT, g_WvT);
    cudaGetSymbolAddress((void**)&WoT, g_WoT);

    cudaFuncSetAttribute(gemm_qkv,
                         cudaFuncAttributeMaxDynamicSharedMemorySize, GEMM_SMEM);
    cudaFuncSetAttribute(gemm_out,
                         cudaFuncAttributeMaxDynamicSharedMemorySize, GEMM_SMEM);
    cudaFuncSetAttribute(flash_attn_mma,
                         cudaFuncAttributeMaxDynamicSharedMemorySize, FLASH_SMEM);

    // fused prep: z=0..3 weight transposes; z=4 X convert (128*64 blocks = 2M float4)
    {
        dim3 g(128, 64, 5);
        prep_kernel<<<g, 256>>>(x, Wq, Wk, Wv, Wo, X16, WqT, WkT, WvT, WoT);
    }

    // fused QKV projection (rope fused into epilogue)
    {
        dim3 g(24, Mrows / 128);      // 24 x 32 = 768 CTAs
        gemm_qkv<<<g, 128, GEMM_SMEM>>>(X16, WqT, WkT, WvT,
                                        Q16, K16, V16, fc, fs);
    }

    // attention (fp16 HMMA flash)
    {
        dim3 g(Tn / 128, NH, Bn);     // 16 x 16 x 2
        flash_attn_mma<<<g, 256, FLASH_SMEM>>>(Q16, K16, V16, Y16);
    }

    // output projection
    {
        dim3 go(Cn / 128, Mrows / 128);   // 16 x 32
        gemm_out<<<go, 128, GEMM_SMEM>>>(Y16, WoT, out, Cn, Cn);
    }
}

// round 10
// speedup vs baseline: 7.9999x; 1.0412x over previous
#include <cuda_runtime.h>
#include <cuda_fp16.h>
#include <cstdint>
#include <math.h>

// Problem constants
#define Bn   2
#define Tn   2048
#define Cn   2048
#define NH   16
#define NKV  4
#define HD   128
#define REP  (NH / NKV)          // 4
#define Mrows (Bn * Tn)          // 4096
#define KVC  (NKV * HD)          // 512

// ===========================================================================
// Scratch (device globals; no runtime allocation allowed)
// ===========================================================================
__device__ __half g_X16[(size_t)Mrows * Cn];
__device__ __half g_Q16[(size_t)Mrows * Cn];
__device__ __half g_K16[(size_t)Mrows * KVC];
__device__ __half g_V16[(size_t)Mrows * KVC];
__device__ __half g_Y16[(size_t)Mrows * Cn];

// transposed weights [N][K] (K-major) fp16
__device__ __half g_WqT[(size_t)Cn * Cn];
__device__ __half g_WkT[(size_t)KVC * Cn];
__device__ __half g_WvT[(size_t)KVC * Cn];
__device__ __half g_WoT[(size_t)Cn * Cn];

// ===========================================================================
// PTX helpers
// ===========================================================================
__device__ __forceinline__ uint32_t smem_u32(const void* p) {
    uint32_t a;
    asm("{ .reg .u64 t; cvta.to.shared.u64 t, %1; cvt.u32.u64 %0, t; }"
        : "=r"(a) : "l"(p));
    return a;
}
__device__ __forceinline__ void cp_async16(uint32_t dst, const void* src) {
    asm volatile("cp.async.cg.shared.global [%0], [%1], 16;"
                 :: "r"(dst), "l"(src) : "memory");
}
__device__ __forceinline__ void cp_commit() {
    asm volatile("cp.async.commit_group;" ::: "memory");
}
template <int N> __device__ __forceinline__ void cp_wait_group() {
    asm volatile("cp.async.wait_group %0;" :: "n"(N) : "memory");
}
__device__ __forceinline__ void ldsm_x4(uint32_t* r, uint32_t addr) {
    asm volatile("ldmatrix.sync.aligned.m8n8.x4.shared.b16 {%0,%1,%2,%3}, [%4];"
                 : "=r"(r[0]), "=r"(r[1]), "=r"(r[2]), "=r"(r[3]) : "r"(addr));
}
__device__ __forceinline__ void ldsm_x4_t(uint32_t* r, uint32_t addr) {
    asm volatile("ldmatrix.sync.aligned.m8n8.x4.trans.shared.b16 {%0,%1,%2,%3}, [%4];"
                 : "=r"(r[0]), "=r"(r[1]), "=r"(r[2]), "=r"(r[3]) : "r"(addr));
}
__device__ __forceinline__ void mma16816(float* c, const uint32_t* a, const uint32_t* b) {
    asm volatile(
        "mma.sync.aligned.m16n8k16.row.col.f32.f16.f16.f32 "
        "{%0,%1,%2,%3}, {%4,%5,%6,%7}, {%8,%9}, {%0,%1,%2,%3};"
        : "+f"(c[0]), "+f"(c[1]), "+f"(c[2]), "+f"(c[3])
        : "r"(a[0]), "r"(a[1]), "r"(a[2]), "r"(a[3]), "r"(b[0]), "r"(b[1]));
}
__device__ __forceinline__ uint32_t pack_h2(float a, float b) {
    __half2 t = __floats2half2_rn(a, b);
    return *(uint32_t*)&t;
}

// ===========================================================================
// Fused prep: z = 0..3 -> transpose+convert Wq/Wk/Wv/Wo;  z = 4 -> convert X
// grid (128, 64, 5): z=4 uses 128*64=8192 blocks * 256 thr = 2M float4.
// ===========================================================================
__global__ __launch_bounds__(256)
void prep_kernel(const float* __restrict__ x,
                 const float* __restrict__ Wq, const float* __restrict__ Wk,
                 const float* __restrict__ Wv, const float* __restrict__ Wo,
                 __half* __restrict__ X16,
                 __half* __restrict__ WqT, __half* __restrict__ WkT,
                 __half* __restrict__ WvT, __half* __restrict__ WoT)
{
    const int z = blockIdx.z;
    if (z == 4) {
        int i = (blockIdx.y * gridDim.x + blockIdx.x) * 256 + threadIdx.x;
        int total4 = (Mrows * Cn) / 4;   // 2M
        if (i < total4) {
            float4 v = ((const float4*)x)[i];
            ((__half2*)X16)[2 * i]     = __floats2half2_rn(v.x, v.y);
            ((__half2*)X16)[2 * i + 1] = __floats2half2_rn(v.z, v.w);
        }
        return;
    }
    const float* W;
    __half* T;
    int N;
    if (z == 0)      { W = Wq; T = WqT; N = Cn; }
    else if (z == 1) { W = Wk; T = WkT; N = KVC; }
    else if (z == 2) { W = Wv; T = WvT; N = KVC; }
    else             { W = Wo; T = WoT; N = Cn; }
    const int K = Cn;
    int n0 = blockIdx.x * 32, k0 = blockIdx.y * 32;
    if (n0 >= N) return;

    __shared__ float tile[32][33];
    int tx = threadIdx.x & 31, ty = threadIdx.x >> 5;
#pragma unroll
    for (int i = 0; i < 32; i += 8)
        tile[ty + i][tx] = W[(size_t)(k0 + ty + i) * N + n0 + tx];
    __syncthreads();
#pragma unroll
    for (int i = 0; i < 32; i += 8)
        T[(size_t)(n0 + ty + i) * K + k0 + tx] = __float2half(tile[tx][ty + i]);
}

// ===========================================================================
// fp16 HMMA GEMM: C[M,N] = A @ B^T (fp32 acc)
// 128x128 CTA tile, BK=64, 128 threads / 4 warps (2x2), 64x64 warp tiles,
// 2-stage cp.async pipeline, loads issued immediately after barrier.
// MODE 0: fp32 out. MODE 1: fp16 out. MODE 2: rope + fp16 out.
// ===========================================================================
#define TBK 64
#define RS  72                            // 64 + 8 pad (halves)
#define MAT_BYTES (128 * RS * 2)          // 18432
#define STG_BYTES (2 * MAT_BYTES)         // 36864
#define GEMM_SMEM (2 * STG_BYTES)         // 73728  -> 3 CTAs/SM

__device__ __forceinline__ void gemm_load(
    uint32_t st,
    const __half* __restrict__ A, const __half* __restrict__ B,
    int K, int c, int tid)
{
#pragma unroll
    for (int j = 0; j < 8; j++) {
        int idx = tid + j * 128;         // 0..1023
        int r = idx >> 3, seg = idx & 7;
        uint32_t so = (uint32_t)(r * (RS * 2) + seg * 16);
        size_t go = (size_t)r * K + (size_t)c * TBK + seg * 8;
        cp_async16(st + so,             A + go);
        cp_async16(st + MAT_BYTES + so, B + go);
    }
    cp_commit();
}

template <int MODE>
__device__ __forceinline__ void gemm_core(
    const __half* __restrict__ A, const __half* __restrict__ B,
    float* __restrict__ Cf, __half* __restrict__ Ch,
    int ldc, int K,
    const float* __restrict__ fcos, const float* __restrict__ fsin, int rowg0)
{
    extern __shared__ char smem[];
    const uint32_t sb = smem_u32(smem);
    const int tid = threadIdx.x;
    const int lane = tid & 31;
    const int wid = tid >> 5;        // 0..3
    const int wm = wid & 1;          // warp row
    const int wn = wid >> 1;         // warp col

    float acc[4][8][4];              // mt x (nt,half) x 4
#pragma unroll
    for (int i = 0; i < 4; i++)
#pragma unroll
        for (int j = 0; j < 8; j++)
#pragma unroll
            for (int q = 0; q < 4; q++) acc[i][j][q] = 0.f;

    const int a_row_in = (lane & 15);
    const int a_koff   = (lane >> 4) * 8;
    const int b_row_in = (lane & 7) + ((lane >> 4) * 8);
    const int b_koff   = ((lane >> 3) & 1) * 8;

    const int NC = K / TBK;
    gemm_load(sb, A, B, K, 0, tid);

    for (int c = 0; c < NC; c++) {
        cp_wait_group<0>();          // data for chunk c ready
        __syncthreads();             // all warps done reading the other buffer
        if (c + 1 < NC)              // prefetch chunk c+1 into the other buffer
            gemm_load(sb + ((c + 1) & 1) * STG_BYTES, A, B, K, c + 1, tid);

        const uint32_t st = sb + (c & 1) * STG_BYTES;
#pragma unroll
        for (int kk = 0; kk < 4; kk++) {
            const int k0 = kk * 16;
            uint32_t af[4][4];
#pragma unroll
            for (int mt = 0; mt < 4; mt++) {
                int row = wm * 64 + mt * 16 + a_row_in;
                ldsm_x4(af[mt], st + (uint32_t)(row * (RS * 2) + (k0 + a_koff) * 2));
            }
            uint32_t bf[4][4];
#pragma unroll
            for (int nt = 0; nt < 4; nt++) {
                int rowb = wn * 64 + nt * 16 + b_row_in;
                ldsm_x4(bf[nt], st + MAT_BYTES
                        + (uint32_t)(rowb * (RS * 2) + (k0 + b_koff) * 2));
            }
#pragma unroll
            for (int mt = 0; mt < 4; mt++)
#pragma unroll
                for (int nt = 0; nt < 4; nt++) {
                    mma16816(acc[mt][2 * nt],     af[mt], bf[nt]);
                    mma16816(acc[mt][2 * nt + 1], af[mt], bf[nt] + 2);
                }
        }
    }

#pragma unroll
    for (int mt = 0; mt < 4; mt++) {
#pragma unroll
        for (int nt = 0; nt < 8; nt++) {
            int row = wm * 64 + mt * 16 + (lane >> 2);
            int col = wn * 64 + nt * 8 + (lane & 3) * 2;
            float v0 = acc[mt][nt][0], v1 = acc[mt][nt][1];
            float v2 = acc[mt][nt][2], v3 = acc[mt][nt][3];
            if (MODE == 0) {
                *(float2*)(Cf + (size_t)row * ldc + col) = make_float2(v0, v1);
                *(float2*)(Cf + (size_t)(row + 8) * ldc + col) = make_float2(v2, v3);
            } else {
                if (MODE == 2) {
                    int i = (col & 127) >> 1;
                    int t1 = (rowg0 + row) & (Tn - 1);
                    int t2 = (rowg0 + row + 8) & (Tn - 1);
                    float c1 = fcos[t1 * 64 + i], s1 = fsin[t1 * 64 + i];
                    float c2 = fcos[t2 * 64 + i], s2 = fsin[t2 * 64 + i];
                    float re = v0, im = v1;
                    v0 = re * c1 - im * s1; v1 = re * s1 + im * c1;
                    re = v2; im = v3;
                    v2 = re * c2 - im * s2; v3 = re * s2 + im * c2;
                }
                *(__half2*)(Ch + (size_t)row * ldc + col) = __floats2half2_rn(v0, v1);
                *(__half2*)(Ch + (size_t)(row + 8) * ldc + col) = __floats2half2_rn(v2, v3);
            }
        }
    }
}

// Fused QKV projection: grid (24, 32). Col tiles 0-15 -> Q, 16-19 -> K, 20-23 -> V
__global__ __launch_bounds__(128)
void gemm_qkv(const __half* __restrict__ X16,
              const __half* __restrict__ WqT, const __half* __restrict__ WkT,
              const __half* __restrict__ WvT,
              __half* __restrict__ Q, __half* __restrict__ Ko, __half* __restrict__ Vo,
              const float* __restrict__ fcos, const float* __restrict__ fsin)
{
    const int ct = blockIdx.x;
    const int row0 = blockIdx.y * 128;
    const __half* Xp = X16 + (size_t)row0 * Cn;
    if (ct < 16) {
        int c0 = ct * 128;
        gemm_core<2>(Xp, WqT + (size_t)c0 * Cn, nullptr,
                     Q + (size_t)row0 * Cn + c0, Cn, Cn, fcos, fsin, row0);
    } else if (ct < 20) {
        int c0 = (ct - 16) * 128;
        gemm_core<2>(Xp, WkT + (size_t)c0 * Cn, nullptr,
                     Ko + (size_t)row0 * KVC + c0, KVC, Cn, fcos, fsin, row0);
    } else {
        int c0 = (ct - 20) * 128;
        gemm_core<1>(Xp, WvT + (size_t)c0 * Cn, nullptr,
                     Vo + (size_t)row0 * KVC + c0, KVC, Cn, nullptr, nullptr, row0);
    }
}

// Output projection GEMM (fp32 out)
__global__ __launch_bounds__(128)
void gemm_out(const __half* __restrict__ A, const __half* __restrict__ B,
              float* __restrict__ C, int N, int K)
{
    const int row0 = blockIdx.y * 128;
    const int col0 = blockIdx.x * 128;
    gemm_core<0>(A + (size_t)row0 * K, B + (size_t)col0 * K,
                 C + (size_t)row0 * N + col0, nullptr,
                 N, K, nullptr, nullptr, 0);
}

// ===========================================================================
// Flash attention on fp16 HMMA (causal, GQA) — unchanged
// ===========================================================================
#define FST 136
#define FROWB (FST * 2)              // 272 bytes per row
#define QTILE_B (128 * FROWB)        // 34816
#define KTILE_B (64 * FROWB)         // 17408
#define KVSTG_B (2 * KTILE_B)        // 34816 per stage (K+V)
#define FLASH_SMEM (QTILE_B + 2 * KVSTG_B)   // 104448

__device__ __forceinline__ void f_load_kv(
    uint32_t skv,
    const __half* __restrict__ Kp, const __half* __restrict__ Vp,
    int k0g, int tid)
{
#pragma unroll
    for (int i = 0; i < 4; i++) {
        int idx = tid + i * 256;
        int r = idx >> 4, seg = idx & 15;
        uint32_t off = (uint32_t)(r * FROWB + seg * 16);
        size_t go = (size_t)(k0g + r) * KVC + seg * 8;
        cp_async16(skv + off,           Kp + go);
        cp_async16(skv + KTILE_B + off, Vp + go);
    }
    cp_commit();
}

__global__ __launch_bounds__(256)
void flash_attn_mma(const __half* __restrict__ Qg, const __half* __restrict__ Kg,
                    const __half* __restrict__ Vg, __half* __restrict__ Yg)
{
    extern __shared__ char smc[];
    const uint32_t sb  = smem_u32(smc);
    const uint32_t sQ  = sb;
    const uint32_t sKV0 = sb + QTILE_B;

    const int tid = threadIdx.x;
    const int lane = tid & 31;
    const int w = tid >> 5;
    const int bq = gridDim.x - 1 - blockIdx.x;       // heavy blocks first
    const int h = blockIdx.y, b = blockIdx.z;
    const int q0 = bq * 128;
    const int kvh = h / REP;

    const __half* Qp = Qg + ((size_t)b * Tn + q0) * Cn + h * HD;
    const __half* Kp = Kg + (size_t)b * Tn * KVC + kvh * HD;
    const __half* Vp = Vg + (size_t)b * Tn * KVC + kvh * HD;

#pragma unroll
    for (int i = 0; i < 8; i++) {
        int idx = tid + i * 256;
        int r = idx >> 4, seg = idx & 15;
        uint32_t off = (uint32_t)(r * FROWB + seg * 16);
        cp_async16(sQ + off, Qp + (size_t)r * Cn + seg * 8);
    }
    f_load_kv(sKV0, Kp, Vp, 0, tid);

    const int arow = lane & 15;
    const int akoff = (lane >> 4) * 8;
    const int brow = (lane & 7) + ((lane >> 4) * 8);
    const int bkoff = ((lane >> 3) & 1) * 8;
    const int vrow = lane & 15;
    const int vnoff = (lane >> 4) * 8;

    float Oa[16][4];
#pragma unroll
    for (int i = 0; i < 16; i++)
#pragma unroll
        for (int q = 0; q < 4; q++) Oa[i][q] = 0.f;

    float m1 = -1e30f, m2 = -1e30f, l1 = 0.f, l2 = 0.f;
    const float sscale = 0.08838834764831845f;
    const int rg1 = q0 + w * 16 + (lane >> 2);
    const int rg2 = rg1 + 8;

    const int nkb = 2 * bq + 2;
    for (int j = 0; j < nkb; j++) {
        const int k0g = j * 64;
        const uint32_t skv = sKV0 + (j & 1) * KVSTG_B;
        if (j + 1 < nkb) {
            f_load_kv(sKV0 + ((j + 1) & 1) * KVSTG_B, Kp, Vp, (j + 1) * 64, tid);
            cp_wait_group<1>();
        } else {
            cp_wait_group<0>();
        }
        __syncthreads();

        const uint32_t sK = skv;
        const uint32_t sV = skv + KTILE_B;

        float S[8][4];
#pragma unroll
        for (int t = 0; t < 8; t++)
#pragma unroll
            for (int q = 0; q < 4; q++) S[t][q] = 0.f;

#pragma unroll
        for (int kc = 0; kc < 8; kc++) {
            uint32_t af[4];
            ldsm_x4(af, sQ + (uint32_t)((w * 16 + arow) * FROWB + (kc * 16 + akoff) * 2));
#pragma unroll
            for (int np = 0; np < 4; np++) {
                uint32_t bf[4];
                ldsm_x4(bf, sK + (uint32_t)((np * 16 + brow) * FROWB + (kc * 16 + bkoff) * 2));
                mma16816(S[2 * np],     af, bf);
                mma16816(S[2 * np + 1], af, bf + 2);
            }
        }

        const bool diag = (k0g + 63 > q0 + w * 16);
        float mx1 = -1e30f, mx2 = -1e30f;
#pragma unroll
        for (int t = 0; t < 8; t++) {
            int cg = k0g + t * 8 + (lane & 3) * 2;
#pragma unroll
            for (int e = 0; e < 2; e++) {
                float s0 = S[t][e] * sscale;
                float s1 = S[t][2 + e] * sscale;
                if (diag) {
                    if (cg + e > rg1) s0 = -1e30f;
                    if (cg + e > rg2) s1 = -1e30f;
                }
                S[t][e] = s0;
                S[t][2 + e] = s1;
                mx1 = fmaxf(mx1, s0);
                mx2 = fmaxf(mx2, s1);
            }
        }
        mx1 = fmaxf(mx1, __shfl_xor_sync(0xffffffff, mx1, 1));
        mx1 = fmaxf(mx1, __shfl_xor_sync(0xffffffff, mx1, 2));
        mx2 = fmaxf(mx2, __shfl_xor_sync(0xffffffff, mx2, 1));
        mx2 = fmaxf(mx2, __shfl_xor_sync(0xffffffff, mx2, 2));

        float mn1 = fmaxf(m1, mx1), mn2 = fmaxf(m2, mx2);
        float f1 = __expf(m1 - mn1), f2 = __expf(m2 - mn2);
        float rs1 = 0.f, rs2 = 0.f;
#pragma unroll
        for (int t = 0; t < 8; t++) {
#pragma unroll
            for (int e = 0; e < 2; e++) {
                float p0 = __expf(S[t][e] - mn1);
                float p1 = __expf(S[t][2 + e] - mn2);
                S[t][e] = p0;
                S[t][2 + e] = p1;
                rs1 += p0;
                rs2 += p1;
            }
        }
        rs1 += __shfl_xor_sync(0xffffffff, rs1, 1);
        rs1 += __shfl_xor_sync(0xffffffff, rs1, 2);
        rs2 += __shfl_xor_sync(0xffffffff, rs2, 1);
        rs2 += __shfl_xor_sync(0xffffffff, rs2, 2);
        l1 = l1 * f1 + rs1;
        l2 = l2 * f2 + rs2;
        m1 = mn1; m2 = mn2;
#pragma unroll
        for (int t = 0; t < 16; t++) {
            Oa[t][0] *= f1; Oa[t][1] *= f1;
            Oa[t][2] *= f2; Oa[t][3] *= f2;
        }

#pragma unroll
        for (int kc = 0; kc < 4; kc++) {
            uint32_t pf[4];
            pf[0] = pack_h2(S[2 * kc][0],     S[2 * kc][1]);
            pf[1] = pack_h2(S[2 * kc][2],     S[2 * kc][3]);
            pf[2] = pack_h2(S[2 * kc + 1][0], S[2 * kc + 1][1]);
            pf[3] = pack_h2(S[2 * kc + 1][2], S[2 * kc + 1][3]);
#pragma unroll
            for (int np = 0; np < 8; np++) {
                uint32_t vf[4];
                ldsm_x4_t(vf, sV + (uint32_t)((kc * 16 + vrow) * FROWB
                                              + (np * 16 + vnoff) * 2));
                mma16816(Oa[2 * np],     pf, vf);
                mma16816(Oa[2 * np + 1], pf, vf + 2);
            }
        }
        __syncthreads();
    }

    const float il1 = 1.f / l1, il2 = 1.f / l2;
    const size_t base1 = ((size_t)b * Tn + q0 + w * 16 + (lane >> 2)) * Cn + h * HD;
    const size_t base2 = base1 + 8 * (size_t)Cn;
#pragma unroll
    for (int nt = 0; nt < 16; nt++) {
        int col = nt * 8 + (lane & 3) * 2;
        *(__half2*)(Yg + base1 + col) =
            __floats2half2_rn(Oa[nt][0] * il1, Oa[nt][1] * il1);
        *(__half2*)(Yg + base2 + col) =
            __floats2half2_rn(Oa[nt][2] * il2, Oa[nt][3] * il2);
    }
}

// ===========================================================================
// launch
// ===========================================================================
extern "C" void kernel_launch(void* const* d_in, const int* in_sizes, int n_in,
                              void* d_out, int out_size)
{
    const float* x   = (const float*)d_in[0];
    const float* Wq  = (const float*)d_in[1];
    const float* Wk  = (const float*)d_in[2];
    const float* Wv  = (const float*)d_in[3];
    const float* Wo  = (const float*)d_in[4];
    const float* fc  = (const float*)d_in[5];
    const float* fs  = (const float*)d_in[6];
    float* out = (float*)d_out;

    __half *X16, *Q16, *K16, *V16, *Y16, *WqT, *WkT, *WvT, *WoT;
    cudaGetSymbolAddress((void**)&X16, g_X16);
    cudaGetSymbolAddress((void**)&Q16, g_Q16);
    cudaGetSymbolAddress((void**)&K16, g_K16);
    cudaGetSymbolAddress((void**)&V16, g_V16);
    cudaGetSymbolAddress((void**)&Y16, g_Y16);
    cudaGetSymbolAddress((void**)&WqT, g_WqT);
    cudaGetSymbolAddress((void**)&WkT, g_WkT);
    cudaGetSymbolAddress((void**)&WvT, g_WvT);
    cudaGetSymbolAddress((void**)&WoT, g_WoT);

    cudaFuncSetAttribute(gemm_qkv,
                         cudaFuncAttributeMaxDynamicSharedMemorySize, GEMM_SMEM);
    cudaFuncSetAttribute(gemm_out,
                         cudaFuncAttributeMaxDynamicSharedMemorySize, GEMM_SMEM);
    cudaFuncSetAttribute(flash_attn_mma,
                         cudaFuncAttributeMaxDynamicSharedMemorySize, FLASH_SMEM);

    // fused prep
    {
        dim3 g(128, 64, 5);
        prep_kernel<<<g, 256>>>(x, Wq, Wk, Wv, Wo, X16, WqT, WkT, WvT, WoT);
    }

    // fused QKV projection (rope fused into epilogue)
    {
        dim3 g(24, Mrows / 128);      // 24 x 32 = 768 CTAs
        gemm_qkv<<<g, 128, GEMM_SMEM>>>(X16, WqT, WkT, WvT,
                                        Q16, K16, V16, fc, fs);
    }

    // attention (fp16 HMMA flash)
    {
        dim3 g(Tn / 128, NH, Bn);     // 16 x 16 x 2
        flash_attn_mma<<<g, 256, FLASH_SMEM>>>(Q16, K16, V16, Y16);
    }

    // output projection
    {
        dim3 go(Cn / 128, Mrows / 128);   // 16 x 32
        gemm_out<<<go, 128, GEMM_SMEM>>>(Y16, WoT, out, Cn, Cn);
    }
}